// round 3
// baseline (speedup 1.0000x reference)
#include <cuda_runtime.h>
#include <math.h>

// ---------------------------------------------------------------------------
// AttentionNet: conv1 -> conv2 -> ConvLSTM(T=32) -> attention core LSTM(T=32)
// Shapes: T=32, B=16, frame (512,3,210,160), conv1 out (512,32,52,40),
// conv2 out (512,64,27,20), ConvLSTM hidden 128ch @27x20, core HID=256.
// ---------------------------------------------------------------------------

#define NT 32
#define NB 16
#define PP 540            // 27*20

// ------------------------- static device scratch ---------------------------
__device__ float g_conv1[512u*32*2080];          // (512,32,52,40)  136 MB
__device__ float g_x    [512u*64*540];           // (512,64,27,20)   71 MB
__device__ float g_Gx   [141557760u];            // (512,512,540)   566 MB  x-part of gates + bias
__device__ float g_O    [512u*128*540];          // (T*B,128,540) RAW NCHW h outputs
__device__ float g_gates[16u*512*540];           // per-step gates
__device__ float g_h    [16*128*540];            // conv h state
__device__ float g_c    [16*128*540];            // conv c state
__device__ float g_S    [540*64];                // spatial basis
__device__ float g_ch   [16*256];                // core h
__device__ float g_cc   [16*256];                // core c
__device__ float g_outs [32*16*256];             // core outputs per step

__device__ __forceinline__ float sigmoidf_(float x) { return 1.f/(1.f+expf(-x)); }

// ------------------------------ init -------------------------------------
__global__ void init_kernel(const float* __restrict__ core_h, const float* __restrict__ core_c,
                            const float* __restrict__ conv_h, const float* __restrict__ conv_c) {
    int i = blockIdx.x*blockDim.x + threadIdx.x;
    if (i < 540*64) {
        int p = i >> 6, k = i & 63;
        int y = p/20, x = p - y*20;
        int u = k >> 3, v = k & 7;
        double PI = 3.14159265358979323846;
        g_S[i] = (float)(cos((double)(y+1)*(u+1)*PI/27.0) * cos((double)(x+1)*(v+1)*PI/20.0));
    }
    if (i < 16*256) { g_ch[i] = core_h[i]; g_cc[i] = core_c[i]; }
    if (i < 16*128*540) { g_h[i] = conv_h[i]; g_c[i] = conv_c[i]; }
}

// -------------------- generic implicit-GEMM conv kernel --------------------
// C[M][N] = sum_k W[m][k] * im2col(B)[k][n], 4 modes.
template<int MODE> struct GP;
// conv1: 8x8 s4 pad(1,2), 3->32, in 210x160, out 52x40
template<> struct GP<0>{ static constexpr int M=32,  K=192,  IC=3,   IH=210,IW=160,OH=52,OW=40,KH=8,KW=8,SH=4,SW=4,PH=1,PW=2,WS=192, WO=0; };
// conv2: 4x4 s2 pad(2,1), 32->64, in 52x40, out 27x20
template<> struct GP<1>{ static constexpr int M=64,  K=512,  IC=32,  IH=52, IW=40, OH=27,OW=20,KH=4,KW=4,SH=2,SW=2,PH=2,PW=1,WS=512, WO=0; };
// Gx: 3x3 s1 pad1, x-channels (64) -> 512 gates, all T*B at once
template<> struct GP<2>{ static constexpr int M=512, K=576,  IC=64,  IH=27, IW=20, OH=27,OW=20,KH=3,KW=3,SH=1,SW=1,PH=1,PW=1,WS=1728,WO=0; };
// h-conv: 3x3 s1 pad1, h-channels (128) -> 512 gates, per step (N = 16*540)
template<> struct GP<3>{ static constexpr int M=512, K=1152, IC=128, IH=27, IW=20, OH=27,OW=20,KH=3,KW=3,SH=1,SW=1,PH=1,PW=1,WS=1728,WO=576; };

template<int MODE>
__global__ void __launch_bounds__(256)
gemm_conv(const float* __restrict__ W, const float* __restrict__ bias,
          const float* __restrict__ frame, int t, const unsigned char* __restrict__ done)
{
    using G = GP<MODE>;
    constexpr int PPI = G::OH * G::OW;
    __shared__ float As[16][64];
    __shared__ float Bs[16][64];

    int tid = threadIdx.x;
    int n0 = blockIdx.x * 64;
    int m0 = blockIdx.y * 64;
    int tx = tid & 15, ty = tid >> 4;

    float acc[4][4];
    #pragma unroll
    for (int i=0;i<4;i++)
        #pragma unroll
        for (int j=0;j<4;j++) acc[i][j] = 0.f;

    // A-load indices: thread loads 4 consecutive k of one m-row
    int a_m = m0 + (tid >> 2);
    int a_k = (tid & 3) * 4;

    // B-load indices: thread owns column nn = tid&63, k rows tid>>6 + {0,4,8,12}
    int b_n = n0 + (tid & 63);
    int img = b_n / PPI;
    int pos = b_n - img * PPI;
    int oy  = pos / G::OW;
    int ox  = pos - oy * G::OW;
    int iy0 = oy * G::SH - G::PH;
    int ix0 = ox * G::SW - G::PW;

    float ndv = 1.f;
    const float* bbase;
    if constexpr (MODE==0)      bbase = frame  + (size_t)img * (3*210*160);
    else if constexpr (MODE==1) bbase = g_conv1 + (size_t)img * (32*52*40);
    else if constexpr (MODE==2) bbase = g_x    + (size_t)img * (64*540);
    else { ndv = (done[t*16+img]==0) ? 1.f : 0.f; bbase = g_h + (size_t)img * (128*540); }

    for (int k0 = 0; k0 < G::K; k0 += 16) {
        // --- load A tile (transposed into smem) ---
        float4 av4;
        if (G::M % 64 == 0 || a_m < G::M)
            av4 = *reinterpret_cast<const float4*>(W + (size_t)a_m * G::WS + G::WO + k0 + a_k);
        else
            av4 = make_float4(0.f,0.f,0.f,0.f);
        As[a_k+0][tid>>2] = av4.x;
        As[a_k+1][tid>>2] = av4.y;
        As[a_k+2][tid>>2] = av4.z;
        As[a_k+3][tid>>2] = av4.w;

        // --- load B tile (im2col on the fly) ---
        #pragma unroll
        for (int j=0;j<4;j++) {
            int kk = (tid>>6) + j*4;
            int k  = k0 + kk;
            int c  = k / (G::KH*G::KW);
            int rs = k - c*(G::KH*G::KW);
            int r  = rs / G::KW;
            int s  = rs - r*G::KW;
            int iy = iy0 + r, ix = ix0 + s;
            float v = 0.f;
            if (iy >= 0 && iy < G::IH && ix >= 0 && ix < G::IW)
                v = bbase[((size_t)c*G::IH + iy)*G::IW + ix];
            Bs[kk][tid & 63] = v * ndv;
        }
        __syncthreads();

        #pragma unroll
        for (int kk=0;kk<16;kk++) {
            float4 a4 = *reinterpret_cast<const float4*>(&As[kk][ty*4]);
            float4 b4 = *reinterpret_cast<const float4*>(&Bs[kk][tx*4]);
            float a[4] = {a4.x,a4.y,a4.z,a4.w};
            float b[4] = {b4.x,b4.y,b4.z,b4.w};
            #pragma unroll
            for (int i=0;i<4;i++)
                #pragma unroll
                for (int j=0;j<4;j++) acc[i][j] += a[i]*b[j];
        }
        __syncthreads();
    }

    // --- epilogue ---
    #pragma unroll
    for (int i=0;i<4;i++) {
        int m = m0 + ty*4 + i;
        if (G::M % 64 != 0 && m >= G::M) continue;
        #pragma unroll
        for (int j=0;j<4;j++) {
            int n  = n0 + tx*4 + j;
            int im = n / PPI;
            int pp = n - im*PPI;
            float v = acc[i][j];
            if constexpr (MODE==0)      { v += bias[m]; g_conv1[(size_t)(im*32+m)*2080 + pp] = v; }
            else if constexpr (MODE==1) { v += bias[m]; g_x[(size_t)(im*64+m)*540 + pp] = v; }
            else if constexpr (MODE==2) { v += bias[m]; g_Gx[((size_t)im*512 + m)*540 + pp] = v; }
            else {
                v += g_Gx[(((size_t)(t*16+im))*512 + m)*540 + pp];
                g_gates[(size_t)(im*512+m)*540 + pp] = v;
            }
        }
    }
}

// ------------------------- ConvLSTM pointwise update ------------------------
__global__ void convlstm_update(int t, const unsigned char* __restrict__ done) {
    int i = blockIdx.x*blockDim.x + threadIdx.x;
    if (i >= 16*128*540) return;
    int b   = i / (128*540);
    int rem = i - b*(128*540);
    int ch  = rem / 540;
    int p   = rem - ch*540;
    float nd = (done[t*16+b]==0) ? 1.f : 0.f;
    const float* gb = g_gates + (size_t)b*512*540;
    float ai = gb[(      ch)*540 + p];
    float af = gb[(128 + ch)*540 + p];
    float ao = gb[(256 + ch)*540 + p];
    float ag = gb[(384 + ch)*540 + p];
    float c  = g_c[i] * nd;
    c = sigmoidf_(af)*c + sigmoidf_(ai)*tanhf(ag);
    float h = sigmoidf_(ao)*tanhf(c);
    g_c[i] = c;
    g_h[i] = h;
    // RAW NCHW layout: reference does a raw reshape (T,B,128,27,20)->(T*B,27,20,128),
    // so g_O flat must equal the NCHW flat order.
    g_O[((size_t)(t*16+b))*69120 + (size_t)ch*540 + p] = h;
}

// --------------------------- fused core step -------------------------------
// One block per batch element; full q-MLP + attention + answer MLP + LSTM.
// K/V are read through the reference's raw-reshape view: O_view[p][ch] =
// g_O[tb*69120 + p*128 + ch] (flat NCHW reinterpreted as (540,128)).
__global__ void __launch_bounds__(256)
core_step(int t, const unsigned char* __restrict__ done,
          const float* __restrict__ qw1, const float* __restrict__ qb1,
          const float* __restrict__ qw2, const float* __restrict__ qb2,
          const float* __restrict__ qw3, const float* __restrict__ qb3,
          const float* __restrict__ aw1, const float* __restrict__ ab1,
          const float* __restrict__ aw2, const float* __restrict__ ab2,
          const float* __restrict__ w_ih, const float* __restrict__ w_hh,
          const float* __restrict__ b_ih, const float* __restrict__ b_hh,
          const int* __restrict__ last_action, const float* __restrict__ reward)
{
    int b = blockIdx.x;
    int tid = threadIdx.x;

    __shared__ float sh[256];
    __shared__ float q1[128];
    __shared__ float q2[288];
    __shared__ float q3[288];
    __shared__ float sA[540*4];
    __shared__ float red[256];
    __shared__ float mx[4], sm[4];
    __shared__ float ans[736];
    __shared__ float a1[512];
    __shared__ float ci[256];

    sh[tid] = g_ch[b*256 + tid];         // UNMASKED h for q computation
    __syncthreads();

    // q1 = relu(h @ qw1 + qb1)   (128)
    if (tid < 128) {
        float s = qb1[tid];
        for (int k=0;k<256;k++) s += sh[k]*qw1[k*128+tid];
        q1[tid] = fmaxf(s, 0.f);
    }
    __syncthreads();
    // q2 = relu(q1 @ qw2 + qb2)  (288)
    for (int j=tid;j<288;j+=256) {
        float s = qb2[j];
        for (int k=0;k<128;k++) s += q1[k]*qw2[k*288+j];
        q2[j] = fmaxf(s, 0.f);
    }
    __syncthreads();
    // q3 = q2 @ qw3 + qb3        (288 = 4 x 72)
    for (int j=tid;j<288;j+=256) {
        float s = qb3[j];
        for (int k=0;k<288;k++) s += q2[k]*qw3[k*288+j];
        q3[j] = s;
    }
    __syncthreads();

    // attention logits A[p][qi] = K[p,:] . q[qi,:]
    const float* Ob = g_O + ((size_t)(t*16+b))*69120;
    for (int idx=tid; idx<2160; idx+=256) {
        int p = idx >> 2, qi = idx & 3;
        const float* qv = q3 + qi*72;
        const float* op = Ob + (size_t)p*128;   // raw-reshape view row
        const float* sp = g_S + p*64;
        float s = 0.f;
        #pragma unroll
        for (int k=0;k<8;k++)  s += op[k]*qv[k];
        #pragma unroll 8
        for (int k=0;k<64;k++) s += sp[k]*qv[8+k];
        sA[idx] = s;
    }
    __syncthreads();

    // softmax over p (540) per qi, 4 groups of 64 threads
    {
        int qi = tid >> 6, lane = tid & 63;
        float m = -1e30f;
        for (int p=lane;p<540;p+=64) m = fmaxf(m, sA[p*4+qi]);
        red[tid] = m;
        __syncthreads();
        if (tid < 4) { float mm=-1e30f; for (int i=0;i<64;i++) mm = fmaxf(mm, red[tid*64+i]); mx[tid]=mm; }
        __syncthreads();
        for (int idx=tid; idx<2160; idx+=256) sA[idx] = expf(sA[idx]-mx[idx&3]);
        __syncthreads();
        float s = 0.f;
        for (int p=lane;p<540;p+=64) s += sA[p*4+qi];
        red[tid] = s;
        __syncthreads();
        if (tid < 4) { float ss=0.f; for (int i=0;i<64;i++) ss += red[tid*64+i]; sm[tid]=ss; }
        __syncthreads();
    }

    // ans[qi][v] = sum_p A[p][qi] * V[p][v] / sum[qi]   (4 x 184)
    for (int o=tid;o<736;o+=256) {
        int qi = o / 184, v = o - qi*184;
        float s = 0.f;
        if (v < 120) {
            const float* ov = Ob + 8 + v;
            for (int p=0;p<540;p++) s += sA[p*4+qi]*ov[(size_t)p*128];
        } else {
            const float* sv = g_S + (v-120);
            for (int p=0;p<540;p++) s += sA[p*4+qi]*sv[p*64];
        }
        ans[o] = s / sm[qi];
    }
    __syncthreads();

    float rclip = fminf(fmaxf(reward[t*16+b], -1.f), 1.f);
    int act = last_action[t*16+b];

    // a1 = relu(answer @ aw1 + ab1)  (512); answer = [ans(736), q(288), r, onehot(18)]
    for (int j=tid;j<512;j+=256) {
        float s = ab1[j];
        for (int k=0;k<736;k++) s += ans[k]*aw1[(size_t)k*512+j];
        for (int k=0;k<288;k++) s += q3[k]*aw1[(size_t)(736+k)*512+j];
        s += rclip * aw1[(size_t)1024*512+j];
        s += aw1[(size_t)(1025+act)*512+j];
        a1[j] = fmaxf(s, 0.f);
    }
    __syncthreads();
    // ci = a1 @ aw2 + ab2  (256)
    {
        float s = ab2[tid];
        for (int k=0;k<512;k++) s += a1[k]*aw2[(size_t)k*256+tid];
        ci[tid] = s;
    }
    __syncthreads();

    // LSTM gates: thread tid owns unit tid, computes its 4 gates
    float nd = (done[t*16+b]==0) ? 1.f : 0.f;
    float g4[4];
    #pragma unroll
    for (int gg=0;gg<4;gg++) {
        int j = gg*256 + tid;
        const float* wi = w_ih + (size_t)j*256;
        const float* wh = w_hh + (size_t)j*256;
        float s1 = 0.f, s2 = 0.f;
        for (int k=0;k<256;k++) { s1 += ci[k]*wi[k]; s2 += sh[k]*wh[k]; }
        g4[gg] = s1 + nd*s2 + b_ih[j] + b_hh[j];
    }
    float gi=g4[0], gf=g4[1], gG=g4[2], go=g4[3];
    float c = nd * g_cc[b*256+tid];
    c = sigmoidf_(gf)*c + sigmoidf_(gi)*tanhf(gG);
    float h = sigmoidf_(go)*tanhf(c);
    g_cc[b*256+tid] = c;
    g_ch[b*256+tid] = h;
    g_outs[((size_t)t*16+b)*256 + tid] = h;
}

// ------------------------------- heads -------------------------------------
__global__ void head_kernel(const float* __restrict__ pw, const float* __restrict__ pb,
                            const float* __restrict__ vw, const float* __restrict__ vb,
                            float* __restrict__ out)
{
    int row = blockIdx.x;        // 512 rows (t*16+b)
    int tid = threadIdx.x;       // 32 threads
    __shared__ float lg[18];
    const float* h = g_outs + (size_t)row*256;
    if (tid < 18) {
        float s = pb[tid];
        for (int k=0;k<256;k++) s += h[k]*pw[k*18+tid];
        lg[tid] = s;
        out[row*18 + tid] = s;
    }
    if (tid == 19) {
        float s = vb[0];
        for (int k=0;k<256;k++) s += h[k]*vw[k];
        out[9216 + row] = s;
    }
    __syncthreads();
    if (tid == 0) {
        int am = 0; float bv = lg[0];
        for (int j=1;j<18;j++) if (lg[j] > bv) { bv = lg[j]; am = j; }
        out[9728 + row] = (float)am;
    }
}

__global__ void write_states(float* __restrict__ out) {
    int i = blockIdx.x*blockDim.x + threadIdx.x;
    if (i < 4096) { out[10240 + i] = g_ch[i]; out[14336 + i] = g_cc[i]; }
    if (i < 1105920) { out[18432 + i] = g_h[i]; out[1124352 + i] = g_c[i]; }
}

// ------------------------------- launch ------------------------------------
extern "C" void kernel_launch(void* const* d_in, const int* in_sizes, int n_in,
                              void* d_out, int out_size) {
    const float*         frame      = (const float*)d_in[0];
    const unsigned char* done       = (const unsigned char*)d_in[1];
    const int*           last_action= (const int*)d_in[2];
    const float*         reward     = (const float*)d_in[3];
    const float*         core_h     = (const float*)d_in[4];
    const float*         core_c     = (const float*)d_in[5];
    const float*         conv_h     = (const float*)d_in[6];
    const float*         conv_c     = (const float*)d_in[7];
    const float*         cnn_w1     = (const float*)d_in[8];
    const float*         cnn_b1     = (const float*)d_in[9];
    const float*         cnn_w2     = (const float*)d_in[10];
    const float*         cnn_b2     = (const float*)d_in[11];
    const float*         lstm_w     = (const float*)d_in[12];
    const float*         lstm_b     = (const float*)d_in[13];
    const float*         qw1        = (const float*)d_in[14];
    const float*         qb1        = (const float*)d_in[15];
    const float*         qw2        = (const float*)d_in[16];
    const float*         qb2        = (const float*)d_in[17];
    const float*         qw3        = (const float*)d_in[18];
    const float*         qb3        = (const float*)d_in[19];
    const float*         aw1        = (const float*)d_in[20];
    const float*         ab1        = (const float*)d_in[21];
    const float*         aw2        = (const float*)d_in[22];
    const float*         ab2        = (const float*)d_in[23];
    const float*         w_ih       = (const float*)d_in[24];
    const float*         w_hh       = (const float*)d_in[25];
    const float*         b_ih       = (const float*)d_in[26];
    const float*         b_hh       = (const float*)d_in[27];
    const float*         pw         = (const float*)d_in[28];
    const float*         pb         = (const float*)d_in[29];
    const float*         vw         = (const float*)d_in[30];
    const float*         vb         = (const float*)d_in[31];
    float* out = (float*)d_out;

    init_kernel<<<4320, 256>>>(core_h, core_c, conv_h, conv_c);

    // conv1: N = 512*2080 = 1,064,960 -> 16640 tiles of 64
    gemm_conv<0><<<dim3(16640,1), 256>>>(cnn_w1, cnn_b1, frame, 0, done);
    // conv2: N = 512*540 = 276,480 -> 4320 tiles
    gemm_conv<1><<<dim3(4320,1), 256>>>(cnn_w2, cnn_b2, frame, 0, done);
    // Gx = conv_x(x) + bias for ALL timesteps (parallel): M=512 -> 8 m-tiles
    gemm_conv<2><<<dim3(4320,8), 256>>>(lstm_w, lstm_b, frame, 0, done);

    for (int t = 0; t < NT; t++) {
        // gates = Gx[t] + conv_h(nd*h): N = 16*540 = 8640 -> 135 tiles
        gemm_conv<3><<<dim3(135,8), 256>>>(lstm_w, lstm_b, frame, t, done);
        convlstm_update<<<4320, 256>>>(t, done);
        core_step<<<16, 256>>>(t, done, qw1,qb1,qw2,qb2,qw3,qb3,
                               aw1,ab1,aw2,ab2, w_ih,w_hh,b_ih,b_hh,
                               last_action, reward);
    }

    head_kernel<<<512, 32>>>(pw, pb, vw, vb, out);
    write_states<<<4320, 256>>>(out);
}

// round 4
// speedup vs baseline: 1.0556x; 1.0556x over previous
#include <cuda_runtime.h>
#include <math.h>

// ---------------------------------------------------------------------------
// AttentionNet: conv1 -> conv2 -> ConvLSTM(T=32) -> attention core LSTM(T=32)
// ---------------------------------------------------------------------------

#define NT 32
#define NB 16
#define PP 540            // 27*20

// ------------------------- static device scratch ---------------------------
__device__ float g_conv1[512u*32*2080];          // (512,32,52,40)
__device__ float g_x    [512u*64*540];           // (512,64,27,20)
__device__ float g_Gx   [141557760u];            // (512,512,540) x-part of gates + bias
__device__ float g_O    [512u*128*540];          // (T*B,128,540) RAW NCHW h outputs
__device__ float g_gates[16u*512*540];           // per-step gates
__device__ float g_h    [16*128*540];            // conv h state
__device__ float g_c    [16*128*540];            // conv c state
__device__ float g_S    [540*64];                // spatial basis
__device__ float g_ch   [16*256];                // core h
__device__ float g_cc   [16*256];                // core c
__device__ float g_outs [32*16*256];             // core outputs per step

__device__ __forceinline__ float sigmoidf_(float x) { return 1.f/(1.f+expf(-x)); }

// ------------------------------ init -------------------------------------
__global__ void init_kernel(const float* __restrict__ core_h, const float* __restrict__ core_c,
                            const float* __restrict__ conv_h, const float* __restrict__ conv_c) {
    int i = blockIdx.x*blockDim.x + threadIdx.x;
    if (i < 540*64) {
        int p = i >> 6, k = i & 63;
        int y = p/20, x = p - y*20;
        int u = k >> 3, v = k & 7;
        double PI = 3.14159265358979323846;
        g_S[i] = (float)(cos((double)(y+1)*(u+1)*PI/27.0) * cos((double)(x+1)*(v+1)*PI/20.0));
    }
    if (i < 16*256) { g_ch[i] = core_h[i]; g_cc[i] = core_c[i]; }
    if (i < 16*128*540) { g_h[i] = conv_h[i]; g_c[i] = conv_c[i]; }
}

// -------------------- generic implicit-GEMM conv kernel (small) -------------
template<int MODE> struct GP;
// conv1: 8x8 s4 pad(1,2), 3->32, in 210x160, out 52x40
template<> struct GP<0>{ static constexpr int M=32,  K=192,  IC=3,   IH=210,IW=160,OH=52,OW=40,KH=8,KW=8,SH=4,SW=4,PH=1,PW=2,WS=192, WO=0; };
// conv2: 4x4 s2 pad(2,1), 32->64, in 52x40, out 27x20
template<> struct GP<1>{ static constexpr int M=64,  K=512,  IC=32,  IH=52, IW=40, OH=27,OW=20,KH=4,KW=4,SH=2,SW=2,PH=2,PW=1,WS=512, WO=0; };

template<int MODE>
__global__ void __launch_bounds__(256)
gemm_conv(const float* __restrict__ W, const float* __restrict__ bias,
          const float* __restrict__ frame)
{
    using G = GP<MODE>;
    constexpr int PPI = G::OH * G::OW;
    __shared__ float As[16][64];
    __shared__ float Bs[16][64];

    int tid = threadIdx.x;
    int n0 = blockIdx.x * 64;
    int m0 = blockIdx.y * 64;
    int tx = tid & 15, ty = tid >> 4;

    float acc[4][4];
    #pragma unroll
    for (int i=0;i<4;i++)
        #pragma unroll
        for (int j=0;j<4;j++) acc[i][j] = 0.f;

    int a_m = m0 + (tid >> 2);
    int a_k = (tid & 3) * 4;

    int b_n = n0 + (tid & 63);
    int img = b_n / PPI;
    int pos = b_n - img * PPI;
    int oy  = pos / G::OW;
    int ox  = pos - oy * G::OW;
    int iy0 = oy * G::SH - G::PH;
    int ix0 = ox * G::SW - G::PW;

    const float* bbase;
    if constexpr (MODE==0) bbase = frame   + (size_t)img * (3*210*160);
    else                   bbase = g_conv1 + (size_t)img * (32*52*40);

    for (int k0 = 0; k0 < G::K; k0 += 16) {
        float4 av4;
        if (G::M % 64 == 0 || a_m < G::M)
            av4 = *reinterpret_cast<const float4*>(W + (size_t)a_m * G::WS + G::WO + k0 + a_k);
        else
            av4 = make_float4(0.f,0.f,0.f,0.f);
        As[a_k+0][tid>>2] = av4.x;
        As[a_k+1][tid>>2] = av4.y;
        As[a_k+2][tid>>2] = av4.z;
        As[a_k+3][tid>>2] = av4.w;

        #pragma unroll
        for (int j=0;j<4;j++) {
            int kk = (tid>>6) + j*4;
            int k  = k0 + kk;
            int c  = k / (G::KH*G::KW);
            int rs = k - c*(G::KH*G::KW);
            int r  = rs / G::KW;
            int s  = rs - r*G::KW;
            int iy = iy0 + r, ix = ix0 + s;
            float v = 0.f;
            if (iy >= 0 && iy < G::IH && ix >= 0 && ix < G::IW)
                v = bbase[((size_t)c*G::IH + iy)*G::IW + ix];
            Bs[kk][tid & 63] = v;
        }
        __syncthreads();

        #pragma unroll
        for (int kk=0;kk<16;kk++) {
            float4 a4 = *reinterpret_cast<const float4*>(&As[kk][ty*4]);
            float4 b4 = *reinterpret_cast<const float4*>(&Bs[kk][tx*4]);
            float a[4] = {a4.x,a4.y,a4.z,a4.w};
            float b[4] = {b4.x,b4.y,b4.z,b4.w};
            #pragma unroll
            for (int i=0;i<4;i++)
                #pragma unroll
                for (int j=0;j<4;j++) acc[i][j] += a[i]*b[j];
        }
        __syncthreads();
    }

    #pragma unroll
    for (int i=0;i<4;i++) {
        int m = m0 + ty*4 + i;
        if (G::M % 64 != 0 && m >= G::M) continue;
        #pragma unroll
        for (int j=0;j<4;j++) {
            int n  = n0 + tx*4 + j;
            int im = n / PPI;
            int pp = n - im*PPI;
            float v = acc[i][j] + bias[m];
            if constexpr (MODE==0) g_conv1[(size_t)(im*32+m)*2080 + pp] = v;
            else                   g_x[(size_t)(im*64+m)*540 + pp] = v;
        }
    }
}

// ------------- 128x128x8 SGEMM, 8x8 micro-tile, for the 3x3 convs -----------
// MODE2: Gx = W_x * im2col(g_x) + bias, all 512 images.   M=512, K=576,  N=276480
// MODE3: gates = Gx[t] + W_h * im2col(nd * g_h), one step. M=512, K=1152, N=8640
template<int MODE>
__global__ void __launch_bounds__(256)
gemm_conv8(const float* __restrict__ W, const float* __restrict__ bias,
           int t, const unsigned char* __restrict__ done)
{
    constexpr int K    = (MODE==2) ? 576 : 1152;
    constexpr int WO   = (MODE==2) ? 0 : 576;      // k-offset into lstm_w rows (len 1728)
    constexpr int ICH  = (MODE==2) ? 64 : 128;     // input channels
    constexpr int NTOT = (MODE==2) ? 512*540 : 16*540;

    __shared__ float As[8][132];
    __shared__ float Bs[8][132];

    int tid = threadIdx.x;
    int n0 = blockIdx.x * 128;
    int m0 = blockIdx.y * 128;
    int tx = tid & 15;      // n-subtile
    int ty = tid >> 4;      // m-subtile

    float acc[8][8];
    #pragma unroll
    for (int i=0;i<8;i++)
        #pragma unroll
        for (int j=0;j<8;j++) acc[i][j] = 0.f;

    // A: thread loads 4 consecutive k of row a_m
    int a_m = tid >> 1;
    int a_k = (tid & 1) * 4;
    const float* Wrow = W + (size_t)(m0 + a_m) * 1728 + WO + a_k;

    // B: thread owns column b_col, k rows kb + {0,2,4,6}
    int b_col = tid & 127;
    int kb    = tid >> 7;            // 0 or 1
    int b_n   = n0 + b_col;
    bool valid = (MODE==2) ? true : (b_n < NTOT);
    int bn_c  = valid ? b_n : 0;
    int img = bn_c / 540;
    int pos = bn_c - img * 540;
    int oy  = pos / 20;
    int ox  = pos - oy * 20;
    int iy0 = oy - 1;
    int ix0 = ox - 1;

    float ndv = 1.f;
    const float* bbase;
    if constexpr (MODE==2) bbase = g_x + (size_t)img * (64*540);
    else { ndv = (done[t*16+img]==0) ? 1.f : 0.f; bbase = g_h + (size_t)img * (128*540); }
    if (!valid) ndv = 0.f;

    float4 aval;
    float  bval[4];

    // prefetch iter 0
    aval = *reinterpret_cast<const float4*>(Wrow);
    #pragma unroll
    for (int j=0;j<4;j++) {
        int k  = kb + j*2;
        int c  = k / 9;
        int rs = k - c*9;
        int r  = rs / 3;
        int s  = rs - r*3;
        int iy = iy0 + r, ix = ix0 + s;
        float v = 0.f;
        if (iy >= 0 && iy < 27 && ix >= 0 && ix < 20)
            v = bbase[(c*27 + iy)*20 + ix];
        bval[j] = v * ndv;
    }

    for (int k0 = 0; k0 < K; k0 += 8) {
        As[a_k+0][a_m] = aval.x;
        As[a_k+1][a_m] = aval.y;
        As[a_k+2][a_m] = aval.z;
        As[a_k+3][a_m] = aval.w;
        #pragma unroll
        for (int j=0;j<4;j++) Bs[kb + j*2][b_col] = bval[j];
        __syncthreads();

        // prefetch next iter
        if (k0 + 8 < K) {
            aval = *reinterpret_cast<const float4*>(Wrow + k0 + 8);
            #pragma unroll
            for (int j=0;j<4;j++) {
                int k  = k0 + 8 + kb + j*2;
                int c  = k / 9;
                int rs = k - c*9;
                int r  = rs / 3;
                int s  = rs - r*3;
                int iy = iy0 + r, ix = ix0 + s;
                float v = 0.f;
                if (iy >= 0 && iy < 27 && ix >= 0 && ix < 20)
                    v = bbase[(c*27 + iy)*20 + ix];
                bval[j] = v * ndv;
            }
        }

        #pragma unroll
        for (int kk=0;kk<8;kk++) {
            float4 a0 = *reinterpret_cast<const float4*>(&As[kk][ty*8]);
            float4 a1 = *reinterpret_cast<const float4*>(&As[kk][ty*8+4]);
            float4 b0 = *reinterpret_cast<const float4*>(&Bs[kk][tx*8]);
            float4 b1 = *reinterpret_cast<const float4*>(&Bs[kk][tx*8+4]);
            float a[8] = {a0.x,a0.y,a0.z,a0.w,a1.x,a1.y,a1.z,a1.w};
            float b[8] = {b0.x,b0.y,b0.z,b0.w,b1.x,b1.y,b1.z,b1.w};
            #pragma unroll
            for (int i=0;i<8;i++)
                #pragma unroll
                for (int j=0;j<8;j++) acc[i][j] += a[i]*b[j];
        }
        __syncthreads();
    }

    // epilogue
    #pragma unroll
    for (int i=0;i<8;i++) {
        int m = m0 + ty*8 + i;
        float bm;
        if constexpr (MODE==2) bm = bias[m];
        #pragma unroll
        for (int j=0;j<8;j++) {
            int n = n0 + tx*8 + j;
            if (MODE==3 && n >= NTOT) continue;
            int im = n / 540;
            int pp = n - im*540;
            if constexpr (MODE==2) {
                g_Gx[((size_t)im*512 + m)*540 + pp] = acc[i][j] + bm;
            } else {
                float v = acc[i][j] + g_Gx[(((size_t)(t*16+im))*512 + m)*540 + pp];
                g_gates[(size_t)(im*512+m)*540 + pp] = v;
            }
        }
    }
}

// ------------------------- ConvLSTM pointwise update ------------------------
__global__ void convlstm_update(int t, const unsigned char* __restrict__ done) {
    int i = blockIdx.x*blockDim.x + threadIdx.x;
    if (i >= 16*128*540) return;
    int b   = i / (128*540);
    int rem = i - b*(128*540);
    int ch  = rem / 540;
    int p   = rem - ch*540;
    float nd = (done[t*16+b]==0) ? 1.f : 0.f;
    const float* gb = g_gates + (size_t)b*512*540;
    float ai = gb[(      ch)*540 + p];
    float af = gb[(128 + ch)*540 + p];
    float ao = gb[(256 + ch)*540 + p];
    float ag = gb[(384 + ch)*540 + p];
    float c  = g_c[i] * nd;
    c = sigmoidf_(af)*c + sigmoidf_(ai)*tanhf(ag);
    float h = sigmoidf_(ao)*tanhf(c);
    g_c[i] = c;
    g_h[i] = h;
    // RAW NCHW layout: reference does a raw reshape, flat order preserved.
    g_O[((size_t)(t*16+b))*69120 + (size_t)ch*540 + p] = h;
}

// --------------------------- fused core step -------------------------------
__global__ void __launch_bounds__(256)
core_step(int t, const unsigned char* __restrict__ done,
          const float* __restrict__ qw1, const float* __restrict__ qb1,
          const float* __restrict__ qw2, const float* __restrict__ qb2,
          const float* __restrict__ qw3, const float* __restrict__ qb3,
          const float* __restrict__ aw1, const float* __restrict__ ab1,
          const float* __restrict__ aw2, const float* __restrict__ ab2,
          const float* __restrict__ w_ih, const float* __restrict__ w_hh,
          const float* __restrict__ b_ih, const float* __restrict__ b_hh,
          const int* __restrict__ last_action, const float* __restrict__ reward)
{
    int b = blockIdx.x;
    int tid = threadIdx.x;

    __shared__ float sh[256];
    __shared__ float q1[128];
    __shared__ float q2[288];
    __shared__ float q3[288];
    __shared__ float sA[540*4];
    __shared__ float red[256];
    __shared__ float mx[4], sm[4];
    __shared__ float ans[736];
    __shared__ float a1[512];
    __shared__ float ci[256];

    sh[tid] = g_ch[b*256 + tid];
    __syncthreads();

    if (tid < 128) {
        float s = qb1[tid];
        for (int k=0;k<256;k++) s += sh[k]*qw1[k*128+tid];
        q1[tid] = fmaxf(s, 0.f);
    }
    __syncthreads();
    for (int j=tid;j<288;j+=256) {
        float s = qb2[j];
        for (int k=0;k<128;k++) s += q1[k]*qw2[k*288+j];
        q2[j] = fmaxf(s, 0.f);
    }
    __syncthreads();
    for (int j=tid;j<288;j+=256) {
        float s = qb3[j];
        for (int k=0;k<288;k++) s += q2[k]*qw3[k*288+j];
        q3[j] = s;
    }
    __syncthreads();

    const float* Ob = g_O + ((size_t)(t*16+b))*69120;
    for (int idx=tid; idx<2160; idx+=256) {
        int p = idx >> 2, qi = idx & 3;
        const float* qv = q3 + qi*72;
        const float* op = Ob + (size_t)p*128;
        const float* sp = g_S + p*64;
        float s = 0.f;
        #pragma unroll
        for (int k=0;k<8;k++)  s += op[k]*qv[k];
        #pragma unroll 8
        for (int k=0;k<64;k++) s += sp[k]*qv[8+k];
        sA[idx] = s;
    }
    __syncthreads();

    {
        int qi = tid >> 6, lane = tid & 63;
        float m = -1e30f;
        for (int p=lane;p<540;p+=64) m = fmaxf(m, sA[p*4+qi]);
        red[tid] = m;
        __syncthreads();
        if (tid < 4) { float mm=-1e30f; for (int i=0;i<64;i++) mm = fmaxf(mm, red[tid*64+i]); mx[tid]=mm; }
        __syncthreads();
        for (int idx=tid; idx<2160; idx+=256) sA[idx] = expf(sA[idx]-mx[idx&3]);
        __syncthreads();
        float s = 0.f;
        for (int p=lane;p<540;p+=64) s += sA[p*4+qi];
        red[tid] = s;
        __syncthreads();
        if (tid < 4) { float ss=0.f; for (int i=0;i<64;i++) ss += red[tid*64+i]; sm[tid]=ss; }
        __syncthreads();
    }

    for (int o=tid;o<736;o+=256) {
        int qi = o / 184, v = o - qi*184;
        float s = 0.f;
        if (v < 120) {
            const float* ov = Ob + 8 + v;
            for (int p=0;p<540;p++) s += sA[p*4+qi]*ov[(size_t)p*128];
        } else {
            const float* sv = g_S + (v-120);
            for (int p=0;p<540;p++) s += sA[p*4+qi]*sv[p*64];
        }
        ans[o] = s / sm[qi];
    }
    __syncthreads();

    float rclip = fminf(fmaxf(reward[t*16+b], -1.f), 1.f);
    int act = last_action[t*16+b];

    for (int j=tid;j<512;j+=256) {
        float s = ab1[j];
        for (int k=0;k<736;k++) s += ans[k]*aw1[(size_t)k*512+j];
        for (int k=0;k<288;k++) s += q3[k]*aw1[(size_t)(736+k)*512+j];
        s += rclip * aw1[(size_t)1024*512+j];
        s += aw1[(size_t)(1025+act)*512+j];
        a1[j] = fmaxf(s, 0.f);
    }
    __syncthreads();
    {
        float s = ab2[tid];
        for (int k=0;k<512;k++) s += a1[k]*aw2[(size_t)k*256+tid];
        ci[tid] = s;
    }
    __syncthreads();

    float nd = (done[t*16+b]==0) ? 1.f : 0.f;
    float g4[4];
    #pragma unroll
    for (int gg=0;gg<4;gg++) {
        int j = gg*256 + tid;
        const float* wi = w_ih + (size_t)j*256;
        const float* wh = w_hh + (size_t)j*256;
        float s1 = 0.f, s2 = 0.f;
        for (int k=0;k<256;k++) { s1 += ci[k]*wi[k]; s2 += sh[k]*wh[k]; }
        g4[gg] = s1 + nd*s2 + b_ih[j] + b_hh[j];
    }
    float gi=g4[0], gf=g4[1], gG=g4[2], go=g4[3];
    float c = nd * g_cc[b*256+tid];
    c = sigmoidf_(gf)*c + sigmoidf_(gi)*tanhf(gG);
    float h = sigmoidf_(go)*tanhf(c);
    g_cc[b*256+tid] = c;
    g_ch[b*256+tid] = h;
    g_outs[((size_t)t*16+b)*256 + tid] = h;
}

// ------------------------------- heads -------------------------------------
__global__ void head_kernel(const float* __restrict__ pw, const float* __restrict__ pb,
                            const float* __restrict__ vw, const float* __restrict__ vb,
                            float* __restrict__ out)
{
    int row = blockIdx.x;
    int tid = threadIdx.x;
    __shared__ float lg[18];
    const float* h = g_outs + (size_t)row*256;
    if (tid < 18) {
        float s = pb[tid];
        for (int k=0;k<256;k++) s += h[k]*pw[k*18+tid];
        lg[tid] = s;
        out[row*18 + tid] = s;
    }
    if (tid == 19) {
        float s = vb[0];
        for (int k=0;k<256;k++) s += h[k]*vw[k];
        out[9216 + row] = s;
    }
    __syncthreads();
    if (tid == 0) {
        int am = 0; float bv = lg[0];
        for (int j=1;j<18;j++) if (lg[j] > bv) { bv = lg[j]; am = j; }
        out[9728 + row] = (float)am;
    }
}

__global__ void write_states(float* __restrict__ out) {
    int i = blockIdx.x*blockDim.x + threadIdx.x;
    if (i < 4096) { out[10240 + i] = g_ch[i]; out[14336 + i] = g_cc[i]; }
    if (i < 1105920) { out[18432 + i] = g_h[i]; out[1124352 + i] = g_c[i]; }
}

// ------------------------------- launch ------------------------------------
extern "C" void kernel_launch(void* const* d_in, const int* in_sizes, int n_in,
                              void* d_out, int out_size) {
    const float*         frame      = (const float*)d_in[0];
    const unsigned char* done       = (const unsigned char*)d_in[1];
    const int*           last_action= (const int*)d_in[2];
    const float*         reward     = (const float*)d_in[3];
    const float*         core_h     = (const float*)d_in[4];
    const float*         core_c     = (const float*)d_in[5];
    const float*         conv_h     = (const float*)d_in[6];
    const float*         conv_c     = (const float*)d_in[7];
    const float*         cnn_w1     = (const float*)d_in[8];
    const float*         cnn_b1     = (const float*)d_in[9];
    const float*         cnn_w2     = (const float*)d_in[10];
    const float*         cnn_b2     = (const float*)d_in[11];
    const float*         lstm_w     = (const float*)d_in[12];
    const float*         lstm_b     = (const float*)d_in[13];
    const float*         qw1        = (const float*)d_in[14];
    const float*         qb1        = (const float*)d_in[15];
    const float*         qw2        = (const float*)d_in[16];
    const float*         qb2        = (const float*)d_in[17];
    const float*         qw3        = (const float*)d_in[18];
    const float*         qb3        = (const float*)d_in[19];
    const float*         aw1        = (const float*)d_in[20];
    const float*         ab1        = (const float*)d_in[21];
    const float*         aw2        = (const float*)d_in[22];
    const float*         ab2        = (const float*)d_in[23];
    const float*         w_ih       = (const float*)d_in[24];
    const float*         w_hh       = (const float*)d_in[25];
    const float*         b_ih       = (const float*)d_in[26];
    const float*         b_hh       = (const float*)d_in[27];
    const float*         pw         = (const float*)d_in[28];
    const float*         pb         = (const float*)d_in[29];
    const float*         vw         = (const float*)d_in[30];
    const float*         vb         = (const float*)d_in[31];
    float* out = (float*)d_out;

    init_kernel<<<4320, 256>>>(core_h, core_c, conv_h, conv_c);

    // conv1: N = 512*2080 -> 16640 tiles of 64
    gemm_conv<0><<<dim3(16640,1), 256>>>(cnn_w1, cnn_b1, frame);
    // conv2: N = 512*540 -> 4320 tiles
    gemm_conv<1><<<dim3(4320,1), 256>>>(cnn_w2, cnn_b2, frame);
    // Gx for ALL timesteps: M=512, N=276480 -> (2160, 4) tiles of 128x128
    gemm_conv8<2><<<dim3(2160,4), 256>>>(lstm_w, lstm_b, 0, done);

    for (int t = 0; t < NT; t++) {
        // gates = Gx[t] + conv_h(nd*h): M=512, N=8640 -> (68, 4) tiles
        gemm_conv8<3><<<dim3(68,4), 256>>>(lstm_w, lstm_b, t, done);
        convlstm_update<<<4320, 256>>>(t, done);
        core_step<<<16, 256>>>(t, done, qw1,qb1,qw2,qb2,qw3,qb3,
                               aw1,ab1,aw2,ab2, w_ih,w_hh,b_ih,b_hh,
                               last_action, reward);
    }

    head_kernel<<<512, 32>>>(pw, pb, vw, vb, out);
    write_states<<<4320, 256>>>(out);
}

// round 6
// speedup vs baseline: 1.1800x; 1.1179x over previous
#include <cuda_runtime.h>
#include <cuda_bf16.h>
#include <math.h>
#include <cstdint>

// ---------------------------------------------------------------------------
// AttentionNet: conv1 -> conv2 -> ConvLSTM(T=32) -> attention core LSTM(T=32)
// Big 3x3-conv GEMMs on HMMA (mma.sync bf16 hi/lo split, fp32 accumulate).
// ---------------------------------------------------------------------------

#define NT 32

// ------------------------- static device scratch ---------------------------
__device__ float g_conv1[512u*32*2080];          // (512,32,52,40)
__device__ float g_x    [512u*64*540];           // (512,64,27,20) fp32
__device__ float g_Gx   [141557760u];            // (512,512,540) x-part of gates + bias
__device__ float g_O    [512u*128*540];          // (T*B,128,540) RAW NCHW h outputs
__device__ float g_gates[16u*512*540];           // per-step gates
__device__ float g_h    [16*128*540];            // conv h state (fp32)
__device__ float g_c    [16*128*540];            // conv c state
__device__ float g_S    [540*64];                // spatial basis
__device__ float g_ch   [16*256];                // core h
__device__ float g_cc   [16*256];                // core c
__device__ float g_outs [32*16*256];             // core outputs per step

// bf16-split operands
__device__ __align__(16) __nv_bfloat16 g_Whi[512u*1728];
__device__ __align__(16) __nv_bfloat16 g_Wlo[512u*1728];
__device__ unsigned int g_xsplit[512u*64*540];   // packed hi | lo<<16
__device__ unsigned int g_hsplit[16u*128*540];   // packed hi | lo<<16

__device__ __forceinline__ float sigmoidf_(float x) { return 1.f/(1.f+expf(-x)); }

__device__ __forceinline__ unsigned int pack_split(float f) {
    __nv_bfloat16 h = __float2bfloat16(f);
    float hf = __bfloat162float(h);
    __nv_bfloat16 l = __float2bfloat16(f - hf);
    unsigned short hu = *reinterpret_cast<unsigned short*>(&h);
    unsigned short lu = *reinterpret_cast<unsigned short*>(&l);
    return (unsigned int)hu | ((unsigned int)lu << 16);
}

// ----------------------------- mma helpers ---------------------------------
__device__ __forceinline__ uint32_t smem_u32(const void* p) {
    uint32_t a;
    asm("{ .reg .u64 t; cvta.to.shared.u64 t, %1; cvt.u32.u64 %0, t; }" : "=r"(a) : "l"(p));
    return a;
}
__device__ __forceinline__ void ldsm_x4(uint32_t* r, uint32_t addr) {
    asm volatile("ldmatrix.sync.aligned.m8n8.x4.shared.b16 {%0,%1,%2,%3}, [%4];"
        : "=r"(r[0]), "=r"(r[1]), "=r"(r[2]), "=r"(r[3]) : "r"(addr));
}
__device__ __forceinline__ void ldsm_x2(uint32_t* r, uint32_t addr) {
    asm volatile("ldmatrix.sync.aligned.m8n8.x2.shared.b16 {%0,%1}, [%2];"
        : "=r"(r[0]), "=r"(r[1]) : "r"(addr));
}
__device__ __forceinline__ void mma16816(float* d, const uint32_t* a, const uint32_t* b) {
    asm volatile(
        "mma.sync.aligned.m16n8k16.row.col.f32.bf16.bf16.f32 "
        "{%0,%1,%2,%3}, {%4,%5,%6,%7}, {%8,%9}, {%0,%1,%2,%3};"
        : "+f"(d[0]), "+f"(d[1]), "+f"(d[2]), "+f"(d[3])
        : "r"(a[0]), "r"(a[1]), "r"(a[2]), "r"(a[3]), "r"(b[0]), "r"(b[1]));
}

// ------------------------------ init -------------------------------------
__global__ void init_kernel(const float* __restrict__ core_h, const float* __restrict__ core_c,
                            const float* __restrict__ conv_h, const float* __restrict__ conv_c) {
    int i = blockIdx.x*blockDim.x + threadIdx.x;
    if (i < 540*64) {
        int p = i >> 6, k = i & 63;
        int y = p/20, x = p - y*20;
        int u = k >> 3, v = k & 7;
        double PI = 3.14159265358979323846;
        g_S[i] = (float)(cos((double)(y+1)*(u+1)*PI/27.0) * cos((double)(x+1)*(v+1)*PI/20.0));
    }
    if (i < 16*256) { g_ch[i] = core_h[i]; g_cc[i] = core_c[i]; }
    if (i < 16*128*540) {
        g_h[i] = conv_h[i]; g_c[i] = conv_c[i];
        g_hsplit[i] = pack_split(conv_h[i]);
    }
}

__global__ void split_w_kernel(const float* __restrict__ w) {
    int i = blockIdx.x*blockDim.x + threadIdx.x;
    if (i >= 512*1728) return;
    float f = w[i];
    __nv_bfloat16 h = __float2bfloat16(f);
    __nv_bfloat16 l = __float2bfloat16(f - __bfloat162float(h));
    g_Whi[i] = h; g_Wlo[i] = l;
}

__global__ void split_x_kernel() {
    int i = blockIdx.x*blockDim.x + threadIdx.x;
    if (i < 512*64*540) g_xsplit[i] = pack_split(g_x[i]);
}

// -------------------- small-conv implicit-GEMM (SIMT) ----------------------
template<int MODE> struct GP;
template<> struct GP<0>{ static constexpr int M=32,  K=192, IH=210,IW=160,OH=52,OW=40,KH=8,KW=8,SH=4,SW=4,PH=1,PW=2,WS=192; };
template<> struct GP<1>{ static constexpr int M=64,  K=512, IH=52, IW=40, OH=27,OW=20,KH=4,KW=4,SH=2,SW=2,PH=2,PW=1,WS=512; };

template<int MODE>
__global__ void __launch_bounds__(256)
gemm_conv(const float* __restrict__ W, const float* __restrict__ bias,
          const float* __restrict__ frame)
{
    using G = GP<MODE>;
    constexpr int PPI = G::OH * G::OW;
    __shared__ float As[16][64];
    __shared__ float Bs[16][64];

    int tid = threadIdx.x;
    int n0 = blockIdx.x * 64;
    int m0 = blockIdx.y * 64;
    int tx = tid & 15, ty = tid >> 4;

    float acc[4][4];
    #pragma unroll
    for (int i=0;i<4;i++)
        #pragma unroll
        for (int j=0;j<4;j++) acc[i][j] = 0.f;

    int a_m = m0 + (tid >> 2);
    int a_k = (tid & 3) * 4;

    int b_n = n0 + (tid & 63);
    int img = b_n / PPI;
    int pos = b_n - img * PPI;
    int oy  = pos / G::OW;
    int ox  = pos - oy * G::OW;
    int iy0 = oy * G::SH - G::PH;
    int ix0 = ox * G::SW - G::PW;

    const float* bbase;
    if constexpr (MODE==0) bbase = frame   + (size_t)img * (3*210*160);
    else                   bbase = g_conv1 + (size_t)img * (32*52*40);

    for (int k0 = 0; k0 < G::K; k0 += 16) {
        float4 av4;
        if (G::M % 64 == 0 || a_m < G::M)
            av4 = *reinterpret_cast<const float4*>(W + (size_t)a_m * G::WS + k0 + a_k);
        else
            av4 = make_float4(0.f,0.f,0.f,0.f);
        As[a_k+0][tid>>2] = av4.x;
        As[a_k+1][tid>>2] = av4.y;
        As[a_k+2][tid>>2] = av4.z;
        As[a_k+3][tid>>2] = av4.w;

        #pragma unroll
        for (int j=0;j<4;j++) {
            int kk = (tid>>6) + j*4;
            int k  = k0 + kk;
            int c  = k / (G::KH*G::KW);
            int rs = k - c*(G::KH*G::KW);
            int r  = rs / G::KW;
            int s  = rs - r*G::KW;
            int iy = iy0 + r, ix = ix0 + s;
            float v = 0.f;
            if (iy >= 0 && iy < G::IH && ix >= 0 && ix < G::IW)
                v = bbase[((size_t)c*G::IH + iy)*G::IW + ix];
            Bs[kk][tid & 63] = v;
        }
        __syncthreads();

        #pragma unroll
        for (int kk=0;kk<16;kk++) {
            float4 a4 = *reinterpret_cast<const float4*>(&As[kk][ty*4]);
            float4 b4 = *reinterpret_cast<const float4*>(&Bs[kk][tx*4]);
            float a[4] = {a4.x,a4.y,a4.z,a4.w};
            float b[4] = {b4.x,b4.y,b4.z,b4.w};
            #pragma unroll
            for (int i=0;i<4;i++)
                #pragma unroll
                for (int j=0;j<4;j++) acc[i][j] += a[i]*b[j];
        }
        __syncthreads();
    }

    #pragma unroll
    for (int i=0;i<4;i++) {
        int m = m0 + ty*4 + i;
        if (G::M % 64 != 0 && m >= G::M) continue;
        #pragma unroll
        for (int j=0;j<4;j++) {
            int n  = n0 + tx*4 + j;
            int im = n / PPI;
            int pp = n - im*PPI;
            float v = acc[i][j] + bias[m];
            if constexpr (MODE==0) g_conv1[(size_t)(im*32+m)*2080 + pp] = v;
            else                   g_x[(size_t)(im*64+m)*540 + pp] = v;
        }
    }
}

// ---------------- HMMA GEMM for the 3x3 convs (bf16 hi/lo split) -----------
// C[128(M-tile), 128(N-tile)] per CTA; grid.y = 4 M-tiles (M=512).
// MODE2: K=576,  B = g_xsplit, out g_Gx (+bias).
// MODE3: K=1152, B = g_hsplit (done-masked), out g_gates (+Gx[t]).
static constexpr int OFF_AHI = 0;
static constexpr int OFF_ALO = 10240;
static constexpr int OFF_BHI = 20480;
static constexpr int OFF_BLO = 30720;
static constexpr int SMEM_MMA = 128*132*4;        // 67584 (stage; tiles fit inside)

template<int MODE>
__global__ void __launch_bounds__(256, 1)
gemm_mma(const float* __restrict__ bias, int t, const unsigned char* __restrict__ done)
{
    constexpr int KTOT  = (MODE==2) ? 576 : 1152;
    constexpr int WO    = (MODE==2) ? 0   : 576;
    constexpr int NTOT  = (MODE==2) ? 512*540 : 16*540;
    constexpr int NCH   = (MODE==2) ? 64  : 128;
    constexpr int NCHUNK= KTOT/32;

    extern __shared__ char smem[];
    uint32_t sb = smem_u32(smem);
    int tid  = threadIdx.x;
    int wid  = tid >> 5;
    int lane = tid & 31;

    int n0 = blockIdx.x * 128;
    int m0 = blockIdx.y * 128;

    // ---- per-thread B-gather coords ----
    int nn    = tid & 127;
    int khalf = tid >> 7;                 // 0/1 -> k 0-15 / 16-31 of chunk
    int bn    = n0 + nn;
    bool nvalid = (bn < NTOT);
    int bnc = nvalid ? bn : 0;
    int img = bnc / 540;
    int pos = bnc - img * 540;
    int oy = pos / 20, ox = pos - oy * 20;
    int iy0 = oy - 1, ix0 = ox - 1;
    const unsigned int* bsrc =
        (MODE==2 ? g_xsplit : g_hsplit) + (size_t)img * NCH * 540;
    if (MODE == 3 && nvalid && done[t*16 + img]) nvalid = false;

    // ---- per-thread A-load coords (2 uint4 per split) ----
    int a_r0 = (tid*2)   >> 2;  int a_k0 = ((tid*2)   & 3) * 8;
    int a_r1 = (tid*2+1) >> 2;  int a_k1 = ((tid*2+1) & 3) * 8;

    // ---- warp tile ----
    int wm = (wid >> 2) * 64;
    int wn = (wid & 3) * 32;

    float cfr[4][4][4];
    #pragma unroll
    for (int mi=0;mi<4;mi++)
        #pragma unroll
        for (int ni=0;ni<4;ni++)
            #pragma unroll
            for (int e=0;e<4;e++) cfr[mi][ni][e] = 0.f;

    uint4   pa[4];     // A prefetch: [split*2 + j]
    uint32_t pb[16];   // B prefetch (packed u32)

    // prefetch chunk 0
    {
        const __nv_bfloat16* whi = g_Whi;
        const __nv_bfloat16* wlo = g_Wlo;
        pa[0] = *reinterpret_cast<const uint4*>(whi + (size_t)(m0+a_r0)*1728 + WO + a_k0);
        pa[1] = *reinterpret_cast<const uint4*>(whi + (size_t)(m0+a_r1)*1728 + WO + a_k1);
        pa[2] = *reinterpret_cast<const uint4*>(wlo + (size_t)(m0+a_r0)*1728 + WO + a_k0);
        pa[3] = *reinterpret_cast<const uint4*>(wlo + (size_t)(m0+a_r1)*1728 + WO + a_k1);
        #pragma unroll
        for (int i=0;i<16;i++) {
            int gk = khalf*16 + i;
            unsigned int v = 0;
            if (nvalid) {
                int c = gk/9, rs = gk - c*9, r = rs/3, s2 = rs - r*3;
                int iy = iy0 + r, ix = ix0 + s2;
                if (iy>=0 && iy<27 && ix>=0 && ix<20) v = bsrc[(c*27+iy)*20+ix];
            }
            pb[i] = v;
        }
    }

    for (int ch = 0; ch < NCHUNK; ch++) {
        // ---- store prefetched chunk to smem ----
        *reinterpret_cast<uint4*>(smem + OFF_AHI + (a_r0*40 + a_k0)*2) = pa[0];
        *reinterpret_cast<uint4*>(smem + OFF_AHI + (a_r1*40 + a_k1)*2) = pa[1];
        *reinterpret_cast<uint4*>(smem + OFF_ALO + (a_r0*40 + a_k0)*2) = pa[2];
        *reinterpret_cast<uint4*>(smem + OFF_ALO + (a_r1*40 + a_k1)*2) = pa[3];
        {
            int kb = khalf*16;
            #pragma unroll
            for (int i=0;i<16;i+=2) {
                uint32_t v0 = pb[i], v1 = pb[i+1];
                uint32_t hi = (v0 & 0xFFFFu) | (v1 << 16);
                uint32_t lo = (v0 >> 16) | (v1 & 0xFFFF0000u);
                *reinterpret_cast<uint32_t*>(smem + OFF_BHI + (nn*40 + kb + i)*2) = hi;
                *reinterpret_cast<uint32_t*>(smem + OFF_BLO + (nn*40 + kb + i)*2) = lo;
            }
        }
        __syncthreads();

        // ---- prefetch next chunk (LDGs overlap the MMAs below) ----
        if (ch + 1 < NCHUNK) {
            int k0 = (ch+1)*32;
            pa[0] = *reinterpret_cast<const uint4*>(g_Whi + (size_t)(m0+a_r0)*1728 + WO + k0 + a_k0);
            pa[1] = *reinterpret_cast<const uint4*>(g_Whi + (size_t)(m0+a_r1)*1728 + WO + k0 + a_k1);
            pa[2] = *reinterpret_cast<const uint4*>(g_Wlo + (size_t)(m0+a_r0)*1728 + WO + k0 + a_k0);
            pa[3] = *reinterpret_cast<const uint4*>(g_Wlo + (size_t)(m0+a_r1)*1728 + WO + k0 + a_k1);
            #pragma unroll
            for (int i=0;i<16;i++) {
                int gk = k0 + khalf*16 + i;
                unsigned int v = 0;
                if (nvalid) {
                    int c = gk/9, rs = gk - c*9, r = rs/3, s2 = rs - r*3;
                    int iy = iy0 + r, ix = ix0 + s2;
                    if (iy>=0 && iy<27 && ix>=0 && ix<20) v = bsrc[(c*27+iy)*20+ix];
                }
                pb[i] = v;
            }
        }

        // ---- MMA on current chunk ----
        #pragma unroll
        for (int kk = 0; kk < 32; kk += 16) {
            uint32_t af[4][4], bfh[4][2], bfl[4][2];
            // A-hi frags
            {
                uint32_t row = wm + (lane & 15);
                uint32_t col = kk + (lane >> 4) * 8;
                #pragma unroll
                for (int mi=0;mi<4;mi++)
                    ldsm_x4(af[mi], sb + OFF_AHI + ((row + mi*16)*40 + col)*2);
            }
            // B-hi / B-lo frags
            {
                int l2 = lane & 15;
                uint32_t row = wn + (l2 & 7);
                uint32_t col = kk + (l2 >> 3) * 8;
                #pragma unroll
                for (int ni=0;ni<4;ni++) {
                    ldsm_x2(bfh[ni], sb + OFF_BHI + ((row + ni*8)*40 + col)*2);
                    ldsm_x2(bfl[ni], sb + OFF_BLO + ((row + ni*8)*40 + col)*2);
                }
            }
            // hi*hi and hi*lo
            #pragma unroll
            for (int mi=0;mi<4;mi++)
                #pragma unroll
                for (int ni=0;ni<4;ni++) {
                    mma16816(cfr[mi][ni], af[mi], bfh[ni]);
                    mma16816(cfr[mi][ni], af[mi], bfl[ni]);
                }
            // A-lo frags, lo*hi
            {
                uint32_t row = wm + (lane & 15);
                uint32_t col = kk + (lane >> 4) * 8;
                #pragma unroll
                for (int mi=0;mi<4;mi++)
                    ldsm_x4(af[mi], sb + OFF_ALO + ((row + mi*16)*40 + col)*2);
            }
            #pragma unroll
            for (int mi=0;mi<4;mi++)
                #pragma unroll
                for (int ni=0;ni<4;ni++)
                    mma16816(cfr[mi][ni], af[mi], bfh[ni]);
        }
        __syncthreads();
    }

    // ---- epilogue: frags -> smem stage -> coalesced global writes ----
    float* stage = reinterpret_cast<float*>(smem);
    int gid = lane >> 2, tig = lane & 3;
    #pragma unroll
    for (int mi=0;mi<4;mi++)
        #pragma unroll
        for (int ni=0;ni<4;ni++) {
            int r0 = wm + mi*16 + gid;
            int c0 = wn + ni*8 + tig*2;
            stage[r0*132 + c0]       = cfr[mi][ni][0];
            stage[r0*132 + c0 + 1]   = cfr[mi][ni][1];
            stage[(r0+8)*132 + c0]   = cfr[mi][ni][2];
            stage[(r0+8)*132 + c0+1] = cfr[mi][ni][3];
        }
    __syncthreads();

    for (int idx = tid; idx < 128*128; idx += 256) {
        int r = idx >> 7, c2 = idx & 127;
        int n = n0 + c2;
        if (MODE == 3 && n >= NTOT) continue;
        int m  = m0 + r;
        int im = n / 540;
        int pp = n - im*540;
        float v = stage[r*132 + c2];
        if constexpr (MODE == 2) {
            g_Gx[((size_t)im*512 + m)*540 + pp] = v + bias[m];
        } else {
            g_gates[((size_t)im*512 + m)*540 + pp] =
                v + g_Gx[(((size_t)(t*16 + im))*512 + m)*540 + pp];
        }
    }
}

// ------------------------- ConvLSTM pointwise update ------------------------
__global__ void convlstm_update(int t, const unsigned char* __restrict__ done) {
    int i = blockIdx.x*blockDim.x + threadIdx.x;
    if (i >= 16*128*540) return;
    int b   = i / (128*540);
    int rem = i - b*(128*540);
    int ch  = rem / 540;
    int p   = rem - ch*540;
    float nd = (done[t*16+b]==0) ? 1.f : 0.f;
    const float* gb = g_gates + (size_t)b*512*540;
    float ai = gb[(      ch)*540 + p];
    float af = gb[(128 + ch)*540 + p];
    float ao = gb[(256 + ch)*540 + p];
    float ag = gb[(384 + ch)*540 + p];
    float c  = g_c[i] * nd;
    c = sigmoidf_(af)*c + sigmoidf_(ai)*tanhf(ag);
    float h = sigmoidf_(ao)*tanhf(c);
    g_c[i] = c;
    g_h[i] = h;
    g_hsplit[i] = pack_split(h);
    // RAW NCHW flat order (reference's raw reshape semantics).
    g_O[((size_t)(t*16+b))*69120 + (size_t)ch*540 + p] = h;
}

// --------------------------- fused core step -------------------------------
__global__ void __launch_bounds__(256)
core_step(int t, const unsigned char* __restrict__ done,
          const float* __restrict__ qw1, const float* __restrict__ qb1,
          const float* __restrict__ qw2, const float* __restrict__ qb2,
          const float* __restrict__ qw3, const float* __restrict__ qb3,
          const float* __restrict__ aw1, const float* __restrict__ ab1,
          const float* __restrict__ aw2, const float* __restrict__ ab2,
          const float* __restrict__ w_ih, const float* __restrict__ w_hh,
          const float* __restrict__ b_ih, const float* __restrict__ b_hh,
          const int* __restrict__ last_action, const float* __restrict__ reward)
{
    int b = blockIdx.x;
    int tid = threadIdx.x;

    __shared__ float sh[256];
    __shared__ float q1[128];
    __shared__ float q2[288];
    __shared__ float q3[288];
    __shared__ float sA[540*4];
    __shared__ float red[256];
    __shared__ float mx[4], sm[4];
    __shared__ float ans[736];
    __shared__ float a1[512];
    __shared__ float ci[256];

    sh[tid] = g_ch[b*256 + tid];
    __syncthreads();

    if (tid < 128) {
        float s = qb1[tid];
        for (int k=0;k<256;k++) s += sh[k]*qw1[k*128+tid];
        q1[tid] = fmaxf(s, 0.f);
    }
    __syncthreads();
    for (int j=tid;j<288;j+=256) {
        float s = qb2[j];
        for (int k=0;k<128;k++) s += q1[k]*qw2[k*288+j];
        q2[j] = fmaxf(s, 0.f);
    }
    __syncthreads();
    for (int j=tid;j<288;j+=256) {
        float s = qb3[j];
        for (int k=0;k<288;k++) s += q2[k]*qw3[k*288+j];
        q3[j] = s;
    }
    __syncthreads();

    const float* Ob = g_O + ((size_t)(t*16+b))*69120;
    for (int idx=tid; idx<2160; idx+=256) {
        int p = idx >> 2, qi = idx & 3;
        const float* qv = q3 + qi*72;
        const float* op = Ob + (size_t)p*128;
        const float* sp = g_S + p*64;
        float s = 0.f;
        #pragma unroll
        for (int k=0;k<8;k++)  s += op[k]*qv[k];
        #pragma unroll 8
        for (int k=0;k<64;k++) s += sp[k]*qv[8+k];
        sA[idx] = s;
    }
    __syncthreads();

    {
        int qi = tid >> 6, lane = tid & 63;
        float m = -1e30f;
        for (int p=lane;p<540;p+=64) m = fmaxf(m, sA[p*4+qi]);
        red[tid] = m;
        __syncthreads();
        if (tid < 4) { float mm=-1e30f; for (int i=0;i<64;i++) mm = fmaxf(mm, red[tid*64+i]); mx[tid]=mm; }
        __syncthreads();
        for (int idx=tid; idx<2160; idx+=256) sA[idx] = expf(sA[idx]-mx[idx&3]);
        __syncthreads();
        float s = 0.f;
        for (int p=lane;p<540;p+=64) s += sA[p*4+qi];
        red[tid] = s;
        __syncthreads();
        if (tid < 4) { float ss=0.f; for (int i=0;i<64;i++) ss += red[tid*64+i]; sm[tid]=ss; }
        __syncthreads();
    }

    for (int o=tid;o<736;o+=256) {
        int qi = o / 184, v = o - qi*184;
        float s = 0.f;
        if (v < 120) {
            const float* ov = Ob + 8 + v;
            for (int p=0;p<540;p++) s += sA[p*4+qi]*ov[(size_t)p*128];
        } else {
            const float* sv = g_S + (v-120);
            for (int p=0;p<540;p++) s += sA[p*4+qi]*sv[p*64];
        }
        ans[o] = s / sm[qi];
    }
    __syncthreads();

    float rclip = fminf(fmaxf(reward[t*16+b], -1.f), 1.f);
    int act = last_action[t*16+b];

    for (int j=tid;j<512;j+=256) {
        float s = ab1[j];
        for (int k=0;k<736;k++) s += ans[k]*aw1[(size_t)k*512+j];
        for (int k=0;k<288;k++) s += q3[k]*aw1[(size_t)(736+k)*512+j];
        s += rclip * aw1[(size_t)1024*512+j];
        s += aw1[(size_t)(1025+act)*512+j];
        a1[j] = fmaxf(s, 0.f);
    }
    __syncthreads();
    {
        float s = ab2[tid];
        for (int k=0;k<512;k++) s += a1[k]*aw2[(size_t)k*256+tid];
        ci[tid] = s;
    }
    __syncthreads();

    float nd = (done[t*16+b]==0) ? 1.f : 0.f;
    float g4[4];
    #pragma unroll
    for (int gg=0;gg<4;gg++) {
        int j = gg*256 + tid;
        const float* wi = w_ih + (size_t)j*256;
        const float* wh = w_hh + (size_t)j*256;
        float s1 = 0.f, s2 = 0.f;
        for (int k=0;k<256;k++) { s1 += ci[k]*wi[k]; s2 += sh[k]*wh[k]; }
        g4[gg] = s1 + nd*s2 + b_ih[j] + b_hh[j];
    }
    float gi=g4[0], gf=g4[1], gG=g4[2], go=g4[3];
    float c = nd * g_cc[b*256+tid];
    c = sigmoidf_(gf)*c + sigmoidf_(gi)*tanhf(gG);
    float h = sigmoidf_(go)*tanhf(c);
    g_cc[b*256+tid] = c;
    g_ch[b*256+tid] = h;
    g_outs[((size_t)t*16+b)*256 + tid] = h;
}

// ------------------------------- heads -------------------------------------
__global__ void head_kernel(const float* __restrict__ pw, const float* __restrict__ pb,
                            const float* __restrict__ vw, const float* __restrict__ vb,
                            float* __restrict__ out)
{
    int row = blockIdx.x;
    int tid = threadIdx.x;
    __shared__ float lg[18];
    const float* h = g_outs + (size_t)row*256;
    if (tid < 18) {
        float s = pb[tid];
        for (int k=0;k<256;k++) s += h[k]*pw[k*18+tid];
        lg[tid] = s;
        out[row*18 + tid] = s;
    }
    if (tid == 19) {
        float s = vb[0];
        for (int k=0;k<256;k++) s += h[k]*vw[k];
        out[9216 + row] = s;
    }
    __syncthreads();
    if (tid == 0) {
        int am = 0; float bv = lg[0];
        for (int j=1;j<18;j++) if (lg[j] > bv) { bv = lg[j]; am = j; }
        out[9728 + row] = (float)am;
    }
}

__global__ void write_states(float* __restrict__ out) {
    int i = blockIdx.x*blockDim.x + threadIdx.x;
    if (i < 4096) { out[10240 + i] = g_ch[i]; out[14336 + i] = g_cc[i]; }
    if (i < 1105920) { out[18432 + i] = g_h[i]; out[1124352 + i] = g_c[i]; }
}

// ------------------------------- launch ------------------------------------
extern "C" void kernel_launch(void* const* d_in, const int* in_sizes, int n_in,
                              void* d_out, int out_size) {
    const float*         frame      = (const float*)d_in[0];
    const unsigned char* done       = (const unsigned char*)d_in[1];
    const int*           last_action= (const int*)d_in[2];
    const float*         reward     = (const float*)d_in[3];
    const float*         core_h     = (const float*)d_in[4];
    const float*         core_c     = (const float*)d_in[5];
    const float*         conv_h     = (const float*)d_in[6];
    const float*         conv_c     = (const float*)d_in[7];
    const float*         cnn_w1     = (const float*)d_in[8];
    const float*         cnn_b1     = (const float*)d_in[9];
    const float*         cnn_w2     = (const float*)d_in[10];
    const float*         cnn_b2     = (const float*)d_in[11];
    const float*         lstm_w     = (const float*)d_in[12];
    const float*         lstm_b     = (const float*)d_in[13];
    const float*         qw1        = (const float*)d_in[14];
    const float*         qb1        = (const float*)d_in[15];
    const float*         qw2        = (const float*)d_in[16];
    const float*         qb2        = (const float*)d_in[17];
    const float*         qw3        = (const float*)d_in[18];
    const float*         qb3        = (const float*)d_in[19];
    const float*         aw1        = (const float*)d_in[20];
    const float*         ab1        = (const float*)d_in[21];
    const float*         aw2        = (const float*)d_in[22];
    const float*         ab2        = (const float*)d_in[23];
    const float*         w_ih       = (const float*)d_in[24];
    const float*         w_hh       = (const float*)d_in[25];
    const float*         b_ih       = (const float*)d_in[26];
    const float*         b_hh       = (const float*)d_in[27];
    const float*         pw         = (const float*)d_in[28];
    const float*         pb         = (const float*)d_in[29];
    const float*         vw         = (const float*)d_in[30];
    const float*         vb         = (const float*)d_in[31];
    float* out = (float*)d_out;

    cudaFuncSetAttribute(gemm_mma<2>, cudaFuncAttributeMaxDynamicSharedMemorySize, SMEM_MMA);
    cudaFuncSetAttribute(gemm_mma<3>, cudaFuncAttributeMaxDynamicSharedMemorySize, SMEM_MMA);

    init_kernel<<<4320, 256>>>(core_h, core_c, conv_h, conv_c);
    split_w_kernel<<<3456, 256>>>(lstm_w);

    gemm_conv<0><<<dim3(16640,1), 256>>>(cnn_w1, cnn_b1, frame);
    gemm_conv<1><<<dim3(4320,1), 256>>>(cnn_w2, cnn_b2, frame);
    split_x_kernel<<<69120, 256>>>();

    // Gx for ALL timesteps on HMMA: N = 276480 -> 2160 n-tiles x 4 m-tiles
    gemm_mma<2><<<dim3(2160,4), 256, SMEM_MMA>>>(lstm_b, 0, done);

    for (int t = 0; t < NT; t++) {
        // gates = Gx[t] + conv_h(nd*h): N = 8640 -> 68 n-tiles x 4 m-tiles
        gemm_mma<3><<<dim3(68,4), 256, SMEM_MMA>>>(lstm_b, t, done);
        convlstm_update<<<4320, 256>>>(t, done);
        core_step<<<16, 256>>>(t, done, qw1,qb1,qw2,qb2,qw3,qb3,
                               aw1,ab1,aw2,ab2, w_ih,w_hh,b_ih,b_hh,
                               last_action, reward);
    }

    head_kernel<<<512, 32>>>(pw, pb, vw, vb, out);
    write_states<<<4320, 256>>>(out);
}

// round 10
// speedup vs baseline: 1.9716x; 1.6709x over previous
#include <cuda_runtime.h>
#include <cuda_bf16.h>
#include <math.h>
#include <cstdint>

// ---------------------------------------------------------------------------
// AttentionNet: conv1 -> conv2 -> ConvLSTM(T=32) -> attention core LSTM(T=32)
// 3x3-conv GEMMs on HMMA (bf16 hi/lo 3-split, fp32 acc). ConvLSTM pointwise
// update fused into the h-conv GEMM epilogue; g_hsplit double-buffered.
// R8 fix: MODE3 epilogue reads Gx at (t*16+im), not im.
// ---------------------------------------------------------------------------

#define NT 32
#define HSZ (16u*128*540)

// ------------------------- static device scratch ---------------------------
__device__ float g_conv1[512u*32*2080];          // (512,32,52,40)
__device__ float g_Gx   [141557760u];            // (512,512,540) permuted-row Gx
__device__ float g_O    [512u*128*540];          // (T*B,128,540) RAW NCHW h outputs
__device__ float g_h    [16*128*540];            // conv h state (fp32, final only)
__device__ float g_c    [16*128*540];            // conv c state
__device__ float g_S    [540*64];                // spatial basis
__device__ float g_ch   [16*256];                // core h
__device__ float g_cc   [16*256];                // core c
__device__ float g_outs [32*16*256];             // core outputs per step

// bf16-split operands (rows PERMUTED: row' = my*128 + g*32 + c32)
__device__ __align__(16) __nv_bfloat16 g_Whi[512u*1728];
__device__ __align__(16) __nv_bfloat16 g_Wlo[512u*1728];
__device__ unsigned int g_xsplit[512u*64*540];   // packed hi | lo<<16
__device__ unsigned int g_hsplit[2u*HSZ];        // DOUBLE-BUFFERED packed h

__device__ __forceinline__ float sigmoidf_(float x) { return 1.f/(1.f+expf(-x)); }

__device__ __forceinline__ unsigned int pack_split(float f) {
    __nv_bfloat16 h = __float2bfloat16(f);
    float hf = __bfloat162float(h);
    __nv_bfloat16 l = __float2bfloat16(f - hf);
    unsigned short hu = *reinterpret_cast<unsigned short*>(&h);
    unsigned short lu = *reinterpret_cast<unsigned short*>(&l);
    return (unsigned int)hu | ((unsigned int)lu << 16);
}

// ----------------------------- mma helpers ---------------------------------
__device__ __forceinline__ uint32_t smem_u32(const void* p) {
    uint32_t a;
    asm("{ .reg .u64 t; cvta.to.shared.u64 t, %1; cvt.u32.u64 %0, t; }" : "=r"(a) : "l"(p));
    return a;
}
__device__ __forceinline__ void ldsm_x4(uint32_t* r, uint32_t addr) {
    asm volatile("ldmatrix.sync.aligned.m8n8.x4.shared.b16 {%0,%1,%2,%3}, [%4];"
        : "=r"(r[0]), "=r"(r[1]), "=r"(r[2]), "=r"(r[3]) : "r"(addr));
}
__device__ __forceinline__ void ldsm_x2(uint32_t* r, uint32_t addr) {
    asm volatile("ldmatrix.sync.aligned.m8n8.x2.shared.b16 {%0,%1}, [%2];"
        : "=r"(r[0]), "=r"(r[1]) : "r"(addr));
}
__device__ __forceinline__ void mma16816(float* d, const uint32_t* a, const uint32_t* b) {
    asm volatile(
        "mma.sync.aligned.m16n8k16.row.col.f32.bf16.bf16.f32 "
        "{%0,%1,%2,%3}, {%4,%5,%6,%7}, {%8,%9}, {%0,%1,%2,%3};"
        : "+f"(d[0]), "+f"(d[1]), "+f"(d[2]), "+f"(d[3])
        : "r"(a[0]), "r"(a[1]), "r"(a[2]), "r"(a[3]), "r"(b[0]), "r"(b[1]));
}

// ------------------------------ init -------------------------------------
__global__ void init_kernel(const float* __restrict__ core_h, const float* __restrict__ core_c,
                            const float* __restrict__ conv_h, const float* __restrict__ conv_c) {
    int i = blockIdx.x*blockDim.x + threadIdx.x;
    if (i < 540*64) {
        int p = i >> 6, k = i & 63;
        int y = p/20, x = p - y*20;
        int u = k >> 3, v = k & 7;
        double PI = 3.14159265358979323846;
        g_S[i] = (float)(cos((double)(y+1)*(u+1)*PI/27.0) * cos((double)(x+1)*(v+1)*PI/20.0));
    }
    if (i < 16*256) { g_ch[i] = core_h[i]; g_cc[i] = core_c[i]; }
    if (i < 16*128*540) {
        g_c[i] = conv_c[i];
        g_hsplit[i] = pack_split(conv_h[i]);      // buffer 0
    }
}

// Weight split with GATE-INTERLEAVED row permutation:
// orig row m = g*128 + rr -> perm row = (rr>>5)*128 + g*32 + (rr&31)
__global__ void split_w_kernel(const float* __restrict__ w) {
    int i = blockIdx.x*blockDim.x + threadIdx.x;
    if (i >= 512*1728) return;
    int row = i / 1728, k = i - row*1728;
    int g = row >> 7, rr = row & 127;
    int rp = (rr >> 5)*128 + g*32 + (rr & 31);
    float f = w[i];
    __nv_bfloat16 h = __float2bfloat16(f);
    __nv_bfloat16 l = __float2bfloat16(f - __bfloat162float(h));
    g_Whi[(size_t)rp*1728 + k] = h;
    g_Wlo[(size_t)rp*1728 + k] = l;
}

// -------------------- small-conv implicit-GEMM (SIMT) ----------------------
template<int MODE> struct GP;
template<> struct GP<0>{ static constexpr int M=32,  K=192, IH=210,IW=160,OH=52,OW=40,KH=8,KW=8,SH=4,SW=4,PH=1,PW=2,WS=192; };
template<> struct GP<1>{ static constexpr int M=64,  K=512, IH=52, IW=40, OH=27,OW=20,KH=4,KW=4,SH=2,SW=2,PH=2,PW=1,WS=512; };

template<int MODE>
__global__ void __launch_bounds__(256)
gemm_conv(const float* __restrict__ W, const float* __restrict__ bias,
          const float* __restrict__ frame)
{
    using G = GP<MODE>;
    constexpr int PPI = G::OH * G::OW;
    __shared__ float As[16][64];
    __shared__ float Bs[16][64];

    int tid = threadIdx.x;
    int n0 = blockIdx.x * 64;
    int m0 = blockIdx.y * 64;
    int tx = tid & 15, ty = tid >> 4;

    float acc[4][4];
    #pragma unroll
    for (int i=0;i<4;i++)
        #pragma unroll
        for (int j=0;j<4;j++) acc[i][j] = 0.f;

    int a_m = m0 + (tid >> 2);
    int a_k = (tid & 3) * 4;

    int b_n = n0 + (tid & 63);
    int img = b_n / PPI;
    int pos = b_n - img * PPI;
    int oy  = pos / G::OW;
    int ox  = pos - oy * G::OW;
    int iy0 = oy * G::SH - G::PH;
    int ix0 = ox * G::SW - G::PW;

    const float* bbase;
    if constexpr (MODE==0) bbase = frame   + (size_t)img * (3*210*160);
    else                   bbase = g_conv1 + (size_t)img * (32*52*40);

    for (int k0 = 0; k0 < G::K; k0 += 16) {
        float4 av4;
        if (G::M % 64 == 0 || a_m < G::M)
            av4 = *reinterpret_cast<const float4*>(W + (size_t)a_m * G::WS + k0 + a_k);
        else
            av4 = make_float4(0.f,0.f,0.f,0.f);
        As[a_k+0][tid>>2] = av4.x;
        As[a_k+1][tid>>2] = av4.y;
        As[a_k+2][tid>>2] = av4.z;
        As[a_k+3][tid>>2] = av4.w;

        #pragma unroll
        for (int j=0;j<4;j++) {
            int kk = (tid>>6) + j*4;
            int k  = k0 + kk;
            int c  = k / (G::KH*G::KW);
            int rs = k - c*(G::KH*G::KW);
            int r  = rs / G::KW;
            int s  = rs - r*G::KW;
            int iy = iy0 + r, ix = ix0 + s;
            float v = 0.f;
            if (iy >= 0 && iy < G::IH && ix >= 0 && ix < G::IW)
                v = bbase[((size_t)c*G::IH + iy)*G::IW + ix];
            Bs[kk][tid & 63] = v;
        }
        __syncthreads();

        #pragma unroll
        for (int kk=0;kk<16;kk++) {
            float4 a4 = *reinterpret_cast<const float4*>(&As[kk][ty*4]);
            float4 b4 = *reinterpret_cast<const float4*>(&Bs[kk][tx*4]);
            float a[4] = {a4.x,a4.y,a4.z,a4.w};
            float b[4] = {b4.x,b4.y,b4.z,b4.w};
            #pragma unroll
            for (int i=0;i<4;i++)
                #pragma unroll
                for (int j=0;j<4;j++) acc[i][j] += a[i]*b[j];
        }
        __syncthreads();
    }

    #pragma unroll
    for (int i=0;i<4;i++) {
        int m = m0 + ty*4 + i;
        if (G::M % 64 != 0 && m >= G::M) continue;
        #pragma unroll
        for (int j=0;j<4;j++) {
            int n  = n0 + tx*4 + j;
            int im = n / PPI;
            int pp = n - im*PPI;
            float v = acc[i][j] + bias[m];
            if constexpr (MODE==0) g_conv1[(size_t)(im*32+m)*2080 + pp] = v;
            else                   g_xsplit[(size_t)(im*64+m)*540 + pp] = pack_split(v);
        }
    }
}

// ---------------- HMMA GEMM for the 3x3 convs (bf16 hi/lo split) -----------
static constexpr int OFF_AHI = 0;
static constexpr int OFF_ALO = 10240;
static constexpr int OFF_BHI = 20480;
static constexpr int OFF_BLO = 30720;
static constexpr int OFF_KTAB = 40960;            // 1152 x u32 (mainloop only)
static constexpr int SMEM_MMA = 128*132*4;        // 67584 (stage reuses tiles)

template<int MODE>
__global__ void __launch_bounds__(256, 1)
gemm_mma(const float* __restrict__ bias, int t, const unsigned char* __restrict__ done)
{
    constexpr int KTOT  = (MODE==2) ? 576 : 1152;
    constexpr int WO    = (MODE==2) ? 0   : 576;
    constexpr int NTOT  = (MODE==2) ? 512*540 : 16*540;
    constexpr int NCH   = (MODE==2) ? 64  : 128;
    constexpr int NCHUNK= KTOT/32;

    extern __shared__ char smem[];
    uint32_t sb = smem_u32(smem);
    uint32_t* ktab = reinterpret_cast<uint32_t*>(smem + OFF_KTAB);
    int tid  = threadIdx.x;
    int wid  = tid >> 5;
    int lane = tid & 31;

    int n0 = blockIdx.x * 128;
    int m0 = blockIdx.y * 128;

    // double-buffer pointers (read old h, write new h elsewhere)
    const unsigned int* hread  = g_hsplit + (size_t)(t & 1) * HSZ;
    unsigned int*       hwrite = g_hsplit + (size_t)((t + 1) & 1) * HSZ;

    // ---- build k -> (delta, r, s) table ----
    for (int k = tid; k < KTOT; k += 256) {
        int c = k/9, rs = k - c*9, r = rs/3, s = rs - r*3;
        ktab[k] = (uint32_t)(c*540 + r*20 + s) | ((uint32_t)r << 20) | ((uint32_t)s << 24);
    }

    // ---- per-thread B-gather coords ----
    int nn    = tid & 127;
    int khalf = tid >> 7;
    int bn    = n0 + nn;
    bool nvalid = (bn < NTOT);
    int bnc = nvalid ? bn : 0;
    int img = bnc / 540;
    int pos = bnc - img * 540;
    int oy = pos / 20, ox = pos - oy * 20;
    int iy0 = oy - 1, ix0 = ox - 1;
    const unsigned int* bptr =
        (MODE==2 ? (const unsigned int*)g_xsplit : hread) + (size_t)img * NCH * 540 + (iy0*20 + ix0);
    if (MODE == 3 && nvalid && done[t*16 + img]) nvalid = false;

    // ---- per-thread A-load coords ----
    int a_r0 = (tid*2)   >> 2;  int a_k0 = ((tid*2)   & 3) * 8;
    int a_r1 = (tid*2+1) >> 2;  int a_k1 = ((tid*2+1) & 3) * 8;

    int wm = (wid >> 2) * 64;
    int wn = (wid & 3) * 32;

    float cfr[4][4][4];
    #pragma unroll
    for (int mi=0;mi<4;mi++)
        #pragma unroll
        for (int ni=0;ni<4;ni++)
            #pragma unroll
            for (int e=0;e<4;e++) cfr[mi][ni][e] = 0.f;

    uint4    pa[4];
    uint32_t pb[16];

    __syncthreads();   // ktab ready

    // prefetch chunk 0
    {
        pa[0] = *reinterpret_cast<const uint4*>(g_Whi + (size_t)(m0+a_r0)*1728 + WO + a_k0);
        pa[1] = *reinterpret_cast<const uint4*>(g_Whi + (size_t)(m0+a_r1)*1728 + WO + a_k1);
        pa[2] = *reinterpret_cast<const uint4*>(g_Wlo + (size_t)(m0+a_r0)*1728 + WO + a_k0);
        pa[3] = *reinterpret_cast<const uint4*>(g_Wlo + (size_t)(m0+a_r1)*1728 + WO + a_k1);
        #pragma unroll
        for (int i=0;i<16;i++) {
            uint32_t tv = ktab[khalf*16 + i];
            int r = (tv>>20)&15, s2 = (tv>>24)&15;
            unsigned int v = 0;
            if (nvalid && (unsigned)(iy0+r)<27u && (unsigned)(ix0+s2)<20u)
                v = bptr[tv & 0xFFFFF];
            pb[i] = v;
        }
    }

    for (int ch = 0; ch < NCHUNK; ch++) {
        *reinterpret_cast<uint4*>(smem + OFF_AHI + (a_r0*40 + a_k0)*2) = pa[0];
        *reinterpret_cast<uint4*>(smem + OFF_AHI + (a_r1*40 + a_k1)*2) = pa[1];
        *reinterpret_cast<uint4*>(smem + OFF_ALO + (a_r0*40 + a_k0)*2) = pa[2];
        *reinterpret_cast<uint4*>(smem + OFF_ALO + (a_r1*40 + a_k1)*2) = pa[3];
        {
            int kb = khalf*16;
            #pragma unroll
            for (int i=0;i<16;i+=2) {
                uint32_t v0 = pb[i], v1 = pb[i+1];
                uint32_t hi = (v0 & 0xFFFFu) | (v1 << 16);
                uint32_t lo = (v0 >> 16) | (v1 & 0xFFFF0000u);
                *reinterpret_cast<uint32_t*>(smem + OFF_BHI + (nn*40 + kb + i)*2) = hi;
                *reinterpret_cast<uint32_t*>(smem + OFF_BLO + (nn*40 + kb + i)*2) = lo;
            }
        }
        __syncthreads();

        if (ch + 1 < NCHUNK) {
            int k0 = (ch+1)*32;
            pa[0] = *reinterpret_cast<const uint4*>(g_Whi + (size_t)(m0+a_r0)*1728 + WO + k0 + a_k0);
            pa[1] = *reinterpret_cast<const uint4*>(g_Whi + (size_t)(m0+a_r1)*1728 + WO + k0 + a_k1);
            pa[2] = *reinterpret_cast<const uint4*>(g_Wlo + (size_t)(m0+a_r0)*1728 + WO + k0 + a_k0);
            pa[3] = *reinterpret_cast<const uint4*>(g_Wlo + (size_t)(m0+a_r1)*1728 + WO + k0 + a_k1);
            #pragma unroll
            for (int i=0;i<16;i++) {
                uint32_t tv = ktab[k0 + khalf*16 + i];
                int r = (tv>>20)&15, s2 = (tv>>24)&15;
                unsigned int v = 0;
                if (nvalid && (unsigned)(iy0+r)<27u && (unsigned)(ix0+s2)<20u)
                    v = bptr[tv & 0xFFFFF];
                pb[i] = v;
            }
        }

        #pragma unroll
        for (int kk = 0; kk < 32; kk += 16) {
            uint32_t af[4][4], bfh[4][2], bfl[4][2];
            {
                uint32_t row = wm + (lane & 15);
                uint32_t col = kk + (lane >> 4) * 8;
                #pragma unroll
                for (int mi=0;mi<4;mi++)
                    ldsm_x4(af[mi], sb + OFF_AHI + ((row + mi*16)*40 + col)*2);
            }
            {
                int l2 = lane & 15;
                uint32_t row = wn + (l2 & 7);
                uint32_t col = kk + (l2 >> 3) * 8;
                #pragma unroll
                for (int ni=0;ni<4;ni++) {
                    ldsm_x2(bfh[ni], sb + OFF_BHI + ((row + ni*8)*40 + col)*2);
                    ldsm_x2(bfl[ni], sb + OFF_BLO + ((row + ni*8)*40 + col)*2);
                }
            }
            #pragma unroll
            for (int mi=0;mi<4;mi++)
                #pragma unroll
                for (int ni=0;ni<4;ni++) {
                    mma16816(cfr[mi][ni], af[mi], bfh[ni]);
                    mma16816(cfr[mi][ni], af[mi], bfl[ni]);
                }
            {
                uint32_t row = wm + (lane & 15);
                uint32_t col = kk + (lane >> 4) * 8;
                #pragma unroll
                for (int mi=0;mi<4;mi++)
                    ldsm_x4(af[mi], sb + OFF_ALO + ((row + mi*16)*40 + col)*2);
            }
            #pragma unroll
            for (int mi=0;mi<4;mi++)
                #pragma unroll
                for (int ni=0;ni<4;ni++)
                    mma16816(cfr[mi][ni], af[mi], bfh[ni]);
        }
        __syncthreads();
    }

    // ---- frags -> smem stage ----
    float* stage = reinterpret_cast<float*>(smem);
    int gid = lane >> 2, tig = lane & 3;
    #pragma unroll
    for (int mi=0;mi<4;mi++)
        #pragma unroll
        for (int ni=0;ni<4;ni++) {
            int r0 = wm + mi*16 + gid;
            int c0 = wn + ni*8 + tig*2;
            stage[r0*132 + c0]       = cfr[mi][ni][0];
            stage[r0*132 + c0 + 1]   = cfr[mi][ni][1];
            stage[(r0+8)*132 + c0]   = cfr[mi][ni][2];
            stage[(r0+8)*132 + c0+1] = cfr[mi][ni][3];
        }
    __syncthreads();

    if constexpr (MODE == 2) {
        int my = blockIdx.y;
        for (int idx = tid; idx < 128*128; idx += 256) {
            int r = idx >> 7, c2 = idx & 127;
            int n = n0 + c2;
            int m  = m0 + r;
            int gg = r >> 5, c32 = r & 31;
            int morig = gg*128 + my*32 + c32;
            int im = n / 540;
            int pp = n - im*540;
            g_Gx[((size_t)im*512 + m)*540 + pp] = stage[r*132 + c2] + bias[morig];
        }
    } else {
        // fused ConvLSTM update: stage rows {c32, 32+c32, 64+c32, 96+c32} are
        // (ai, af, ao, ag) for channel my*32+c32.
        int my = blockIdx.y;
        int tb = t*16;
        for (int idx = tid; idx < 32*128; idx += 256) {
            int c32 = idx >> 7, col = idx & 127;
            int n = n0 + col;
            if (n >= 8640) continue;
            int im = n / 540, pp = n - im*540;
            int ch = my*32 + c32;
            // R8 FIX: Gx is indexed by the GLOBAL image (t*16+im), not im.
            size_t gxb = ((size_t)(tb + im)*512 + my*128 + c32)*540 + pp;
            float ai = stage[(     c32)*132 + col] + g_Gx[gxb];
            float af = stage[(32 + c32)*132 + col] + g_Gx[gxb + (size_t)32*540];
            float ao = stage[(64 + c32)*132 + col] + g_Gx[gxb + (size_t)64*540];
            float ag = stage[(96 + c32)*132 + col] + g_Gx[gxb + (size_t)96*540];
            float nd = (done[tb+im]==0) ? 1.f : 0.f;
            int hidx = (im*128 + ch)*540 + pp;
            float c = g_c[hidx] * nd;
            c = sigmoidf_(af)*c + sigmoidf_(ai)*tanhf(ag);
            float h = sigmoidf_(ao)*tanhf(c);
            g_c[hidx] = c;
            g_h[hidx] = h;
            hwrite[hidx] = pack_split(h);
            g_O[(size_t)(tb+im)*69120 + (size_t)ch*540 + pp] = h;
        }
    }
}

// --------------------------- fused core step -------------------------------
__global__ void __launch_bounds__(256)
core_step(int t, const unsigned char* __restrict__ done,
          const float* __restrict__ qw1, const float* __restrict__ qb1,
          const float* __restrict__ qw2, const float* __restrict__ qb2,
          const float* __restrict__ qw3, const float* __restrict__ qb3,
          const float* __restrict__ aw1, const float* __restrict__ ab1,
          const float* __restrict__ aw2, const float* __restrict__ ab2,
          const float* __restrict__ w_ih, const float* __restrict__ w_hh,
          const float* __restrict__ b_ih, const float* __restrict__ b_hh,
          const int* __restrict__ last_action, const float* __restrict__ reward)
{
    int b = blockIdx.x;
    int tid = threadIdx.x;
    int wid = tid >> 5, lane = tid & 31;

    __shared__ float sh[256];
    __shared__ float q1[128];
    __shared__ float q2[288];
    __shared__ float q3[288];
    __shared__ float sA[540*4];
    __shared__ float red[256];
    __shared__ float mx[4], sm[4];
    __shared__ float ans[736];
    __shared__ float a1[512];
    __shared__ float ci[256];
    __shared__ float gsum[1024];

    sh[tid] = g_ch[b*256 + tid];
    __syncthreads();

    if (tid < 128) {
        float s = qb1[tid];
        for (int k=0;k<256;k++) s += sh[k]*qw1[k*128+tid];
        q1[tid] = fmaxf(s, 0.f);
    }
    __syncthreads();
    for (int j=tid;j<288;j+=256) {
        float s = qb2[j];
        for (int k=0;k<128;k++) s += q1[k]*qw2[k*288+j];
        q2[j] = fmaxf(s, 0.f);
    }
    __syncthreads();
    for (int j=tid;j<288;j+=256) {
        float s = qb3[j];
        for (int k=0;k<288;k++) s += q2[k]*qw3[k*288+j];
        q3[j] = s;
    }
    __syncthreads();

    const float* Ob = g_O + ((size_t)(t*16+b))*69120;
    for (int idx=tid; idx<2160; idx+=256) {
        int p = idx >> 2, qi = idx & 3;
        const float* qv = q3 + qi*72;
        const float* op = Ob + (size_t)p*128;
        const float* sp = g_S + p*64;
        float s = 0.f;
        #pragma unroll
        for (int k=0;k<8;k++)  s += op[k]*qv[k];
        #pragma unroll 8
        for (int k=0;k<64;k++) s += sp[k]*qv[8+k];
        sA[idx] = s;
    }
    __syncthreads();

    {
        int qi = tid >> 6, lane6 = tid & 63;
        float m = -1e30f;
        for (int p=lane6;p<540;p+=64) m = fmaxf(m, sA[p*4+qi]);
        red[tid] = m;
        __syncthreads();
        if (tid < 4) { float mm=-1e30f; for (int i=0;i<64;i++) mm = fmaxf(mm, red[tid*64+i]); mx[tid]=mm; }
        __syncthreads();
        for (int idx=tid; idx<2160; idx+=256) sA[idx] = expf(sA[idx]-mx[idx&3]);
        __syncthreads();
        float s = 0.f;
        for (int p=lane6;p<540;p+=64) s += sA[p*4+qi];
        red[tid] = s;
        __syncthreads();
        if (tid < 4) { float ss=0.f; for (int i=0;i<64;i++) ss += red[tid*64+i]; sm[tid]=ss; }
        __syncthreads();
    }

    // ans with 3 parallel accumulators (one p-loop)
    {
        int o0 = tid, o1 = tid+256, o2 = tid+512;
        bool has2 = (o2 < 736);
        int q0 = o0/184, v0 = o0-q0*184;
        int q1i = o1/184, v1 = o1-q1i*184;
        int q2i = has2 ? o2/184 : 0, v2 = has2 ? o2-q2i*184 : 0;
        const float* b0 = (v0<120) ? Ob+8+v0 : g_S+(v0-120);
        const float* b1 = (v1<120) ? Ob+8+v1 : g_S+(v1-120);
        const float* b2 = (v2<120) ? Ob+8+v2 : g_S+(v2-120);
        int s0 = (v0<120)?128:64, s1 = (v1<120)?128:64, s2 = (v2<120)?128:64;
        float a0=0.f, a1v=0.f, a2=0.f;
        #pragma unroll 4
        for (int p=0;p<540;p++) {
            a0  += sA[p*4+q0]  * b0[(size_t)p*s0];
            a1v += sA[p*4+q1i] * b1[(size_t)p*s1];
            if (has2) a2 += sA[p*4+q2i] * b2[(size_t)p*s2];
        }
        ans[o0] = a0 / sm[q0];
        ans[o1] = a1v / sm[q1i];
        if (has2) ans[o2] = a2 / sm[q2i];
    }
    __syncthreads();

    float rclip = fminf(fmaxf(reward[t*16+b], -1.f), 1.f);
    int act = last_action[t*16+b];
    float nd = (done[t*16+b]==0) ? 1.f : 0.f;

    // a1 = relu(answer @ aw1 + ab1): 2 outputs per thread
    {
        int j0 = tid, j1 = tid + 256;
        float s0 = ab1[j0], s1 = ab1[j1];
        for (int k=0;k<736;k++) {
            float f = ans[k];
            s0 += f*aw1[(size_t)k*512+j0];
            s1 += f*aw1[(size_t)k*512+j1];
        }
        for (int k=0;k<288;k++) {
            float f = q3[k];
            s0 += f*aw1[(size_t)(736+k)*512+j0];
            s1 += f*aw1[(size_t)(736+k)*512+j1];
        }
        s0 += rclip*aw1[(size_t)1024*512+j0] + aw1[(size_t)(1025+act)*512+j0];
        s1 += rclip*aw1[(size_t)1024*512+j1] + aw1[(size_t)(1025+act)*512+j1];
        a1[j0] = fmaxf(s0, 0.f);
        a1[j1] = fmaxf(s1, 0.f);
    }
    __syncthreads();
    {
        float s = ab2[tid];
        for (int k=0;k<512;k++) s += a1[k]*aw2[(size_t)k*256+tid];
        ci[tid] = s;
    }
    __syncthreads();

    // LSTM gates: warp-per-output, coalesced reads + shuffle reduce
    for (int j = wid; j < 1024; j += 8) {
        const float* wi = w_ih + (size_t)j*256;
        const float* wh = w_hh + (size_t)j*256;
        float s1 = 0.f, s2 = 0.f;
        #pragma unroll
        for (int k = lane; k < 256; k += 32) { s1 += ci[k]*wi[k]; s2 += sh[k]*wh[k]; }
        #pragma unroll
        for (int off=16; off; off>>=1) {
            s1 += __shfl_down_sync(0xFFFFFFFFu, s1, off);
            s2 += __shfl_down_sync(0xFFFFFFFFu, s2, off);
        }
        if (lane == 0) gsum[j] = s1 + nd*s2 + b_ih[j] + b_hh[j];
    }
    __syncthreads();

    {
        float gi = gsum[tid], gf = gsum[256+tid], gG = gsum[512+tid], go = gsum[768+tid];
        float c = nd * g_cc[b*256+tid];
        c = sigmoidf_(gf)*c + sigmoidf_(gi)*tanhf(gG);
        float h = sigmoidf_(go)*tanhf(c);
        g_cc[b*256+tid] = c;
        g_ch[b*256+tid] = h;
        g_outs[((size_t)t*16+b)*256 + tid] = h;
    }
}

// ------------------------------- heads -------------------------------------
__global__ void head_kernel(const float* __restrict__ pw, const float* __restrict__ pb,
                            const float* __restrict__ vw, const float* __restrict__ vb,
                            float* __restrict__ out)
{
    int row = blockIdx.x;
    int tid = threadIdx.x;
    __shared__ float lg[18];
    const float* h = g_outs + (size_t)row*256;
    if (tid < 18) {
        float s = pb[tid];
        for (int k=0;k<256;k++) s += h[k]*pw[k*18+tid];
        lg[tid] = s;
        out[row*18 + tid] = s;
    }
    if (tid == 19) {
        float s = vb[0];
        for (int k=0;k<256;k++) s += h[k]*vw[k];
        out[9216 + row] = s;
    }
    __syncthreads();
    if (tid == 0) {
        int am = 0; float bv = lg[0];
        for (int j=1;j<18;j++) if (lg[j] > bv) { bv = lg[j]; am = j; }
        out[9728 + row] = (float)am;
    }
}

__global__ void write_states(float* __restrict__ out) {
    int i = blockIdx.x*blockDim.x + threadIdx.x;
    if (i < 4096) { out[10240 + i] = g_ch[i]; out[14336 + i] = g_cc[i]; }
    if (i < 1105920) { out[18432 + i] = g_h[i]; out[1124352 + i] = g_c[i]; }
}

// ------------------------------- launch ------------------------------------
extern "C" void kernel_launch(void* const* d_in, const int* in_sizes, int n_in,
                              void* d_out, int out_size) {
    const float*         frame      = (const float*)d_in[0];
    const unsigned char* done       = (const unsigned char*)d_in[1];
    const int*           last_action= (const int*)d_in[2];
    const float*         reward     = (const float*)d_in[3];
    const float*         core_h     = (const float*)d_in[4];
    const float*         core_c     = (const float*)d_in[5];
    const float*         conv_h     = (const float*)d_in[6];
    const float*         conv_c     = (const float*)d_in[7];
    const float*         cnn_w1     = (const float*)d_in[8];
    const float*         cnn_b1     = (const float*)d_in[9];
    const float*         cnn_w2     = (const float*)d_in[10];
    const float*         cnn_b2     = (const float*)d_in[11];
    const float*         lstm_w     = (const float*)d_in[12];
    const float*         lstm_b     = (const float*)d_in[13];
    const float*         qw1        = (const float*)d_in[14];
    const float*         qb1        = (const float*)d_in[15];
    const float*         qw2        = (const float*)d_in[16];
    const float*         qb2        = (const float*)d_in[17];
    const float*         qw3        = (const float*)d_in[18];
    const float*         qb3        = (const float*)d_in[19];
    const float*         aw1        = (const float*)d_in[20];
    const float*         ab1        = (const float*)d_in[21];
    const float*         aw2        = (const float*)d_in[22];
    const float*         ab2        = (const float*)d_in[23];
    const float*         w_ih       = (const float*)d_in[24];
    const float*         w_hh       = (const float*)d_in[25];
    const float*         b_ih       = (const float*)d_in[26];
    const float*         b_hh       = (const float*)d_in[27];
    const float*         pw         = (const float*)d_in[28];
    const float*         pb         = (const float*)d_in[29];
    const float*         vw         = (const float*)d_in[30];
    const float*         vb         = (const float*)d_in[31];
    float* out = (float*)d_out;

    cudaFuncSetAttribute(gemm_mma<2>, cudaFuncAttributeMaxDynamicSharedMemorySize, SMEM_MMA);
    cudaFuncSetAttribute(gemm_mma<3>, cudaFuncAttributeMaxDynamicSharedMemorySize, SMEM_MMA);

    init_kernel<<<4320, 256>>>(core_h, core_c, conv_h, conv_c);
    split_w_kernel<<<3456, 256>>>(lstm_w);

    gemm_conv<0><<<dim3(16640,1), 256>>>(cnn_w1, cnn_b1, frame);
    gemm_conv<1><<<dim3(4320,1), 256>>>(cnn_w2, cnn_b2, frame);

    // Gx for ALL timesteps: N = 276480 -> 2160 n-tiles x 4 m-tiles
    gemm_mma<2><<<dim3(2160,4), 256, SMEM_MMA>>>(lstm_b, 0, done);

    for (int t = 0; t < NT; t++) {
        // gates + fused ConvLSTM pointwise update (double-buffered h)
        gemm_mma<3><<<dim3(68,4), 256, SMEM_MMA>>>(lstm_b, t, done);
        core_step<<<16, 256>>>(t, done, qw1,qb1,qw2,qb2,qw3,qb3,
                               aw1,ab1,aw2,ab2, w_ih,w_hh,b_ih,b_hh,
                               last_action, reward);
    }

    head_kernel<<<512, 32>>>(pw, pb, vw, vb, out);
    write_states<<<4320, 256>>>(out);
}

// round 12
// speedup vs baseline: 2.1551x; 1.0930x over previous
#include <cuda_runtime.h>
#include <cuda_bf16.h>
#include <math.h>
#include <cstdint>

// ---------------------------------------------------------------------------
// AttentionNet: conv1 -> conv2 -> ConvLSTM(T=32) -> attention core LSTM(T=32)
// 3x3-conv GEMMs on HMMA (bf16 hi/lo 3-split, fp32 acc). ConvLSTM pointwise
// update fused into the h-conv GEMM epilogue; g_hsplit double-buffered.
// R11: multi-stream overlap — core_step on its own stream (overlaps next
// step's h-conv GEMM); Gx GEMM chunked 4x and overlapped with the t-loop.
// ---------------------------------------------------------------------------

#define NT 32
#define HSZ (16u*128*540)

// ------------------------- static device scratch ---------------------------
__device__ float g_conv1[512u*32*2080];          // (512,32,52,40)
__device__ float g_Gx   [141557760u];            // (512,512,540) permuted-row Gx
__device__ float g_O    [512u*128*540];          // (T*B,128,540) RAW NCHW h outputs
__device__ float g_h    [16*128*540];            // conv h state (fp32, final only)
__device__ float g_c    [16*128*540];            // conv c state
__device__ float g_S    [540*64];                // spatial basis
__device__ float g_ch   [16*256];                // core h
__device__ float g_cc   [16*256];                // core c
__device__ float g_outs [32*16*256];             // core outputs per step

// bf16-split operands (rows PERMUTED: row' = my*128 + g*32 + c32)
__device__ __align__(16) __nv_bfloat16 g_Whi[512u*1728];
__device__ __align__(16) __nv_bfloat16 g_Wlo[512u*1728];
__device__ unsigned int g_xsplit[512u*64*540];   // packed hi | lo<<16
__device__ unsigned int g_hsplit[2u*HSZ];        // DOUBLE-BUFFERED packed h

__device__ __forceinline__ float sigmoidf_(float x) { return 1.f/(1.f+expf(-x)); }

__device__ __forceinline__ unsigned int pack_split(float f) {
    __nv_bfloat16 h = __float2bfloat16(f);
    float hf = __bfloat162float(h);
    __nv_bfloat16 l = __float2bfloat16(f - hf);
    unsigned short hu = *reinterpret_cast<unsigned short*>(&h);
    unsigned short lu = *reinterpret_cast<unsigned short*>(&l);
    return (unsigned int)hu | ((unsigned int)lu << 16);
}

// ----------------------------- mma helpers ---------------------------------
__device__ __forceinline__ uint32_t smem_u32(const void* p) {
    uint32_t a;
    asm("{ .reg .u64 t; cvta.to.shared.u64 t, %1; cvt.u32.u64 %0, t; }" : "=r"(a) : "l"(p));
    return a;
}
__device__ __forceinline__ void ldsm_x4(uint32_t* r, uint32_t addr) {
    asm volatile("ldmatrix.sync.aligned.m8n8.x4.shared.b16 {%0,%1,%2,%3}, [%4];"
        : "=r"(r[0]), "=r"(r[1]), "=r"(r[2]), "=r"(r[3]) : "r"(addr));
}
__device__ __forceinline__ void ldsm_x2(uint32_t* r, uint32_t addr) {
    asm volatile("ldmatrix.sync.aligned.m8n8.x2.shared.b16 {%0,%1}, [%2];"
        : "=r"(r[0]), "=r"(r[1]) : "r"(addr));
}
__device__ __forceinline__ void mma16816(float* d, const uint32_t* a, const uint32_t* b) {
    asm volatile(
        "mma.sync.aligned.m16n8k16.row.col.f32.bf16.bf16.f32 "
        "{%0,%1,%2,%3}, {%4,%5,%6,%7}, {%8,%9}, {%0,%1,%2,%3};"
        : "+f"(d[0]), "+f"(d[1]), "+f"(d[2]), "+f"(d[3])
        : "r"(a[0]), "r"(a[1]), "r"(a[2]), "r"(a[3]), "r"(b[0]), "r"(b[1]));
}

// ------------------------------ init -------------------------------------
__global__ void init_kernel(const float* __restrict__ core_h, const float* __restrict__ core_c,
                            const float* __restrict__ conv_h, const float* __restrict__ conv_c) {
    int i = blockIdx.x*blockDim.x + threadIdx.x;
    if (i < 540*64) {
        int p = i >> 6, k = i & 63;
        int y = p/20, x = p - y*20;
        int u = k >> 3, v = k & 7;
        double PI = 3.14159265358979323846;
        g_S[i] = (float)(cos((double)(y+1)*(u+1)*PI/27.0) * cos((double)(x+1)*(v+1)*PI/20.0));
    }
    if (i < 16*256) { g_ch[i] = core_h[i]; g_cc[i] = core_c[i]; }
    if (i < 16*128*540) {
        g_c[i] = conv_c[i];
        g_hsplit[i] = pack_split(conv_h[i]);      // buffer 0
    }
}

// Weight split with GATE-INTERLEAVED row permutation:
// orig row m = g*128 + rr -> perm row = (rr>>5)*128 + g*32 + (rr&31)
__global__ void split_w_kernel(const float* __restrict__ w) {
    int i = blockIdx.x*blockDim.x + threadIdx.x;
    if (i >= 512*1728) return;
    int row = i / 1728, k = i - row*1728;
    int g = row >> 7, rr = row & 127;
    int rp = (rr >> 5)*128 + g*32 + (rr & 31);
    float f = w[i];
    __nv_bfloat16 h = __float2bfloat16(f);
    __nv_bfloat16 l = __float2bfloat16(f - __bfloat162float(h));
    g_Whi[(size_t)rp*1728 + k] = h;
    g_Wlo[(size_t)rp*1728 + k] = l;
}

// -------------------- small-conv implicit-GEMM (SIMT) ----------------------
template<int MODE> struct GP;
template<> struct GP<0>{ static constexpr int M=32,  K=192, IH=210,IW=160,OH=52,OW=40,KH=8,KW=8,SH=4,SW=4,PH=1,PW=2,WS=192; };
template<> struct GP<1>{ static constexpr int M=64,  K=512, IH=52, IW=40, OH=27,OW=20,KH=4,KW=4,SH=2,SW=2,PH=2,PW=1,WS=512; };

template<int MODE>
__global__ void __launch_bounds__(256)
gemm_conv(const float* __restrict__ W, const float* __restrict__ bias,
          const float* __restrict__ frame)
{
    using G = GP<MODE>;
    constexpr int PPI = G::OH * G::OW;
    __shared__ float As[16][64];
    __shared__ float Bs[16][64];

    int tid = threadIdx.x;
    int n0 = blockIdx.x * 64;
    int m0 = blockIdx.y * 64;
    int tx = tid & 15, ty = tid >> 4;

    float acc[4][4];
    #pragma unroll
    for (int i=0;i<4;i++)
        #pragma unroll
        for (int j=0;j<4;j++) acc[i][j] = 0.f;

    int a_m = m0 + (tid >> 2);
    int a_k = (tid & 3) * 4;

    int b_n = n0 + (tid & 63);
    int img = b_n / PPI;
    int pos = b_n - img * PPI;
    int oy  = pos / G::OW;
    int ox  = pos - oy * G::OW;
    int iy0 = oy * G::SH - G::PH;
    int ix0 = ox * G::SW - G::PW;

    const float* bbase;
    if constexpr (MODE==0) bbase = frame   + (size_t)img * (3*210*160);
    else                   bbase = g_conv1 + (size_t)img * (32*52*40);

    for (int k0 = 0; k0 < G::K; k0 += 16) {
        float4 av4;
        if (G::M % 64 == 0 || a_m < G::M)
            av4 = *reinterpret_cast<const float4*>(W + (size_t)a_m * G::WS + k0 + a_k);
        else
            av4 = make_float4(0.f,0.f,0.f,0.f);
        As[a_k+0][tid>>2] = av4.x;
        As[a_k+1][tid>>2] = av4.y;
        As[a_k+2][tid>>2] = av4.z;
        As[a_k+3][tid>>2] = av4.w;

        #pragma unroll
        for (int j=0;j<4;j++) {
            int kk = (tid>>6) + j*4;
            int k  = k0 + kk;
            int c  = k / (G::KH*G::KW);
            int rs = k - c*(G::KH*G::KW);
            int r  = rs / G::KW;
            int s  = rs - r*G::KW;
            int iy = iy0 + r, ix = ix0 + s;
            float v = 0.f;
            if (iy >= 0 && iy < G::IH && ix >= 0 && ix < G::IW)
                v = bbase[((size_t)c*G::IH + iy)*G::IW + ix];
            Bs[kk][tid & 63] = v;
        }
        __syncthreads();

        #pragma unroll
        for (int kk=0;kk<16;kk++) {
            float4 a4 = *reinterpret_cast<const float4*>(&As[kk][ty*4]);
            float4 b4 = *reinterpret_cast<const float4*>(&Bs[kk][tx*4]);
            float a[4] = {a4.x,a4.y,a4.z,a4.w};
            float b[4] = {b4.x,b4.y,b4.z,b4.w};
            #pragma unroll
            for (int i=0;i<4;i++)
                #pragma unroll
                for (int j=0;j<4;j++) acc[i][j] += a[i]*b[j];
        }
        __syncthreads();
    }

    #pragma unroll
    for (int i=0;i<4;i++) {
        int m = m0 + ty*4 + i;
        if (G::M % 64 != 0 && m >= G::M) continue;
        #pragma unroll
        for (int j=0;j<4;j++) {
            int n  = n0 + tx*4 + j;
            int im = n / PPI;
            int pp = n - im*PPI;
            float v = acc[i][j] + bias[m];
            if constexpr (MODE==0) g_conv1[(size_t)(im*32+m)*2080 + pp] = v;
            else                   g_xsplit[(size_t)(im*64+m)*540 + pp] = pack_split(v);
        }
    }
}

// ---------------- HMMA GEMM for the 3x3 convs (bf16 hi/lo split) -----------
static constexpr int OFF_AHI = 0;
static constexpr int OFF_ALO = 10240;
static constexpr int OFF_BHI = 20480;
static constexpr int OFF_BLO = 30720;
static constexpr int OFF_KTAB = 40960;            // 1152 x u32 (mainloop only)
static constexpr int SMEM_MMA = 128*132*4;        // 67584 (stage reuses tiles)

template<int MODE>
__global__ void __launch_bounds__(256, 1)
gemm_mma(const float* __restrict__ bias, int t, const unsigned char* __restrict__ done,
         int nbase)
{
    constexpr int KTOT  = (MODE==2) ? 576 : 1152;
    constexpr int WO    = (MODE==2) ? 0   : 576;
    constexpr int NTOT  = (MODE==2) ? 512*540 : 16*540;
    constexpr int NCH   = (MODE==2) ? 64  : 128;
    constexpr int NCHUNK= KTOT/32;

    extern __shared__ char smem[];
    uint32_t sb = smem_u32(smem);
    uint32_t* ktab = reinterpret_cast<uint32_t*>(smem + OFF_KTAB);
    int tid  = threadIdx.x;
    int wid  = tid >> 5;
    int lane = tid & 31;

    int n0 = (nbase + blockIdx.x) * 128;
    int m0 = blockIdx.y * 128;

    // double-buffer pointers (read old h, write new h elsewhere)
    const unsigned int* hread  = g_hsplit + (size_t)(t & 1) * HSZ;
    unsigned int*       hwrite = g_hsplit + (size_t)((t + 1) & 1) * HSZ;

    // ---- build k -> (delta, r, s) table ----
    for (int k = tid; k < KTOT; k += 256) {
        int c = k/9, rs = k - c*9, r = rs/3, s = rs - r*3;
        ktab[k] = (uint32_t)(c*540 + r*20 + s) | ((uint32_t)r << 20) | ((uint32_t)s << 24);
    }

    // ---- per-thread B-gather coords ----
    int nn    = tid & 127;
    int khalf = tid >> 7;
    int bn    = n0 + nn;
    bool nvalid = (bn < NTOT);
    int bnc = nvalid ? bn : 0;
    int img = bnc / 540;
    int pos = bnc - img * 540;
    int oy = pos / 20, ox = pos - oy * 20;
    int iy0 = oy - 1, ix0 = ox - 1;
    const unsigned int* bptr =
        (MODE==2 ? (const unsigned int*)g_xsplit : hread) + (size_t)img * NCH * 540 + (iy0*20 + ix0);
    if (MODE == 3 && nvalid && done[t*16 + img]) nvalid = false;

    // ---- per-thread A-load coords ----
    int a_r0 = (tid*2)   >> 2;  int a_k0 = ((tid*2)   & 3) * 8;
    int a_r1 = (tid*2+1) >> 2;  int a_k1 = ((tid*2+1) & 3) * 8;

    int wm = (wid >> 2) * 64;
    int wn = (wid & 3) * 32;

    float cfr[4][4][4];
    #pragma unroll
    for (int mi=0;mi<4;mi++)
        #pragma unroll
        for (int ni=0;ni<4;ni++)
            #pragma unroll
            for (int e=0;e<4;e++) cfr[mi][ni][e] = 0.f;

    uint4    pa[4];
    uint32_t pb[16];

    __syncthreads();   // ktab ready

    // prefetch chunk 0
    {
        pa[0] = *reinterpret_cast<const uint4*>(g_Whi + (size_t)(m0+a_r0)*1728 + WO + a_k0);
        pa[1] = *reinterpret_cast<const uint4*>(g_Whi + (size_t)(m0+a_r1)*1728 + WO + a_k1);
        pa[2] = *reinterpret_cast<const uint4*>(g_Wlo + (size_t)(m0+a_r0)*1728 + WO + a_k0);
        pa[3] = *reinterpret_cast<const uint4*>(g_Wlo + (size_t)(m0+a_r1)*1728 + WO + a_k1);
        #pragma unroll
        for (int i=0;i<16;i++) {
            uint32_t tv = ktab[khalf*16 + i];
            int r = (tv>>20)&15, s2 = (tv>>24)&15;
            unsigned int v = 0;
            if (nvalid && (unsigned)(iy0+r)<27u && (unsigned)(ix0+s2)<20u)
                v = bptr[tv & 0xFFFFF];
            pb[i] = v;
        }
    }

    for (int ch = 0; ch < NCHUNK; ch++) {
        *reinterpret_cast<uint4*>(smem + OFF_AHI + (a_r0*40 + a_k0)*2) = pa[0];
        *reinterpret_cast<uint4*>(smem + OFF_AHI + (a_r1*40 + a_k1)*2) = pa[1];
        *reinterpret_cast<uint4*>(smem + OFF_ALO + (a_r0*40 + a_k0)*2) = pa[2];
        *reinterpret_cast<uint4*>(smem + OFF_ALO + (a_r1*40 + a_k1)*2) = pa[3];
        {
            int kb = khalf*16;
            #pragma unroll
            for (int i=0;i<16;i+=2) {
                uint32_t v0 = pb[i], v1 = pb[i+1];
                uint32_t hi = (v0 & 0xFFFFu) | (v1 << 16);
                uint32_t lo = (v0 >> 16) | (v1 & 0xFFFF0000u);
                *reinterpret_cast<uint32_t*>(smem + OFF_BHI + (nn*40 + kb + i)*2) = hi;
                *reinterpret_cast<uint32_t*>(smem + OFF_BLO + (nn*40 + kb + i)*2) = lo;
            }
        }
        __syncthreads();

        if (ch + 1 < NCHUNK) {
            int k0 = (ch+1)*32;
            pa[0] = *reinterpret_cast<const uint4*>(g_Whi + (size_t)(m0+a_r0)*1728 + WO + k0 + a_k0);
            pa[1] = *reinterpret_cast<const uint4*>(g_Whi + (size_t)(m0+a_r1)*1728 + WO + k0 + a_k1);
            pa[2] = *reinterpret_cast<const uint4*>(g_Wlo + (size_t)(m0+a_r0)*1728 + WO + k0 + a_k0);
            pa[3] = *reinterpret_cast<const uint4*>(g_Wlo + (size_t)(m0+a_r1)*1728 + WO + k0 + a_k1);
            #pragma unroll
            for (int i=0;i<16;i++) {
                uint32_t tv = ktab[k0 + khalf*16 + i];
                int r = (tv>>20)&15, s2 = (tv>>24)&15;
                unsigned int v = 0;
                if (nvalid && (unsigned)(iy0+r)<27u && (unsigned)(ix0+s2)<20u)
                    v = bptr[tv & 0xFFFFF];
                pb[i] = v;
            }
        }

        #pragma unroll
        for (int kk = 0; kk < 32; kk += 16) {
            uint32_t af[4][4], bfh[4][2], bfl[4][2];
            {
                uint32_t row = wm + (lane & 15);
                uint32_t col = kk + (lane >> 4) * 8;
                #pragma unroll
                for (int mi=0;mi<4;mi++)
                    ldsm_x4(af[mi], sb + OFF_AHI + ((row + mi*16)*40 + col)*2);
            }
            {
                int l2 = lane & 15;
                uint32_t row = wn + (l2 & 7);
                uint32_t col = kk + (l2 >> 3) * 8;
                #pragma unroll
                for (int ni=0;ni<4;ni++) {
                    ldsm_x2(bfh[ni], sb + OFF_BHI + ((row + ni*8)*40 + col)*2);
                    ldsm_x2(bfl[ni], sb + OFF_BLO + ((row + ni*8)*40 + col)*2);
                }
            }
            #pragma unroll
            for (int mi=0;mi<4;mi++)
                #pragma unroll
                for (int ni=0;ni<4;ni++) {
                    mma16816(cfr[mi][ni], af[mi], bfh[ni]);
                    mma16816(cfr[mi][ni], af[mi], bfl[ni]);
                }
            {
                uint32_t row = wm + (lane & 15);
                uint32_t col = kk + (lane >> 4) * 8;
                #pragma unroll
                for (int mi=0;mi<4;mi++)
                    ldsm_x4(af[mi], sb + OFF_ALO + ((row + mi*16)*40 + col)*2);
            }
            #pragma unroll
            for (int mi=0;mi<4;mi++)
                #pragma unroll
                for (int ni=0;ni<4;ni++)
                    mma16816(cfr[mi][ni], af[mi], bfh[ni]);
        }
        __syncthreads();
    }

    // ---- frags -> smem stage ----
    float* stage = reinterpret_cast<float*>(smem);
    int gid = lane >> 2, tig = lane & 3;
    #pragma unroll
    for (int mi=0;mi<4;mi++)
        #pragma unroll
        for (int ni=0;ni<4;ni++) {
            int r0 = wm + mi*16 + gid;
            int c0 = wn + ni*8 + tig*2;
            stage[r0*132 + c0]       = cfr[mi][ni][0];
            stage[r0*132 + c0 + 1]   = cfr[mi][ni][1];
            stage[(r0+8)*132 + c0]   = cfr[mi][ni][2];
            stage[(r0+8)*132 + c0+1] = cfr[mi][ni][3];
        }
    __syncthreads();

    if constexpr (MODE == 2) {
        int my = blockIdx.y;
        for (int idx = tid; idx < 128*128; idx += 256) {
            int r = idx >> 7, c2 = idx & 127;
            int n = n0 + c2;
            int m  = m0 + r;
            int gg = r >> 5, c32 = r & 31;
            int morig = gg*128 + my*32 + c32;
            int im = n / 540;
            int pp = n - im*540;
            g_Gx[((size_t)im*512 + m)*540 + pp] = stage[r*132 + c2] + bias[morig];
        }
    } else {
        // fused ConvLSTM update: stage rows {c32, 32+c32, 64+c32, 96+c32} are
        // (ai, af, ao, ag) for channel my*32+c32.
        int my = blockIdx.y;
        int tb = t*16;
        for (int idx = tid; idx < 32*128; idx += 256) {
            int c32 = idx >> 7, col = idx & 127;
            int n = n0 + col;
            if (n >= 8640) continue;
            int im = n / 540, pp = n - im*540;
            int ch = my*32 + c32;
            size_t gxb = ((size_t)(tb + im)*512 + my*128 + c32)*540 + pp;
            float ai = stage[(     c32)*132 + col] + g_Gx[gxb];
            float af = stage[(32 + c32)*132 + col] + g_Gx[gxb + (size_t)32*540];
            float ao = stage[(64 + c32)*132 + col] + g_Gx[gxb + (size_t)64*540];
            float ag = stage[(96 + c32)*132 + col] + g_Gx[gxb + (size_t)96*540];
            float nd = (done[tb+im]==0) ? 1.f : 0.f;
            int hidx = (im*128 + ch)*540 + pp;
            float c = g_c[hidx] * nd;
            c = sigmoidf_(af)*c + sigmoidf_(ai)*tanhf(ag);
            float h = sigmoidf_(ao)*tanhf(c);
            g_c[hidx] = c;
            g_h[hidx] = h;
            hwrite[hidx] = pack_split(h);
            g_O[(size_t)(tb+im)*69120 + (size_t)ch*540 + pp] = h;
        }
    }
}

// --------------------------- fused core step -------------------------------
__global__ void __launch_bounds__(256)
core_step(int t, const unsigned char* __restrict__ done,
          const float* __restrict__ qw1, const float* __restrict__ qb1,
          const float* __restrict__ qw2, const float* __restrict__ qb2,
          const float* __restrict__ qw3, const float* __restrict__ qb3,
          const float* __restrict__ aw1, const float* __restrict__ ab1,
          const float* __restrict__ aw2, const float* __restrict__ ab2,
          const float* __restrict__ w_ih, const float* __restrict__ w_hh,
          const float* __restrict__ b_ih, const float* __restrict__ b_hh,
          const int* __restrict__ last_action, const float* __restrict__ reward)
{
    int b = blockIdx.x;
    int tid = threadIdx.x;
    int wid = tid >> 5, lane = tid & 31;

    __shared__ float sh[256];
    __shared__ float q1[128];
    __shared__ float q2[288];
    __shared__ float q3[288];
    __shared__ float sA[540*4];
    __shared__ float red[256];
    __shared__ float mx[4], sm[4];
    __shared__ float ans[736];
    __shared__ float a1[512];
    __shared__ float ci[256];
    __shared__ float gsum[1024];

    sh[tid] = g_ch[b*256 + tid];
    __syncthreads();

    if (tid < 128) {
        float s = qb1[tid];
        for (int k=0;k<256;k++) s += sh[k]*qw1[k*128+tid];
        q1[tid] = fmaxf(s, 0.f);
    }
    __syncthreads();
    for (int j=tid;j<288;j+=256) {
        float s = qb2[j];
        for (int k=0;k<128;k++) s += q1[k]*qw2[k*288+j];
        q2[j] = fmaxf(s, 0.f);
    }
    __syncthreads();
    for (int j=tid;j<288;j+=256) {
        float s = qb3[j];
        for (int k=0;k<288;k++) s += q2[k]*qw3[k*288+j];
        q3[j] = s;
    }
    __syncthreads();

    const float* Ob = g_O + ((size_t)(t*16+b))*69120;
    for (int idx=tid; idx<2160; idx+=256) {
        int p = idx >> 2, qi = idx & 3;
        const float* qv = q3 + qi*72;
        const float* op = Ob + (size_t)p*128;
        const float* sp = g_S + p*64;
        float s = 0.f;
        #pragma unroll
        for (int k=0;k<8;k++)  s += op[k]*qv[k];
        #pragma unroll 8
        for (int k=0;k<64;k++) s += sp[k]*qv[8+k];
        sA[idx] = s;
    }
    __syncthreads();

    {
        int qi = tid >> 6, lane6 = tid & 63;
        float m = -1e30f;
        for (int p=lane6;p<540;p+=64) m = fmaxf(m, sA[p*4+qi]);
        red[tid] = m;
        __syncthreads();
        if (tid < 4) { float mm=-1e30f; for (int i=0;i<64;i++) mm = fmaxf(mm, red[tid*64+i]); mx[tid]=mm; }
        __syncthreads();
        for (int idx=tid; idx<2160; idx+=256) sA[idx] = expf(sA[idx]-mx[idx&3]);
        __syncthreads();
        float s = 0.f;
        for (int p=lane6;p<540;p+=64) s += sA[p*4+qi];
        red[tid] = s;
        __syncthreads();
        if (tid < 4) { float ss=0.f; for (int i=0;i<64;i++) ss += red[tid*64+i]; sm[tid]=ss; }
        __syncthreads();
    }

    // ans with 3 parallel accumulators (one p-loop)
    {
        int o0 = tid, o1 = tid+256, o2 = tid+512;
        bool has2 = (o2 < 736);
        int q0 = o0/184, v0 = o0-q0*184;
        int q1i = o1/184, v1 = o1-q1i*184;
        int q2i = has2 ? o2/184 : 0, v2 = has2 ? o2-q2i*184 : 0;
        const float* b0 = (v0<120) ? Ob+8+v0 : g_S+(v0-120);
        const float* b1 = (v1<120) ? Ob+8+v1 : g_S+(v1-120);
        const float* b2 = (v2<120) ? Ob+8+v2 : g_S+(v2-120);
        int s0 = (v0<120)?128:64, s1 = (v1<120)?128:64, s2 = (v2<120)?128:64;
        float a0=0.f, a1v=0.f, a2=0.f;
        #pragma unroll 4
        for (int p=0;p<540;p++) {
            a0  += sA[p*4+q0]  * b0[(size_t)p*s0];
            a1v += sA[p*4+q1i] * b1[(size_t)p*s1];
            if (has2) a2 += sA[p*4+q2i] * b2[(size_t)p*s2];
        }
        ans[o0] = a0 / sm[q0];
        ans[o1] = a1v / sm[q1i];
        if (has2) ans[o2] = a2 / sm[q2i];
    }
    __syncthreads();

    float rclip = fminf(fmaxf(reward[t*16+b], -1.f), 1.f);
    int act = last_action[t*16+b];
    float nd = (done[t*16+b]==0) ? 1.f : 0.f;

    // a1 = relu(answer @ aw1 + ab1): 2 outputs per thread
    {
        int j0 = tid, j1 = tid + 256;
        float s0 = ab1[j0], s1 = ab1[j1];
        for (int k=0;k<736;k++) {
            float f = ans[k];
            s0 += f*aw1[(size_t)k*512+j0];
            s1 += f*aw1[(size_t)k*512+j1];
        }
        for (int k=0;k<288;k++) {
            float f = q3[k];
            s0 += f*aw1[(size_t)(736+k)*512+j0];
            s1 += f*aw1[(size_t)(736+k)*512+j1];
        }
        s0 += rclip*aw1[(size_t)1024*512+j0] + aw1[(size_t)(1025+act)*512+j0];
        s1 += rclip*aw1[(size_t)1024*512+j1] + aw1[(size_t)(1025+act)*512+j1];
        a1[j0] = fmaxf(s0, 0.f);
        a1[j1] = fmaxf(s1, 0.f);
    }
    __syncthreads();
    {
        float s = ab2[tid];
        for (int k=0;k<512;k++) s += a1[k]*aw2[(size_t)k*256+tid];
        ci[tid] = s;
    }
    __syncthreads();

    // LSTM gates: warp-per-output, float4 weight reads + shuffle reduce
    for (int j = wid; j < 1024; j += 8) {
        const float4* wi4 = reinterpret_cast<const float4*>(w_ih + (size_t)j*256);
        const float4* wh4 = reinterpret_cast<const float4*>(w_hh + (size_t)j*256);
        float s1 = 0.f, s2 = 0.f;
        #pragma unroll
        for (int it = 0; it < 2; it++) {
            int k4 = lane + it*32;          // float4 index (0..63)
            float4 a = wi4[k4];
            float4 bq = wh4[k4];
            int kb = k4*4;
            s1 += ci[kb]*a.x + ci[kb+1]*a.y + ci[kb+2]*a.z + ci[kb+3]*a.w;
            s2 += sh[kb]*bq.x + sh[kb+1]*bq.y + sh[kb+2]*bq.z + sh[kb+3]*bq.w;
        }
        #pragma unroll
        for (int off=16; off; off>>=1) {
            s1 += __shfl_down_sync(0xFFFFFFFFu, s1, off);
            s2 += __shfl_down_sync(0xFFFFFFFFu, s2, off);
        }
        if (lane == 0) gsum[j] = s1 + nd*s2 + b_ih[j] + b_hh[j];
    }
    __syncthreads();

    {
        float gi = gsum[tid], gf = gsum[256+tid], gG = gsum[512+tid], go = gsum[768+tid];
        float c = nd * g_cc[b*256+tid];
        c = sigmoidf_(gf)*c + sigmoidf_(gi)*tanhf(gG);
        float h = sigmoidf_(go)*tanhf(c);
        g_cc[b*256+tid] = c;
        g_ch[b*256+tid] = h;
        g_outs[((size_t)t*16+b)*256 + tid] = h;
    }
}

// ------------------------------- heads -------------------------------------
__global__ void head_kernel(const float* __restrict__ pw, const float* __restrict__ pb,
                            const float* __restrict__ vw, const float* __restrict__ vb,
                            float* __restrict__ out)
{
    int row = blockIdx.x;
    int tid = threadIdx.x;
    __shared__ float lg[18];
    const float* h = g_outs + (size_t)row*256;
    if (tid < 18) {
        float s = pb[tid];
        for (int k=0;k<256;k++) s += h[k]*pw[k*18+tid];
        lg[tid] = s;
        out[row*18 + tid] = s;
    }
    if (tid == 19) {
        float s = vb[0];
        for (int k=0;k<256;k++) s += h[k]*vw[k];
        out[9216 + row] = s;
    }
    __syncthreads();
    if (tid == 0) {
        int am = 0; float bv = lg[0];
        for (int j=1;j<18;j++) if (lg[j] > bv) { bv = lg[j]; am = j; }
        out[9728 + row] = (float)am;
    }
}

__global__ void write_states(float* __restrict__ out) {
    int i = blockIdx.x*blockDim.x + threadIdx.x;
    if (i < 4096) { out[10240 + i] = g_ch[i]; out[14336 + i] = g_cc[i]; }
    if (i < 1105920) { out[18432 + i] = g_h[i]; out[1124352 + i] = g_c[i]; }
}

// ------------------------------- launch ------------------------------------
extern "C" void kernel_launch(void* const* d_in, const int* in_sizes, int n_in,
                              void* d_out, int out_size) {
    const float*         frame      = (const float*)d_in[0];
    const unsigned char* done       = (const unsigned char*)d_in[1];
    const int*           last_action= (const int*)d_in[2];
    const float*         reward     = (const float*)d_in[3];
    const float*         core_h     = (const float*)d_in[4];
    const float*         core_c     = (const float*)d_in[5];
    const float*         conv_h     = (const float*)d_in[6];
    const float*         conv_c     = (const float*)d_in[7];
    const float*         cnn_w1     = (const float*)d_in[8];
    const float*         cnn_b1     = (const float*)d_in[9];
    const float*         cnn_w2     = (const float*)d_in[10];
    const float*         cnn_b2     = (const float*)d_in[11];
    const float*         lstm_w     = (const float*)d_in[12];
    const float*         lstm_b     = (const float*)d_in[13];
    const float*         qw1        = (const float*)d_in[14];
    const float*         qb1        = (const float*)d_in[15];
    const float*         qw2        = (const float*)d_in[16];
    const float*         qb2        = (const float*)d_in[17];
    const float*         qw3        = (const float*)d_in[18];
    const float*         qb3        = (const float*)d_in[19];
    const float*         aw1        = (const float*)d_in[20];
    const float*         ab1        = (const float*)d_in[21];
    const float*         aw2        = (const float*)d_in[22];
    const float*         ab2        = (const float*)d_in[23];
    const float*         w_ih       = (const float*)d_in[24];
    const float*         w_hh       = (const float*)d_in[25];
    const float*         b_ih       = (const float*)d_in[26];
    const float*         b_hh       = (const float*)d_in[27];
    const float*         pw         = (const float*)d_in[28];
    const float*         pb         = (const float*)d_in[29];
    const float*         vw         = (const float*)d_in[30];
    const float*         vb         = (const float*)d_in[31];
    float* out = (float*)d_out;

    // lazily-created streams/events (host-side objects only; created on the
    // first (correctness) call, reused during graph capture)
    static cudaStream_t sGx = nullptr, sCore = nullptr;
    static cudaEvent_t evFront, evGx[4], evM[NT], evCoreDone;
    if (!sGx) {
        cudaStreamCreateWithFlags(&sGx,   cudaStreamNonBlocking);
        cudaStreamCreateWithFlags(&sCore, cudaStreamNonBlocking);
        cudaEventCreateWithFlags(&evFront, cudaEventDisableTiming);
        for (int c = 0; c < 4; c++) cudaEventCreateWithFlags(&evGx[c], cudaEventDisableTiming);
        for (int t = 0; t < NT; t++) cudaEventCreateWithFlags(&evM[t], cudaEventDisableTiming);
        cudaEventCreateWithFlags(&evCoreDone, cudaEventDisableTiming);
        cudaFuncSetAttribute(gemm_mma<2>, cudaFuncAttributeMaxDynamicSharedMemorySize, SMEM_MMA);
        cudaFuncSetAttribute(gemm_mma<3>, cudaFuncAttributeMaxDynamicSharedMemorySize, SMEM_MMA);
    }

    init_kernel<<<4320, 256>>>(core_h, core_c, conv_h, conv_c);
    split_w_kernel<<<3456, 256>>>(lstm_w);

    gemm_conv<0><<<dim3(16640,1), 256>>>(cnn_w1, cnn_b1, frame);
    gemm_conv<1><<<dim3(4320,1), 256>>>(cnn_w2, cnn_b2, frame);
    cudaEventRecord(evFront, 0);

    // Gx in 4 chunks of 8 timesteps each (540 n-tiles = exactly 128 images),
    // on its own stream so chunks 1-3 overlap the t-loop below.
    cudaStreamWaitEvent(sGx, evFront, 0);
    for (int c = 0; c < 4; c++) {
        gemm_mma<2><<<dim3(540,4), 256, SMEM_MMA, sGx>>>(lstm_b, 0, done, c*540);
        cudaEventRecord(evGx[c], sGx);
    }

    for (int t = 0; t < NT; t++) {
        if ((t & 7) == 0) cudaStreamWaitEvent(0, evGx[t >> 3], 0);
        // gates + fused ConvLSTM pointwise update (double-buffered h)
        gemm_mma<3><<<dim3(68,4), 256, SMEM_MMA>>>(lstm_b, t, done, 0);
        cudaEventRecord(evM[t], 0);
        // core_step(t) on its own stream: overlaps gemm_mma<3>(t+1)
        cudaStreamWaitEvent(sCore, evM[t], 0);
        core_step<<<16, 256, 0, sCore>>>(t, done, qw1,qb1,qw2,qb2,qw3,qb3,
                                         aw1,ab1,aw2,ab2, w_ih,w_hh,b_ih,b_hh,
                                         last_action, reward);
    }
    cudaEventRecord(evCoreDone, sCore);
    cudaStreamWaitEvent(0, evCoreDone, 0);

    head_kernel<<<512, 32>>>(pw, pb, vw, vb, out);
    write_states<<<4320, 256>>>(out);
}

// round 13
// speedup vs baseline: 3.1436x; 1.4587x over previous
#include <cuda_runtime.h>
#include <cuda_bf16.h>
#include <math.h>
#include <cstdint>

// ---------------------------------------------------------------------------
// AttentionNet: conv1 -> conv2 -> ConvLSTM(T=32) -> attention core LSTM(T=32)
// 3x3-conv GEMMs on HMMA (bf16 hi/lo 3-split, fp32 acc), 2 CTAs/SM.
// ConvLSTM pointwise update fused into h-conv epilogue; g_hsplit double-buffered.
// R13: no reg-prefetch (launch_bounds(256,2) => 1 dual-CTA wave), core_step
// widened to 512 threads, Gx in 8 overlap chunks.
// ---------------------------------------------------------------------------

#define NT 32
#define HSZ (16u*128*540)

// ------------------------- static device scratch ---------------------------
__device__ float g_conv1[512u*32*2080];          // (512,32,52,40)
__device__ float g_Gx   [141557760u];            // (512,512,540) permuted-row Gx
__device__ float g_O    [512u*128*540];          // (T*B,128,540) RAW NCHW h outputs
__device__ float g_h    [16*128*540];            // conv h state (fp32, final only)
__device__ float g_c    [16*128*540];            // conv c state
__device__ float g_S    [540*64];                // spatial basis
__device__ float g_ch   [16*256];                // core h
__device__ float g_cc   [16*256];                // core c
__device__ float g_outs [32*16*256];             // core outputs per step

// bf16-split operands (rows PERMUTED: row' = my*128 + g*32 + c32)
__device__ __align__(16) __nv_bfloat16 g_Whi[512u*1728];
__device__ __align__(16) __nv_bfloat16 g_Wlo[512u*1728];
__device__ unsigned int g_xsplit[512u*64*540];   // packed hi | lo<<16
__device__ unsigned int g_hsplit[2u*HSZ];        // DOUBLE-BUFFERED packed h

__device__ __forceinline__ float sigmoidf_(float x) { return 1.f/(1.f+expf(-x)); }

__device__ __forceinline__ unsigned int pack_split(float f) {
    __nv_bfloat16 h = __float2bfloat16(f);
    float hf = __bfloat162float(h);
    __nv_bfloat16 l = __float2bfloat16(f - hf);
    unsigned short hu = *reinterpret_cast<unsigned short*>(&h);
    unsigned short lu = *reinterpret_cast<unsigned short*>(&l);
    return (unsigned int)hu | ((unsigned int)lu << 16);
}

// ----------------------------- mma helpers ---------------------------------
__device__ __forceinline__ uint32_t smem_u32(const void* p) {
    uint32_t a;
    asm("{ .reg .u64 t; cvta.to.shared.u64 t, %1; cvt.u32.u64 %0, t; }" : "=r"(a) : "l"(p));
    return a;
}
__device__ __forceinline__ void ldsm_x4(uint32_t* r, uint32_t addr) {
    asm volatile("ldmatrix.sync.aligned.m8n8.x4.shared.b16 {%0,%1,%2,%3}, [%4];"
        : "=r"(r[0]), "=r"(r[1]), "=r"(r[2]), "=r"(r[3]) : "r"(addr));
}
__device__ __forceinline__ void ldsm_x2(uint32_t* r, uint32_t addr) {
    asm volatile("ldmatrix.sync.aligned.m8n8.x2.shared.b16 {%0,%1}, [%2];"
        : "=r"(r[0]), "=r"(r[1]) : "r"(addr));
}
__device__ __forceinline__ void mma16816(float* d, const uint32_t* a, const uint32_t* b) {
    asm volatile(
        "mma.sync.aligned.m16n8k16.row.col.f32.bf16.bf16.f32 "
        "{%0,%1,%2,%3}, {%4,%5,%6,%7}, {%8,%9}, {%0,%1,%2,%3};"
        : "+f"(d[0]), "+f"(d[1]), "+f"(d[2]), "+f"(d[3])
        : "r"(a[0]), "r"(a[1]), "r"(a[2]), "r"(a[3]), "r"(b[0]), "r"(b[1]));
}

// ------------------------------ init -------------------------------------
__global__ void init_kernel(const float* __restrict__ core_h, const float* __restrict__ core_c,
                            const float* __restrict__ conv_h, const float* __restrict__ conv_c) {
    int i = blockIdx.x*blockDim.x + threadIdx.x;
    if (i < 540*64) {
        int p = i >> 6, k = i & 63;
        int y = p/20, x = p - y*20;
        int u = k >> 3, v = k & 7;
        double PI = 3.14159265358979323846;
        g_S[i] = (float)(cos((double)(y+1)*(u+1)*PI/27.0) * cos((double)(x+1)*(v+1)*PI/20.0));
    }
    if (i < 16*256) { g_ch[i] = core_h[i]; g_cc[i] = core_c[i]; }
    if (i < 16*128*540) {
        g_c[i] = conv_c[i];
        g_hsplit[i] = pack_split(conv_h[i]);      // buffer 0
    }
}

// Weight split with GATE-INTERLEAVED row permutation:
// orig row m = g*128 + rr -> perm row = (rr>>5)*128 + g*32 + (rr&31)
__global__ void split_w_kernel(const float* __restrict__ w) {
    int i = blockIdx.x*blockDim.x + threadIdx.x;
    if (i >= 512*1728) return;
    int row = i / 1728, k = i - row*1728;
    int g = row >> 7, rr = row & 127;
    int rp = (rr >> 5)*128 + g*32 + (rr & 31);
    float f = w[i];
    __nv_bfloat16 h = __float2bfloat16(f);
    __nv_bfloat16 l = __float2bfloat16(f - __bfloat162float(h));
    g_Whi[(size_t)rp*1728 + k] = h;
    g_Wlo[(size_t)rp*1728 + k] = l;
}

// -------------------- small-conv implicit-GEMM (SIMT) ----------------------
template<int MODE> struct GP;
template<> struct GP<0>{ static constexpr int M=32,  K=192, IH=210,IW=160,OH=52,OW=40,KH=8,KW=8,SH=4,SW=4,PH=1,PW=2,WS=192; };
template<> struct GP<1>{ static constexpr int M=64,  K=512, IH=52, IW=40, OH=27,OW=20,KH=4,KW=4,SH=2,SW=2,PH=2,PW=1,WS=512; };

template<int MODE>
__global__ void __launch_bounds__(256)
gemm_conv(const float* __restrict__ W, const float* __restrict__ bias,
          const float* __restrict__ frame)
{
    using G = GP<MODE>;
    constexpr int PPI = G::OH * G::OW;
    __shared__ float As[16][64];
    __shared__ float Bs[16][64];

    int tid = threadIdx.x;
    int n0 = blockIdx.x * 64;
    int m0 = blockIdx.y * 64;
    int tx = tid & 15, ty = tid >> 4;

    float acc[4][4];
    #pragma unroll
    for (int i=0;i<4;i++)
        #pragma unroll
        for (int j=0;j<4;j++) acc[i][j] = 0.f;

    int a_m = m0 + (tid >> 2);
    int a_k = (tid & 3) * 4;

    int b_n = n0 + (tid & 63);
    int img = b_n / PPI;
    int pos = b_n - img * PPI;
    int oy  = pos / G::OW;
    int ox  = pos - oy * G::OW;
    int iy0 = oy * G::SH - G::PH;
    int ix0 = ox * G::SW - G::PW;

    const float* bbase;
    if constexpr (MODE==0) bbase = frame   + (size_t)img * (3*210*160);
    else                   bbase = g_conv1 + (size_t)img * (32*52*40);

    for (int k0 = 0; k0 < G::K; k0 += 16) {
        float4 av4;
        if (G::M % 64 == 0 || a_m < G::M)
            av4 = *reinterpret_cast<const float4*>(W + (size_t)a_m * G::WS + k0 + a_k);
        else
            av4 = make_float4(0.f,0.f,0.f,0.f);
        As[a_k+0][tid>>2] = av4.x;
        As[a_k+1][tid>>2] = av4.y;
        As[a_k+2][tid>>2] = av4.z;
        As[a_k+3][tid>>2] = av4.w;

        #pragma unroll
        for (int j=0;j<4;j++) {
            int kk = (tid>>6) + j*4;
            int k  = k0 + kk;
            int c  = k / (G::KH*G::KW);
            int rs = k - c*(G::KH*G::KW);
            int r  = rs / G::KW;
            int s  = rs - r*G::KW;
            int iy = iy0 + r, ix = ix0 + s;
            float v = 0.f;
            if (iy >= 0 && iy < G::IH && ix >= 0 && ix < G::IW)
                v = bbase[((size_t)c*G::IH + iy)*G::IW + ix];
            Bs[kk][tid & 63] = v;
        }
        __syncthreads();

        #pragma unroll
        for (int kk=0;kk<16;kk++) {
            float4 a4 = *reinterpret_cast<const float4*>(&As[kk][ty*4]);
            float4 b4 = *reinterpret_cast<const float4*>(&Bs[kk][tx*4]);
            float a[4] = {a4.x,a4.y,a4.z,a4.w};
            float b[4] = {b4.x,b4.y,b4.z,b4.w};
            #pragma unroll
            for (int i=0;i<4;i++)
                #pragma unroll
                for (int j=0;j<4;j++) acc[i][j] += a[i]*b[j];
        }
        __syncthreads();
    }

    #pragma unroll
    for (int i=0;i<4;i++) {
        int m = m0 + ty*4 + i;
        if (G::M % 64 != 0 && m >= G::M) continue;
        #pragma unroll
        for (int j=0;j<4;j++) {
            int n  = n0 + tx*4 + j;
            int im = n / PPI;
            int pp = n - im*PPI;
            float v = acc[i][j] + bias[m];
            if constexpr (MODE==0) g_conv1[(size_t)(im*32+m)*2080 + pp] = v;
            else                   g_xsplit[(size_t)(im*64+m)*540 + pp] = pack_split(v);
        }
    }
}

// ---------------- HMMA GEMM for the 3x3 convs (bf16 hi/lo split) -----------
static constexpr int OFF_AHI = 0;
static constexpr int OFF_ALO = 10240;
static constexpr int OFF_BHI = 20480;
static constexpr int OFF_BLO = 30720;
static constexpr int OFF_KTAB = 40960;            // 1152 x u32 (mainloop only)
static constexpr int SMEM_MMA = 128*132*4;        // 67584 (stage reuses tiles)

template<int MODE>
__global__ void __launch_bounds__(256, 2)
gemm_mma(const float* __restrict__ bias, int t, const unsigned char* __restrict__ done,
         int nbase)
{
    constexpr int KTOT  = (MODE==2) ? 576 : 1152;
    constexpr int WO    = (MODE==2) ? 0   : 576;
    constexpr int NTOT  = (MODE==2) ? 512*540 : 16*540;
    constexpr int NCH   = (MODE==2) ? 64  : 128;
    constexpr int NCHUNK= KTOT/32;

    extern __shared__ char smem[];
    uint32_t sb = smem_u32(smem);
    uint32_t* ktab = reinterpret_cast<uint32_t*>(smem + OFF_KTAB);
    int tid  = threadIdx.x;
    int wid  = tid >> 5;
    int lane = tid & 31;

    int n0 = (nbase + blockIdx.x) * 128;
    int m0 = blockIdx.y * 128;

    // double-buffer pointers (read old h, write new h elsewhere)
    const unsigned int* hread  = g_hsplit + (size_t)(t & 1) * HSZ;
    unsigned int*       hwrite = g_hsplit + (size_t)((t + 1) & 1) * HSZ;

    // ---- build k -> (delta, r, s) table ----
    for (int k = tid; k < KTOT; k += 256) {
        int c = k/9, rs = k - c*9, r = rs/3, s = rs - r*3;
        ktab[k] = (uint32_t)(c*540 + r*20 + s) | ((uint32_t)r << 20) | ((uint32_t)s << 24);
    }

    // ---- per-thread B-gather coords ----
    int nn    = tid & 127;
    int khalf = tid >> 7;
    int bn    = n0 + nn;
    bool nvalid = (bn < NTOT);
    int bnc = nvalid ? bn : 0;
    int img = bnc / 540;
    int pos = bnc - img * 540;
    int oy = pos / 20, ox = pos - oy * 20;
    int iy0 = oy - 1, ix0 = ox - 1;
    const unsigned int* bptr =
        (MODE==2 ? (const unsigned int*)g_xsplit : hread) + (size_t)img * NCH * 540 + (iy0*20 + ix0);
    if (MODE == 3 && nvalid && done[t*16 + img]) nvalid = false;

    // ---- per-thread A-load coords ----
    int a_r0 = (tid*2)   >> 2;  int a_k0 = ((tid*2)   & 3) * 8;
    int a_r1 = (tid*2+1) >> 2;  int a_k1 = ((tid*2+1) & 3) * 8;

    int wm = (wid >> 2) * 64;
    int wn = (wid & 3) * 32;

    float cfr[4][4][4];
    #pragma unroll
    for (int mi=0;mi<4;mi++)
        #pragma unroll
        for (int ni=0;ni<4;ni++)
            #pragma unroll
            for (int e=0;e<4;e++) cfr[mi][ni][e] = 0.f;

    __syncthreads();   // ktab ready

    for (int ch = 0; ch < NCHUNK; ch++) {
        int k0 = ch * 32;

        // ---- A tiles: direct gmem -> smem (latency hidden by co-resident CTA) ----
        *reinterpret_cast<uint4*>(smem + OFF_AHI + (a_r0*40 + a_k0)*2) =
            *reinterpret_cast<const uint4*>(g_Whi + (size_t)(m0+a_r0)*1728 + WO + k0 + a_k0);
        *reinterpret_cast<uint4*>(smem + OFF_AHI + (a_r1*40 + a_k1)*2) =
            *reinterpret_cast<const uint4*>(g_Whi + (size_t)(m0+a_r1)*1728 + WO + k0 + a_k1);
        *reinterpret_cast<uint4*>(smem + OFF_ALO + (a_r0*40 + a_k0)*2) =
            *reinterpret_cast<const uint4*>(g_Wlo + (size_t)(m0+a_r0)*1728 + WO + k0 + a_k0);
        *reinterpret_cast<uint4*>(smem + OFF_ALO + (a_r1*40 + a_k1)*2) =
            *reinterpret_cast<const uint4*>(g_Wlo + (size_t)(m0+a_r1)*1728 + WO + k0 + a_k1);

        // ---- B gather (im2col) direct to smem ----
        {
            int kb = khalf*16;
            #pragma unroll
            for (int i=0;i<16;i+=2) {
                uint32_t tv0 = ktab[k0 + kb + i];
                uint32_t tv1 = ktab[k0 + kb + i + 1];
                unsigned int v0 = 0, v1 = 0;
                int r0_=(tv0>>20)&15, s0_=(tv0>>24)&15;
                int r1_=(tv1>>20)&15, s1_=(tv1>>24)&15;
                if (nvalid && (unsigned)(iy0+r0_)<27u && (unsigned)(ix0+s0_)<20u)
                    v0 = bptr[tv0 & 0xFFFFF];
                if (nvalid && (unsigned)(iy0+r1_)<27u && (unsigned)(ix0+s1_)<20u)
                    v1 = bptr[tv1 & 0xFFFFF];
                uint32_t hi = (v0 & 0xFFFFu) | (v1 << 16);
                uint32_t lo = (v0 >> 16) | (v1 & 0xFFFF0000u);
                *reinterpret_cast<uint32_t*>(smem + OFF_BHI + (nn*40 + kb + i)*2) = hi;
                *reinterpret_cast<uint32_t*>(smem + OFF_BLO + (nn*40 + kb + i)*2) = lo;
            }
        }
        __syncthreads();

        #pragma unroll
        for (int kk = 0; kk < 32; kk += 16) {
            uint32_t af[4][4], bfh[4][2], bfl[4][2];
            {
                uint32_t row = wm + (lane & 15);
                uint32_t col = kk + (lane >> 4) * 8;
                #pragma unroll
                for (int mi=0;mi<4;mi++)
                    ldsm_x4(af[mi], sb + OFF_AHI + ((row + mi*16)*40 + col)*2);
            }
            {
                int l2 = lane & 15;
                uint32_t row = wn + (l2 & 7);
                uint32_t col = kk + (l2 >> 3) * 8;
                #pragma unroll
                for (int ni=0;ni<4;ni++) {
                    ldsm_x2(bfh[ni], sb + OFF_BHI + ((row + ni*8)*40 + col)*2);
                    ldsm_x2(bfl[ni], sb + OFF_BLO + ((row + ni*8)*40 + col)*2);
                }
            }
            #pragma unroll
            for (int mi=0;mi<4;mi++)
                #pragma unroll
                for (int ni=0;ni<4;ni++) {
                    mma16816(cfr[mi][ni], af[mi], bfh[ni]);
                    mma16816(cfr[mi][ni], af[mi], bfl[ni]);
                }
            {
                uint32_t row = wm + (lane & 15);
                uint32_t col = kk + (lane >> 4) * 8;
                #pragma unroll
                for (int mi=0;mi<4;mi++)
                    ldsm_x4(af[mi], sb + OFF_ALO + ((row + mi*16)*40 + col)*2);
            }
            #pragma unroll
            for (int mi=0;mi<4;mi++)
                #pragma unroll
                for (int ni=0;ni<4;ni++)
                    mma16816(cfr[mi][ni], af[mi], bfh[ni]);
        }
        __syncthreads();
    }

    // ---- frags -> smem stage ----
    float* stage = reinterpret_cast<float*>(smem);
    int gid = lane >> 2, tig = lane & 3;
    #pragma unroll
    for (int mi=0;mi<4;mi++)
        #pragma unroll
        for (int ni=0;ni<4;ni++) {
            int r0 = wm + mi*16 + gid;
            int c0 = wn + ni*8 + tig*2;
            stage[r0*132 + c0]       = cfr[mi][ni][0];
            stage[r0*132 + c0 + 1]   = cfr[mi][ni][1];
            stage[(r0+8)*132 + c0]   = cfr[mi][ni][2];
            stage[(r0+8)*132 + c0+1] = cfr[mi][ni][3];
        }
    __syncthreads();

    if constexpr (MODE == 2) {
        int my = blockIdx.y;
        for (int idx = tid; idx < 128*128; idx += 256) {
            int r = idx >> 7, c2 = idx & 127;
            int n = n0 + c2;
            int m  = m0 + r;
            int gg = r >> 5, c32 = r & 31;
            int morig = gg*128 + my*32 + c32;
            int im = n / 540;
            int pp = n - im*540;
            g_Gx[((size_t)im*512 + m)*540 + pp] = stage[r*132 + c2] + bias[morig];
        }
    } else {
        // fused ConvLSTM update: stage rows {c32, 32+c32, 64+c32, 96+c32} are
        // (ai, af, ao, ag) for channel my*32+c32.
        int my = blockIdx.y;
        int tb = t*16;
        for (int idx = tid; idx < 32*128; idx += 256) {
            int c32 = idx >> 7, col = idx & 127;
            int n = n0 + col;
            if (n >= 8640) continue;
            int im = n / 540, pp = n - im*540;
            int ch = my*32 + c32;
            size_t gxb = ((size_t)(tb + im)*512 + my*128 + c32)*540 + pp;
            float ai = stage[(     c32)*132 + col] + g_Gx[gxb];
            float af = stage[(32 + c32)*132 + col] + g_Gx[gxb + (size_t)32*540];
            float ao = stage[(64 + c32)*132 + col] + g_Gx[gxb + (size_t)64*540];
            float ag = stage[(96 + c32)*132 + col] + g_Gx[gxb + (size_t)96*540];
            float nd = (done[tb+im]==0) ? 1.f : 0.f;
            int hidx = (im*128 + ch)*540 + pp;
            float c = g_c[hidx] * nd;
            c = sigmoidf_(af)*c + sigmoidf_(ai)*tanhf(ag);
            float h = sigmoidf_(ao)*tanhf(c);
            g_c[hidx] = c;
            g_h[hidx] = h;
            hwrite[hidx] = pack_split(h);
            g_O[(size_t)(tb+im)*69120 + (size_t)ch*540 + pp] = h;
        }
    }
}

// --------------------------- fused core step (512 threads) ------------------
__global__ void __launch_bounds__(512)
core_step(int t, const unsigned char* __restrict__ done,
          const float* __restrict__ qw1, const float* __restrict__ qb1,
          const float* __restrict__ qw2, const float* __restrict__ qb2,
          const float* __restrict__ qw3, const float* __restrict__ qb3,
          const float* __restrict__ aw1, const float* __restrict__ ab1,
          const float* __restrict__ aw2, const float* __restrict__ ab2,
          const float* __restrict__ w_ih, const float* __restrict__ w_hh,
          const float* __restrict__ b_ih, const float* __restrict__ b_hh,
          const int* __restrict__ last_action, const float* __restrict__ reward)
{
    int b = blockIdx.x;
    int tid = threadIdx.x;
    int wid = tid >> 5, lane = tid & 31;

    __shared__ float sh[256];
    __shared__ float q1[128];
    __shared__ float q2[288];
    __shared__ float q3[288];
    __shared__ float sA[2160];
    __shared__ float red[512];
    __shared__ float mx[4], sm[4];
    __shared__ float ans[736];
    __shared__ float a1[512];
    __shared__ float ci[256];
    __shared__ float gsum[1024];

    if (tid < 256) sh[tid] = g_ch[b*256 + tid];
    __syncthreads();

    if (tid < 128) {
        float s = qb1[tid];
        for (int k=0;k<256;k++) s += sh[k]*qw1[k*128+tid];
        q1[tid] = fmaxf(s, 0.f);
    }
    __syncthreads();
    if (tid < 288) {
        float s = qb2[tid];
        for (int k=0;k<128;k++) s += q1[k]*qw2[k*288+tid];
        q2[tid] = fmaxf(s, 0.f);
    }
    __syncthreads();
    if (tid < 288) {
        float s = qb3[tid];
        for (int k=0;k<288;k++) s += q2[k]*qw3[k*288+tid];
        q3[tid] = s;
    }
    __syncthreads();

    const float* Ob = g_O + ((size_t)(t*16+b))*69120;
    for (int idx=tid; idx<2160; idx+=512) {
        int p = idx >> 2, qi = idx & 3;
        const float* qv = q3 + qi*72;
        const float* op = Ob + (size_t)p*128;
        const float* sp = g_S + p*64;
        float s = 0.f;
        #pragma unroll
        for (int k=0;k<8;k++)  s += op[k]*qv[k];
        #pragma unroll 8
        for (int k=0;k<64;k++) s += sp[k]*qv[8+k];
        sA[idx] = s;
    }
    __syncthreads();

    {
        int qi = tid >> 7, lane7 = tid & 127;
        float m = -1e30f;
        for (int p=lane7;p<540;p+=128) m = fmaxf(m, sA[p*4+qi]);
        red[tid] = m;
        __syncthreads();
        if (tid < 4) { float mm=-1e30f; for (int i=0;i<128;i++) mm = fmaxf(mm, red[tid*128+i]); mx[tid]=mm; }
        __syncthreads();
        for (int idx=tid; idx<2160; idx+=512) sA[idx] = expf(sA[idx]-mx[idx&3]);
        __syncthreads();
        float s = 0.f;
        for (int p=lane7;p<540;p+=128) s += sA[p*4+qi];
        red[tid] = s;
        __syncthreads();
        if (tid < 4) { float ss=0.f; for (int i=0;i<128;i++) ss += red[tid*128+i]; sm[tid]=ss; }
        __syncthreads();
    }

    // ans: <=2 outputs per thread (o0=tid, o1=tid+512 for tid<224)
    {
        int o0 = tid, o1 = tid + 512;
        bool has1 = (o1 < 736);
        int q0 = o0/184, v0 = o0-q0*184;
        int q1i = has1 ? o1/184 : 0, v1 = has1 ? o1-q1i*184 : 0;
        const float* b0 = (v0<120) ? Ob+8+v0 : g_S+(v0-120);
        const float* b1 = (v1<120) ? Ob+8+v1 : g_S+(v1-120);
        int s0 = (v0<120)?128:64, s1 = (v1<120)?128:64;
        float a0=0.f, a1v=0.f;
        #pragma unroll 4
        for (int p=0;p<540;p++) {
            a0 += sA[p*4+q0] * b0[(size_t)p*s0];
            if (has1) a1v += sA[p*4+q1i] * b1[(size_t)p*s1];
        }
        ans[o0] = a0 / sm[q0];
        if (has1) ans[o1] = a1v / sm[q1i];
    }
    __syncthreads();

    float rclip = fminf(fmaxf(reward[t*16+b], -1.f), 1.f);
    int act = last_action[t*16+b];
    float nd = (done[t*16+b]==0) ? 1.f : 0.f;

    // a1 = relu(answer @ aw1 + ab1): exactly 1 output per thread
    {
        int j = tid;
        float s0 = ab1[j];
        for (int k=0;k<736;k++) s0 += ans[k]*aw1[(size_t)k*512+j];
        for (int k=0;k<288;k++) s0 += q3[k]*aw1[(size_t)(736+k)*512+j];
        s0 += rclip*aw1[(size_t)1024*512+j] + aw1[(size_t)(1025+act)*512+j];
        a1[j] = fmaxf(s0, 0.f);
    }
    __syncthreads();
    if (tid < 256) {
        float s = ab2[tid];
        for (int k=0;k<512;k++) s += a1[k]*aw2[(size_t)k*256+tid];
        ci[tid] = s;
    }
    __syncthreads();

    // LSTM gates: 16 warps, warp-per-output, float4 reads + shuffle reduce
    for (int j = wid; j < 1024; j += 16) {
        const float4* wi4 = reinterpret_cast<const float4*>(w_ih + (size_t)j*256);
        const float4* wh4 = reinterpret_cast<const float4*>(w_hh + (size_t)j*256);
        float s1 = 0.f, s2 = 0.f;
        #pragma unroll
        for (int it = 0; it < 2; it++) {
            int k4 = lane + it*32;
            float4 a = wi4[k4];
            float4 bq = wh4[k4];
            int kb = k4*4;
            s1 += ci[kb]*a.x + ci[kb+1]*a.y + ci[kb+2]*a.z + ci[kb+3]*a.w;
            s2 += sh[kb]*bq.x + sh[kb+1]*bq.y + sh[kb+2]*bq.z + sh[kb+3]*bq.w;
        }
        #pragma unroll
        for (int off=16; off; off>>=1) {
            s1 += __shfl_down_sync(0xFFFFFFFFu, s1, off);
            s2 += __shfl_down_sync(0xFFFFFFFFu, s2, off);
        }
        if (lane == 0) gsum[j] = s1 + nd*s2 + b_ih[j] + b_hh[j];
    }
    __syncthreads();

    if (tid < 256) {
        float gi = gsum[tid], gf = gsum[256+tid], gG = gsum[512+tid], go = gsum[768+tid];
        float c = nd * g_cc[b*256+tid];
        c = sigmoidf_(gf)*c + sigmoidf_(gi)*tanhf(gG);
        float h = sigmoidf_(go)*tanhf(c);
        g_cc[b*256+tid] = c;
        g_ch[b*256+tid] = h;
        g_outs[((size_t)t*16+b)*256 + tid] = h;
    }
}

// ------------------------------- heads -------------------------------------
__global__ void head_kernel(const float* __restrict__ pw, const float* __restrict__ pb,
                            const float* __restrict__ vw, const float* __restrict__ vb,
                            float* __restrict__ out)
{
    int row = blockIdx.x;
    int tid = threadIdx.x;
    __shared__ float lg[18];
    const float* h = g_outs + (size_t)row*256;
    if (tid < 18) {
        float s = pb[tid];
        for (int k=0;k<256;k++) s += h[k]*pw[k*18+tid];
        lg[tid] = s;
        out[row*18 + tid] = s;
    }
    if (tid == 19) {
        float s = vb[0];
        for (int k=0;k<256;k++) s += h[k]*vw[k];
        out[9216 + row] = s;
    }
    __syncthreads();
    if (tid == 0) {
        int am = 0; float bv = lg[0];
        for (int j=1;j<18;j++) if (lg[j] > bv) { bv = lg[j]; am = j; }
        out[9728 + row] = (float)am;
    }
}

__global__ void write_states(float* __restrict__ out) {
    int i = blockIdx.x*blockDim.x + threadIdx.x;
    if (i < 4096) { out[10240 + i] = g_ch[i]; out[14336 + i] = g_cc[i]; }
    if (i < 1105920) { out[18432 + i] = g_h[i]; out[1124352 + i] = g_c[i]; }
}

// ------------------------------- launch ------------------------------------
extern "C" void kernel_launch(void* const* d_in, const int* in_sizes, int n_in,
                              void* d_out, int out_size) {
    const float*         frame      = (const float*)d_in[0];
    const unsigned char* done       = (const unsigned char*)d_in[1];
    const int*           last_action= (const int*)d_in[2];
    const float*         reward     = (const float*)d_in[3];
    const float*         core_h     = (const float*)d_in[4];
    const float*         core_c     = (const float*)d_in[5];
    const float*         conv_h     = (const float*)d_in[6];
    const float*         conv_c     = (const float*)d_in[7];
    const float*         cnn_w1     = (const float*)d_in[8];
    const float*         cnn_b1     = (const float*)d_in[9];
    const float*         cnn_w2     = (const float*)d_in[10];
    const float*         cnn_b2     = (const float*)d_in[11];
    const float*         lstm_w     = (const float*)d_in[12];
    const float*         lstm_b     = (const float*)d_in[13];
    const float*         qw1        = (const float*)d_in[14];
    const float*         qb1        = (const float*)d_in[15];
    const float*         qw2        = (const float*)d_in[16];
    const float*         qb2        = (const float*)d_in[17];
    const float*         qw3        = (const float*)d_in[18];
    const float*         qb3        = (const float*)d_in[19];
    const float*         aw1        = (const float*)d_in[20];
    const float*         ab1        = (const float*)d_in[21];
    const float*         aw2        = (const float*)d_in[22];
    const float*         ab2        = (const float*)d_in[23];
    const float*         w_ih       = (const float*)d_in[24];
    const float*         w_hh       = (const float*)d_in[25];
    const float*         b_ih       = (const float*)d_in[26];
    const float*         b_hh       = (const float*)d_in[27];
    const float*         pw         = (const float*)d_in[28];
    const float*         pb         = (const float*)d_in[29];
    const float*         vw         = (const float*)d_in[30];
    const float*         vb         = (const float*)d_in[31];
    float* out = (float*)d_out;

    static cudaStream_t sGx = nullptr, sCore = nullptr;
    static cudaEvent_t evFront, evGx[8], evM[NT], evCoreDone;
    if (!sGx) {
        cudaStreamCreateWithFlags(&sGx,   cudaStreamNonBlocking);
        cudaStreamCreateWithFlags(&sCore, cudaStreamNonBlocking);
        cudaEventCreateWithFlags(&evFront, cudaEventDisableTiming);
        for (int c = 0; c < 8; c++) cudaEventCreateWithFlags(&evGx[c], cudaEventDisableTiming);
        for (int t = 0; t < NT; t++) cudaEventCreateWithFlags(&evM[t], cudaEventDisableTiming);
        cudaEventCreateWithFlags(&evCoreDone, cudaEventDisableTiming);
        cudaFuncSetAttribute(gemm_mma<2>, cudaFuncAttributeMaxDynamicSharedMemorySize, SMEM_MMA);
        cudaFuncSetAttribute(gemm_mma<3>, cudaFuncAttributeMaxDynamicSharedMemorySize, SMEM_MMA);
    }

    init_kernel<<<4320, 256>>>(core_h, core_c, conv_h, conv_c);
    split_w_kernel<<<3456, 256>>>(lstm_w);

    gemm_conv<0><<<dim3(16640,1), 256>>>(cnn_w1, cnn_b1, frame);
    gemm_conv<1><<<dim3(4320,1), 256>>>(cnn_w2, cnn_b2, frame);
    cudaEventRecord(evFront, 0);

    // Gx in 8 chunks of 4 timesteps each (270 n-tiles = 64 images exactly),
    // on its own stream so later chunks overlap the t-loop below.
    cudaStreamWaitEvent(sGx, evFront, 0);
    for (int c = 0; c < 8; c++) {
        gemm_mma<2><<<dim3(270,4), 256, SMEM_MMA, sGx>>>(lstm_b, 0, done, c*270);
        cudaEventRecord(evGx[c], sGx);
    }

    for (int t = 0; t < NT; t++) {
        if ((t & 3) == 0) cudaStreamWaitEvent(0, evGx[t >> 2], 0);
        // gates + fused ConvLSTM pointwise update (double-buffered h)
        gemm_mma<3><<<dim3(68,4), 256, SMEM_MMA>>>(lstm_b, t, done, 0);
        cudaEventRecord(evM[t], 0);
        // core_step(t) on its own stream: overlaps gemm_mma<3>(t+1)
        cudaStreamWaitEvent(sCore, evM[t], 0);
        core_step<<<16, 512, 0, sCore>>>(t, done, qw1,qb1,qw2,qb2,qw3,qb3,
                                         aw1,ab1,aw2,ab2, w_ih,w_hh,b_ih,b_hh,
                                         last_action, reward);
    }
    cudaEventRecord(evCoreDone, sCore);
    cudaStreamWaitEvent(0, evCoreDone, 0);

    head_kernel<<<512, 32>>>(pw, pb, vw, vb, out);
    write_states<<<4320, 256>>>(out);
}

// round 15
// speedup vs baseline: 3.2842x; 1.0447x over previous
#include <cuda_runtime.h>
#include <cuda_bf16.h>
#include <math.h>
#include <cstdint>

// ---------------------------------------------------------------------------
// AttentionNet: conv1 -> conv2 -> ConvLSTM(T=32) -> attention core LSTM(T=32)
// 3x3-conv GEMMs on HMMA (bf16 hi/lo 3-split, fp32 acc), 2 CTAs/SM.
// R15: R13 scheduling topology (2 streams — passed teardown memory check)
// + retiled conv0 (32x128, no wasted M-half).
// ---------------------------------------------------------------------------

#define NT 32
#define HSZ (16u*128*540)

// ------------------------- static device scratch ---------------------------
__device__ float g_conv1[512u*32*2080];          // (512,32,52,40)
__device__ float g_Gx   [141557760u];            // (512,512,540) permuted-row Gx
__device__ float g_O    [512u*128*540];          // (T*B,128,540) RAW NCHW h outputs
__device__ float g_h    [16*128*540];            // conv h state (fp32, final only)
__device__ float g_c    [16*128*540];            // conv c state
__device__ float g_S    [540*64];                // spatial basis
__device__ float g_ch   [16*256];                // core h
__device__ float g_cc   [16*256];                // core c
__device__ float g_outs [32*16*256];             // core outputs per step

// bf16-split operands (rows PERMUTED: row' = my*128 + g*32 + c32)
__device__ __align__(16) __nv_bfloat16 g_Whi[512u*1728];
__device__ __align__(16) __nv_bfloat16 g_Wlo[512u*1728];
__device__ unsigned int g_xsplit[512u*64*540];   // packed hi | lo<<16
__device__ unsigned int g_hsplit[2u*HSZ];        // DOUBLE-BUFFERED packed h

__device__ __forceinline__ float sigmoidf_(float x) { return 1.f/(1.f+expf(-x)); }

__device__ __forceinline__ unsigned int pack_split(float f) {
    __nv_bfloat16 h = __float2bfloat16(f);
    float hf = __bfloat162float(h);
    __nv_bfloat16 l = __float2bfloat16(f - hf);
    unsigned short hu = *reinterpret_cast<unsigned short*>(&h);
    unsigned short lu = *reinterpret_cast<unsigned short*>(&l);
    return (unsigned int)hu | ((unsigned int)lu << 16);
}

// ----------------------------- mma helpers ---------------------------------
__device__ __forceinline__ uint32_t smem_u32(const void* p) {
    uint32_t a;
    asm("{ .reg .u64 t; cvta.to.shared.u64 t, %1; cvt.u32.u64 %0, t; }" : "=r"(a) : "l"(p));
    return a;
}
__device__ __forceinline__ void ldsm_x4(uint32_t* r, uint32_t addr) {
    asm volatile("ldmatrix.sync.aligned.m8n8.x4.shared.b16 {%0,%1,%2,%3}, [%4];"
        : "=r"(r[0]), "=r"(r[1]), "=r"(r[2]), "=r"(r[3]) : "r"(addr));
}
__device__ __forceinline__ void ldsm_x2(uint32_t* r, uint32_t addr) {
    asm volatile("ldmatrix.sync.aligned.m8n8.x2.shared.b16 {%0,%1}, [%2];"
        : "=r"(r[0]), "=r"(r[1]) : "r"(addr));
}
__device__ __forceinline__ void mma16816(float* d, const uint32_t* a, const uint32_t* b) {
    asm volatile(
        "mma.sync.aligned.m16n8k16.row.col.f32.bf16.bf16.f32 "
        "{%0,%1,%2,%3}, {%4,%5,%6,%7}, {%8,%9}, {%0,%1,%2,%3};"
        : "+f"(d[0]), "+f"(d[1]), "+f"(d[2]), "+f"(d[3])
        : "r"(a[0]), "r"(a[1]), "r"(a[2]), "r"(a[3]), "r"(b[0]), "r"(b[1]));
}

// ------------------------------ init -------------------------------------
__global__ void init_kernel(const float* __restrict__ core_h, const float* __restrict__ core_c,
                            const float* __restrict__ conv_h, const float* __restrict__ conv_c) {
    int i = blockIdx.x*blockDim.x + threadIdx.x;
    if (i < 540*64) {
        int p = i >> 6, k = i & 63;
        int y = p/20, x = p - y*20;
        int u = k >> 3, v = k & 7;
        double PI = 3.14159265358979323846;
        g_S[i] = (float)(cos((double)(y+1)*(u+1)*PI/27.0) * cos((double)(x+1)*(v+1)*PI/20.0));
    }
    if (i < 16*256) { g_ch[i] = core_h[i]; g_cc[i] = core_c[i]; }
    if (i < 16*128*540) {
        g_c[i] = conv_c[i];
        g_hsplit[i] = pack_split(conv_h[i]);      // buffer 0
    }
}

// Weight split with GATE-INTERLEAVED row permutation:
// orig row m = g*128 + rr -> perm row = (rr>>5)*128 + g*32 + (rr&31)
__global__ void split_w_kernel(const float* __restrict__ w) {
    int i = blockIdx.x*blockDim.x + threadIdx.x;
    if (i >= 512*1728) return;
    int row = i / 1728, k = i - row*1728;
    int g = row >> 7, rr = row & 127;
    int rp = (rr >> 5)*128 + g*32 + (rr & 31);
    float f = w[i];
    __nv_bfloat16 h = __float2bfloat16(f);
    __nv_bfloat16 l = __float2bfloat16(f - __bfloat162float(h));
    g_Whi[(size_t)rp*1728 + k] = h;
    g_Wlo[(size_t)rp*1728 + k] = l;
}

// -------------------- conv0: 8x8 s4, 3->32, tile 32x128 --------------------
__global__ void __launch_bounds__(256)
conv0_kernel(const float* __restrict__ W, const float* __restrict__ bias,
             const float* __restrict__ frame)
{
    __shared__ float As[16][32];
    __shared__ float Bs[16][128];

    int tid = threadIdx.x;
    int n0 = blockIdx.x * 128;
    int tx = tid & 31, ty = tid >> 5;          // ty 0..7 -> m, tx 0..31 -> n

    float acc[4][4];
    #pragma unroll
    for (int i=0;i<4;i++)
        #pragma unroll
        for (int j=0;j<4;j++) acc[i][j] = 0.f;

    int a_m = tid >> 3;            // 0..31
    int a_k = (tid & 7) * 2;       // 0,2,..,14

    int b_n = n0 + (tid & 127);
    int img = b_n / 2080;
    int pos = b_n - img * 2080;
    int oy  = pos / 40, ox = pos - oy*40;
    int iy0 = oy*4 - 1, ix0 = ox*4 - 2;
    int kh  = tid >> 7;            // 0/1
    const float* bbase = frame + (size_t)img * (3*210*160);

    for (int k0 = 0; k0 < 192; k0 += 16) {
        float2 av = *reinterpret_cast<const float2*>(W + a_m*192 + k0 + a_k);
        As[a_k  ][a_m] = av.x;
        As[a_k+1][a_m] = av.y;
        #pragma unroll
        for (int i=0;i<8;i++) {
            int kk = kh*8 + i;
            int k  = k0 + kk;
            int c  = k >> 6;
            int rs = k & 63;
            int r  = rs >> 3, s = rs & 7;
            int iy = iy0 + r, ix = ix0 + s;
            float v = 0.f;
            if ((unsigned)iy < 210u && (unsigned)ix < 160u)
                v = bbase[(c*210 + iy)*160 + ix];
            Bs[kk][tid & 127] = v;
        }
        __syncthreads();

        #pragma unroll
        for (int kk=0;kk<16;kk++) {
            float4 a4 = *reinterpret_cast<const float4*>(&As[kk][ty*4]);
            float4 b4 = *reinterpret_cast<const float4*>(&Bs[kk][tx*4]);
            float a[4] = {a4.x,a4.y,a4.z,a4.w};
            float b[4] = {b4.x,b4.y,b4.z,b4.w};
            #pragma unroll
            for (int i=0;i<4;i++)
                #pragma unroll
                for (int j=0;j<4;j++) acc[i][j] += a[i]*b[j];
        }
        __syncthreads();
    }

    #pragma unroll
    for (int i=0;i<4;i++) {
        int m = ty*4 + i;
        float bm = bias[m];
        #pragma unroll
        for (int j=0;j<4;j++) {
            int n  = n0 + tx*4 + j;
            int im = n / 2080;
            int pp = n - im*2080;
            g_conv1[(size_t)(im*32+m)*2080 + pp] = acc[i][j] + bm;
        }
    }
}

// -------------------- conv1: 4x4 s2, 32->64, tile 64x64 --------------------
__global__ void __launch_bounds__(256)
conv1_kernel(const float* __restrict__ W, const float* __restrict__ bias)
{
    constexpr int K=512, IH=52, IW=40, KH=4, KW=4;
    __shared__ float As[16][64];
    __shared__ float Bs[16][64];

    int tid = threadIdx.x;
    int n0 = blockIdx.x * 64;
    int tx = tid & 15, ty = tid >> 4;

    float acc[4][4];
    #pragma unroll
    for (int i=0;i<4;i++)
        #pragma unroll
        for (int j=0;j<4;j++) acc[i][j] = 0.f;

    int a_m = tid >> 2;
    int a_k = (tid & 3) * 4;

    int b_n = n0 + (tid & 63);
    int img = b_n / 540;
    int pos = b_n - img * 540;
    int oy  = pos / 20;
    int ox  = pos - oy * 20;
    int iy0 = oy * 2 - 2;
    int ix0 = ox * 2 - 1;

    const float* bbase = g_conv1 + (size_t)img * (32*52*40);

    for (int k0 = 0; k0 < K; k0 += 16) {
        float4 av4 = *reinterpret_cast<const float4*>(W + (size_t)a_m * K + k0 + a_k);
        As[a_k+0][a_m] = av4.x;
        As[a_k+1][a_m] = av4.y;
        As[a_k+2][a_m] = av4.z;
        As[a_k+3][a_m] = av4.w;

        #pragma unroll
        for (int j=0;j<4;j++) {
            int kk = (tid>>6) + j*4;
            int k  = k0 + kk;
            int c  = k / (KH*KW);
            int rs = k - c*(KH*KW);
            int r  = rs / KW;
            int s  = rs - r*KW;
            int iy = iy0 + r, ix = ix0 + s;
            float v = 0.f;
            if (iy >= 0 && iy < IH && ix >= 0 && ix < IW)
                v = bbase[((size_t)c*IH + iy)*IW + ix];
            Bs[kk][tid & 63] = v;
        }
        __syncthreads();

        #pragma unroll
        for (int kk=0;kk<16;kk++) {
            float4 a4 = *reinterpret_cast<const float4*>(&As[kk][ty*4]);
            float4 b4 = *reinterpret_cast<const float4*>(&Bs[kk][tx*4]);
            float a[4] = {a4.x,a4.y,a4.z,a4.w};
            float b[4] = {b4.x,b4.y,b4.z,b4.w};
            #pragma unroll
            for (int i=0;i<4;i++)
                #pragma unroll
                for (int j=0;j<4;j++) acc[i][j] += a[i]*b[j];
        }
        __syncthreads();
    }

    #pragma unroll
    for (int i=0;i<4;i++) {
        int m = ty*4 + i;
        float bm = bias[m];
        #pragma unroll
        for (int j=0;j<4;j++) {
            int n  = n0 + tx*4 + j;
            int im = n / 540;
            int pp = n - im*540;
            g_xsplit[(size_t)(im*64+m)*540 + pp] = pack_split(acc[i][j] + bm);
        }
    }
}

// ---------------- HMMA GEMM for the 3x3 convs (bf16 hi/lo split) -----------
static constexpr int OFF_AHI = 0;
static constexpr int OFF_ALO = 10240;
static constexpr int OFF_BHI = 20480;
static constexpr int OFF_BLO = 30720;
static constexpr int OFF_KTAB = 40960;            // 1152 x u32 (mainloop only)
static constexpr int SMEM_MMA = 128*132*4;        // 67584 (stage reuses tiles)

template<int MODE>
__global__ void __launch_bounds__(256, 2)
gemm_mma(const float* __restrict__ bias, int t, const unsigned char* __restrict__ done,
         int nbase)
{
    constexpr int KTOT  = (MODE==2) ? 576 : 1152;
    constexpr int WO    = (MODE==2) ? 0   : 576;
    constexpr int NTOT  = (MODE==2) ? 512*540 : 16*540;
    constexpr int NCH   = (MODE==2) ? 64  : 128;
    constexpr int NCHUNK= KTOT/32;

    extern __shared__ char smem[];
    uint32_t sb = smem_u32(smem);
    uint32_t* ktab = reinterpret_cast<uint32_t*>(smem + OFF_KTAB);
    int tid  = threadIdx.x;
    int wid  = tid >> 5;
    int lane = tid & 31;

    int n0 = (nbase + blockIdx.x) * 128;
    int m0 = blockIdx.y * 128;

    // double-buffer pointers (read old h, write new h elsewhere)
    const unsigned int* hread  = g_hsplit + (size_t)(t & 1) * HSZ;
    unsigned int*       hwrite = g_hsplit + (size_t)((t + 1) & 1) * HSZ;

    // ---- build k -> (delta, r, s) table ----
    for (int k = tid; k < KTOT; k += 256) {
        int c = k/9, rs = k - c*9, r = rs/3, s = rs - r*3;
        ktab[k] = (uint32_t)(c*540 + r*20 + s) | ((uint32_t)r << 20) | ((uint32_t)s << 24);
    }

    // ---- per-thread B-gather coords ----
    int nn    = tid & 127;
    int khalf = tid >> 7;
    int bn    = n0 + nn;
    bool nvalid = (bn < NTOT);
    int bnc = nvalid ? bn : 0;
    int img = bnc / 540;
    int pos = bnc - img * 540;
    int oy = pos / 20, ox = pos - oy * 20;
    int iy0 = oy - 1, ix0 = ox - 1;
    const unsigned int* bptr =
        (MODE==2 ? (const unsigned int*)g_xsplit : hread) + (size_t)img * NCH * 540 + (iy0*20 + ix0);
    if (MODE == 3 && nvalid && done[t*16 + img]) nvalid = false;

    // ---- per-thread A-load coords ----
    int a_r0 = (tid*2)   >> 2;  int a_k0 = ((tid*2)   & 3) * 8;
    int a_r1 = (tid*2+1) >> 2;  int a_k1 = ((tid*2+1) & 3) * 8;

    int wm = (wid >> 2) * 64;
    int wn = (wid & 3) * 32;

    float cfr[4][4][4];
    #pragma unroll
    for (int mi=0;mi<4;mi++)
        #pragma unroll
        for (int ni=0;ni<4;ni++)
            #pragma unroll
            for (int e=0;e<4;e++) cfr[mi][ni][e] = 0.f;

    __syncthreads();   // ktab ready

    for (int ch = 0; ch < NCHUNK; ch++) {
        int k0 = ch * 32;

        // ---- A tiles: direct gmem -> smem (latency hidden by co-resident CTA) ----
        *reinterpret_cast<uint4*>(smem + OFF_AHI + (a_r0*40 + a_k0)*2) =
            *reinterpret_cast<const uint4*>(g_Whi + (size_t)(m0+a_r0)*1728 + WO + k0 + a_k0);
        *reinterpret_cast<uint4*>(smem + OFF_AHI + (a_r1*40 + a_k1)*2) =
            *reinterpret_cast<const uint4*>(g_Whi + (size_t)(m0+a_r1)*1728 + WO + k0 + a_k1);
        *reinterpret_cast<uint4*>(smem + OFF_ALO + (a_r0*40 + a_k0)*2) =
            *reinterpret_cast<const uint4*>(g_Wlo + (size_t)(m0+a_r0)*1728 + WO + k0 + a_k0);
        *reinterpret_cast<uint4*>(smem + OFF_ALO + (a_r1*40 + a_k1)*2) =
            *reinterpret_cast<const uint4*>(g_Wlo + (size_t)(m0+a_r1)*1728 + WO + k0 + a_k1);

        // ---- B gather (im2col) direct to smem ----
        {
            int kb = khalf*16;
            #pragma unroll
            for (int i=0;i<16;i+=2) {
                uint32_t tv0 = ktab[k0 + kb + i];
                uint32_t tv1 = ktab[k0 + kb + i + 1];
                unsigned int v0 = 0, v1 = 0;
                int r0_=(tv0>>20)&15, s0_=(tv0>>24)&15;
                int r1_=(tv1>>20)&15, s1_=(tv1>>24)&15;
                if (nvalid && (unsigned)(iy0+r0_)<27u && (unsigned)(ix0+s0_)<20u)
                    v0 = bptr[tv0 & 0xFFFFF];
                if (nvalid && (unsigned)(iy0+r1_)<27u && (unsigned)(ix0+s1_)<20u)
                    v1 = bptr[tv1 & 0xFFFFF];
                uint32_t hi = (v0 & 0xFFFFu) | (v1 << 16);
                uint32_t lo = (v0 >> 16) | (v1 & 0xFFFF0000u);
                *reinterpret_cast<uint32_t*>(smem + OFF_BHI + (nn*40 + kb + i)*2) = hi;
                *reinterpret_cast<uint32_t*>(smem + OFF_BLO + (nn*40 + kb + i)*2) = lo;
            }
        }
        __syncthreads();

        #pragma unroll
        for (int kk = 0; kk < 32; kk += 16) {
            uint32_t af[4][4], bfh[4][2], bfl[4][2];
            {
                uint32_t row = wm + (lane & 15);
                uint32_t col = kk + (lane >> 4) * 8;
                #pragma unroll
                for (int mi=0;mi<4;mi++)
                    ldsm_x4(af[mi], sb + OFF_AHI + ((row + mi*16)*40 + col)*2);
            }
            {
                int l2 = lane & 15;
                uint32_t row = wn + (l2 & 7);
                uint32_t col = kk + (l2 >> 3) * 8;
                #pragma unroll
                for (int ni=0;ni<4;ni++) {
                    ldsm_x2(bfh[ni], sb + OFF_BHI + ((row + ni*8)*40 + col)*2);
                    ldsm_x2(bfl[ni], sb + OFF_BLO + ((row + ni*8)*40 + col)*2);
                }
            }
            #pragma unroll
            for (int mi=0;mi<4;mi++)
                #pragma unroll
                for (int ni=0;ni<4;ni++) {
                    mma16816(cfr[mi][ni], af[mi], bfh[ni]);
                    mma16816(cfr[mi][ni], af[mi], bfl[ni]);
                }
            {
                uint32_t row = wm + (lane & 15);
                uint32_t col = kk + (lane >> 4) * 8;
                #pragma unroll
                for (int mi=0;mi<4;mi++)
                    ldsm_x4(af[mi], sb + OFF_ALO + ((row + mi*16)*40 + col)*2);
            }
            #pragma unroll
            for (int mi=0;mi<4;mi++)
                #pragma unroll
                for (int ni=0;ni<4;ni++)
                    mma16816(cfr[mi][ni], af[mi], bfh[ni]);
        }
        __syncthreads();
    }

    // ---- frags -> smem stage ----
    float* stage = reinterpret_cast<float*>(smem);
    int gid = lane >> 2, tig = lane & 3;
    #pragma unroll
    for (int mi=0;mi<4;mi++)
        #pragma unroll
        for (int ni=0;ni<4;ni++) {
            int r0 = wm + mi*16 + gid;
            int c0 = wn + ni*8 + tig*2;
            stage[r0*132 + c0]       = cfr[mi][ni][0];
            stage[r0*132 + c0 + 1]   = cfr[mi][ni][1];
            stage[(r0+8)*132 + c0]   = cfr[mi][ni][2];
            stage[(r0+8)*132 + c0+1] = cfr[mi][ni][3];
        }
    __syncthreads();

    if constexpr (MODE == 2) {
        int my = blockIdx.y;
        for (int idx = tid; idx < 128*128; idx += 256) {
            int r = idx >> 7, c2 = idx & 127;
            int n = n0 + c2;
            int m  = m0 + r;
            int gg = r >> 5, c32 = r & 31;
            int morig = gg*128 + my*32 + c32;
            int im = n / 540;
            int pp = n - im*540;
            g_Gx[((size_t)im*512 + m)*540 + pp] = stage[r*132 + c2] + bias[morig];
        }
    } else {
        // fused ConvLSTM update: stage rows {c32, 32+c32, 64+c32, 96+c32} are
        // (ai, af, ao, ag) for channel my*32+c32.
        int my = blockIdx.y;
        int tb = t*16;
        for (int idx = tid; idx < 32*128; idx += 256) {
            int c32 = idx >> 7, col = idx & 127;
            int n = n0 + col;
            if (n >= 8640) continue;
            int im = n / 540, pp = n - im*540;
            int ch = my*32 + c32;
            size_t gxb = ((size_t)(tb + im)*512 + my*128 + c32)*540 + pp;
            float ai = stage[(     c32)*132 + col] + g_Gx[gxb];
            float af = stage[(32 + c32)*132 + col] + g_Gx[gxb + (size_t)32*540];
            float ao = stage[(64 + c32)*132 + col] + g_Gx[gxb + (size_t)64*540];
            float ag = stage[(96 + c32)*132 + col] + g_Gx[gxb + (size_t)96*540];
            float nd = (done[tb+im]==0) ? 1.f : 0.f;
            int hidx = (im*128 + ch)*540 + pp;
            float c = g_c[hidx] * nd;
            c = sigmoidf_(af)*c + sigmoidf_(ai)*tanhf(ag);
            float h = sigmoidf_(ao)*tanhf(c);
            g_c[hidx] = c;
            g_h[hidx] = h;
            hwrite[hidx] = pack_split(h);
            g_O[(size_t)(tb+im)*69120 + (size_t)ch*540 + pp] = h;
        }
    }
}

// --------------------------- fused core step (512 threads) ------------------
__global__ void __launch_bounds__(512)
core_step(int t, const unsigned char* __restrict__ done,
          const float* __restrict__ qw1, const float* __restrict__ qb1,
          const float* __restrict__ qw2, const float* __restrict__ qb2,
          const float* __restrict__ qw3, const float* __restrict__ qb3,
          const float* __restrict__ aw1, const float* __restrict__ ab1,
          const float* __restrict__ aw2, const float* __restrict__ ab2,
          const float* __restrict__ w_ih, const float* __restrict__ w_hh,
          const float* __restrict__ b_ih, const float* __restrict__ b_hh,
          const int* __restrict__ last_action, const float* __restrict__ reward)
{
    int b = blockIdx.x;
    int tid = threadIdx.x;
    int wid = tid >> 5, lane = tid & 31;

    __shared__ float sh[256];
    __shared__ float q1[128];
    __shared__ float q2[288];
    __shared__ float q3[288];
    __shared__ float sA[2160];
    __shared__ float red[512];
    __shared__ float mx[4], sm[4];
    __shared__ float ans[736];
    __shared__ float a1[512];
    __shared__ float ci[256];
    __shared__ float gsum[1024];

    if (tid < 256) sh[tid] = g_ch[b*256 + tid];
    __syncthreads();

    if (tid < 128) {
        float s = qb1[tid];
        for (int k=0;k<256;k++) s += sh[k]*qw1[k*128+tid];
        q1[tid] = fmaxf(s, 0.f);
    }
    __syncthreads();
    if (tid < 288) {
        float s = qb2[tid];
        for (int k=0;k<128;k++) s += q1[k]*qw2[k*288+tid];
        q2[tid] = fmaxf(s, 0.f);
    }
    __syncthreads();
    if (tid < 288) {
        float s = qb3[tid];
        for (int k=0;k<288;k++) s += q2[k]*qw3[k*288+tid];
        q3[tid] = s;
    }
    __syncthreads();

    const float* Ob = g_O + ((size_t)(t*16+b))*69120;
    for (int idx=tid; idx<2160; idx+=512) {
        int p = idx >> 2, qi = idx & 3;
        const float* qv = q3 + qi*72;
        const float* op = Ob + (size_t)p*128;
        const float* sp = g_S + p*64;
        float s = 0.f;
        #pragma unroll
        for (int k=0;k<8;k++)  s += op[k]*qv[k];
        #pragma unroll 8
        for (int k=0;k<64;k++) s += sp[k]*qv[8+k];
        sA[idx] = s;
    }
    __syncthreads();

    {
        int qi = tid >> 7, lane7 = tid & 127;
        float m = -1e30f;
        for (int p=lane7;p<540;p+=128) m = fmaxf(m, sA[p*4+qi]);
        red[tid] = m;
        __syncthreads();
        if (tid < 4) { float mm=-1e30f; for (int i=0;i<128;i++) mm = fmaxf(mm, red[tid*128+i]); mx[tid]=mm; }
        __syncthreads();
        for (int idx=tid; idx<2160; idx+=512) sA[idx] = expf(sA[idx]-mx[idx&3]);
        __syncthreads();
        float s = 0.f;
        for (int p=lane7;p<540;p+=128) s += sA[p*4+qi];
        red[tid] = s;
        __syncthreads();
        if (tid < 4) { float ss=0.f; for (int i=0;i<128;i++) ss += red[tid*128+i]; sm[tid]=ss; }
        __syncthreads();
    }

    // ans: <=2 outputs per thread
    {
        int o0 = tid, o1 = tid + 512;
        bool has1 = (o1 < 736);
        int q0 = o0/184, v0 = o0-q0*184;
        int q1i = has1 ? o1/184 : 0, v1 = has1 ? o1-q1i*184 : 0;
        const float* b0 = (v0<120) ? Ob+8+v0 : g_S+(v0-120);
        const float* b1 = (v1<120) ? Ob+8+v1 : g_S+(v1-120);
        int s0 = (v0<120)?128:64, s1 = (v1<120)?128:64;
        float a0=0.f, a1v=0.f;
        #pragma unroll 4
        for (int p=0;p<540;p++) {
            a0 += sA[p*4+q0] * b0[(size_t)p*s0];
            if (has1) a1v += sA[p*4+q1i] * b1[(size_t)p*s1];
        }
        ans[o0] = a0 / sm[q0];
        if (has1) ans[o1] = a1v / sm[q1i];
    }
    __syncthreads();

    float rclip = fminf(fmaxf(reward[t*16+b], -1.f), 1.f);
    int act = last_action[t*16+b];
    float nd = (done[t*16+b]==0) ? 1.f : 0.f;

    // a1 = relu(answer @ aw1 + ab1): exactly 1 output per thread
    {
        int j = tid;
        float s0 = ab1[j];
        for (int k=0;k<736;k++) s0 += ans[k]*aw1[(size_t)k*512+j];
        for (int k=0;k<288;k++) s0 += q3[k]*aw1[(size_t)(736+k)*512+j];
        s0 += rclip*aw1[(size_t)1024*512+j] + aw1[(size_t)(1025+act)*512+j];
        a1[j] = fmaxf(s0, 0.f);
    }
    __syncthreads();
    if (tid < 256) {
        float s = ab2[tid];
        for (int k=0;k<512;k++) s += a1[k]*aw2[(size_t)k*256+tid];
        ci[tid] = s;
    }
    __syncthreads();

    // LSTM gates: 16 warps, warp-per-output, float4 reads + shuffle reduce
    for (int j = wid; j < 1024; j += 16) {
        const float4* wi4 = reinterpret_cast<const float4*>(w_ih + (size_t)j*256);
        const float4* wh4 = reinterpret_cast<const float4*>(w_hh + (size_t)j*256);
        float s1 = 0.f, s2 = 0.f;
        #pragma unroll
        for (int it = 0; it < 2; it++) {
            int k4 = lane + it*32;
            float4 a = wi4[k4];
            float4 bq = wh4[k4];
            int kb = k4*4;
            s1 += ci[kb]*a.x + ci[kb+1]*a.y + ci[kb+2]*a.z + ci[kb+3]*a.w;
            s2 += sh[kb]*bq.x + sh[kb+1]*bq.y + sh[kb+2]*bq.z + sh[kb+3]*bq.w;
        }
        #pragma unroll
        for (int off=16; off; off>>=1) {
            s1 += __shfl_down_sync(0xFFFFFFFFu, s1, off);
            s2 += __shfl_down_sync(0xFFFFFFFFu, s2, off);
        }
        if (lane == 0) gsum[j] = s1 + nd*s2 + b_ih[j] + b_hh[j];
    }
    __syncthreads();

    if (tid < 256) {
        float gi = gsum[tid], gf = gsum[256+tid], gG = gsum[512+tid], go = gsum[768+tid];
        float c = nd * g_cc[b*256+tid];
        c = sigmoidf_(gf)*c + sigmoidf_(gi)*tanhf(gG);
        float h = sigmoidf_(go)*tanhf(c);
        g_cc[b*256+tid] = c;
        g_ch[b*256+tid] = h;
        g_outs[((size_t)t*16+b)*256 + tid] = h;
    }
}

// ------------------------------- heads -------------------------------------
__global__ void head_kernel(const float* __restrict__ pw, const float* __restrict__ pb,
                            const float* __restrict__ vw, const float* __restrict__ vb,
                            float* __restrict__ out)
{
    int row = blockIdx.x;
    int tid = threadIdx.x;
    __shared__ float lg[18];
    const float* h = g_outs + (size_t)row*256;
    if (tid < 18) {
        float s = pb[tid];
        for (int k=0;k<256;k++) s += h[k]*pw[k*18+tid];
        lg[tid] = s;
        out[row*18 + tid] = s;
    }
    if (tid == 19) {
        float s = vb[0];
        for (int k=0;k<256;k++) s += h[k]*vw[k];
        out[9216 + row] = s;
    }
    __syncthreads();
    if (tid == 0) {
        int am = 0; float bv = lg[0];
        for (int j=1;j<18;j++) if (lg[j] > bv) { bv = lg[j]; am = j; }
        out[9728 + row] = (float)am;
    }
}

__global__ void write_states(float* __restrict__ out) {
    int i = blockIdx.x*blockDim.x + threadIdx.x;
    if (i < 4096) { out[10240 + i] = g_ch[i]; out[14336 + i] = g_cc[i]; }
    if (i < 1105920) { out[18432 + i] = g_h[i]; out[1124352 + i] = g_c[i]; }
}

// ------------------------------- launch ------------------------------------
extern "C" void kernel_launch(void* const* d_in, const int* in_sizes, int n_in,
                              void* d_out, int out_size) {
    const float*         frame      = (const float*)d_in[0];
    const unsigned char* done       = (const unsigned char*)d_in[1];
    const int*           last_action= (const int*)d_in[2];
    const float*         reward     = (const float*)d_in[3];
    const float*         core_h     = (const float*)d_in[4];
    const float*         core_c     = (const float*)d_in[5];
    const float*         conv_h     = (const float*)d_in[6];
    const float*         conv_c     = (const float*)d_in[7];
    const float*         cnn_w1     = (const float*)d_in[8];
    const float*         cnn_b1     = (const float*)d_in[9];
    const float*         cnn_w2     = (const float*)d_in[10];
    const float*         cnn_b2     = (const float*)d_in[11];
    const float*         lstm_w     = (const float*)d_in[12];
    const float*         lstm_b     = (const float*)d_in[13];
    const float*         qw1        = (const float*)d_in[14];
    const float*         qb1        = (const float*)d_in[15];
    const float*         qw2        = (const float*)d_in[16];
    const float*         qb2        = (const float*)d_in[17];
    const float*         qw3        = (const float*)d_in[18];
    const float*         qb3        = (const float*)d_in[19];
    const float*         aw1        = (const float*)d_in[20];
    const float*         ab1        = (const float*)d_in[21];
    const float*         aw2        = (const float*)d_in[22];
    const float*         ab2        = (const float*)d_in[23];
    const float*         w_ih       = (const float*)d_in[24];
    const float*         w_hh       = (const float*)d_in[25];
    const float*         b_ih       = (const float*)d_in[26];
    const float*         b_hh       = (const float*)d_in[27];
    const float*         pw         = (const float*)d_in[28];
    const float*         pb         = (const float*)d_in[29];
    const float*         vw         = (const float*)d_in[30];
    const float*         vb         = (const float*)d_in[31];
    float* out = (float*)d_out;

    // R13-proven topology: 2 streams only (passed the teardown memory check)
    static cudaStream_t sGx = nullptr, sCore = nullptr;
    static cudaEvent_t evFront, evGx[8], evM[NT], evCoreDone;
    if (!sGx) {
        cudaStreamCreateWithFlags(&sGx,   cudaStreamNonBlocking);
        cudaStreamCreateWithFlags(&sCore, cudaStreamNonBlocking);
        cudaEventCreateWithFlags(&evFront, cudaEventDisableTiming);
        for (int c = 0; c < 8; c++) cudaEventCreateWithFlags(&evGx[c], cudaEventDisableTiming);
        for (int t = 0; t < NT; t++) cudaEventCreateWithFlags(&evM[t], cudaEventDisableTiming);
        cudaEventCreateWithFlags(&evCoreDone, cudaEventDisableTiming);
        cudaFuncSetAttribute(gemm_mma<2>, cudaFuncAttributeMaxDynamicSharedMemorySize, SMEM_MMA);
        cudaFuncSetAttribute(gemm_mma<3>, cudaFuncAttributeMaxDynamicSharedMemorySize, SMEM_MMA);
    }

    init_kernel<<<4320, 256>>>(core_h, core_c, conv_h, conv_c);
    split_w_kernel<<<3456, 256>>>(lstm_w);

    // retiled conv0 (32x128 tile, no wasted M-half) + conv1
    conv0_kernel<<<8320, 256>>>(cnn_w1, cnn_b1, frame);
    conv1_kernel<<<4320, 256>>>(cnn_w2, cnn_b2);
    cudaEventRecord(evFront, 0);

    // Gx in 8 chunks of 4 timesteps each (270 n-tiles = 64 images exactly),
    // on its own stream so later chunks overlap the t-loop below.
    cudaStreamWaitEvent(sGx, evFront, 0);
    for (int c = 0; c < 8; c++) {
        gemm_mma<2><<<dim3(270,4), 256, SMEM_MMA, sGx>>>(lstm_b, 0, done, c*270);
        cudaEventRecord(evGx[c], sGx);
    }

    for (int t = 0; t < NT; t++) {
        if ((t & 3) == 0) cudaStreamWaitEvent(0, evGx[t >> 2], 0);
        // gates + fused ConvLSTM pointwise update (double-buffered h)
        gemm_mma<3><<<dim3(68,4), 256, SMEM_MMA>>>(lstm_b, t, done, 0);
        cudaEventRecord(evM[t], 0);
        // core_step(t) on its own stream: overlaps gemm_mma<3>(t+1)
        cudaStreamWaitEvent(sCore, evM[t], 0);
        core_step<<<16, 512, 0, sCore>>>(t, done, qw1,qb1,qw2,qb2,qw3,qb3,
                                         aw1,ab1,aw2,ab2, w_ih,w_hh,b_ih,b_hh,
                                         last_action, reward);
    }
    cudaEventRecord(evCoreDone, sCore);
    cudaStreamWaitEvent(0, evCoreDone, 0);

    head_kernel<<<512, 32>>>(pw, pb, vw, vb, out);
    write_states<<<4320, 256>>>(out);
}

// round 16
// speedup vs baseline: 3.6886x; 1.1231x over previous
#include <cuda_runtime.h>
#include <cuda_bf16.h>
#include <math.h>
#include <cstdint>

// ---------------------------------------------------------------------------
// AttentionNet: conv1 -> conv2 -> ConvLSTM(T=32) -> attention core LSTM(T=32)
// 3x3-conv GEMMs on HMMA (bf16 hi/lo 3-split, fp32 acc), 2 CTAs/SM.
// R16: split_w overlapped with conv0 (same 2-stream topology), conv1 retiled
// to 64x128 w/ 8x4 micro (broadcast A, conflict-free B), core_step widened to
// 1024 threads with split-k a1/ci and 32-warp gates.
// ---------------------------------------------------------------------------

#define NT 32
#define HSZ (16u*128*540)

// ------------------------- static device scratch ---------------------------
__device__ float g_conv1[512u*32*2080];          // (512,32,52,40)
__device__ float g_Gx   [141557760u];            // (512,512,540) permuted-row Gx
__device__ float g_O    [512u*128*540];          // (T*B,128,540) RAW NCHW h outputs
__device__ float g_h    [16*128*540];            // conv h state (fp32, final only)
__device__ float g_c    [16*128*540];            // conv c state
__device__ float g_S    [540*64];                // spatial basis
__device__ float g_ch   [16*256];                // core h
__device__ float g_cc   [16*256];                // core c
__device__ float g_outs [32*16*256];             // core outputs per step

// bf16-split operands (rows PERMUTED: row' = my*128 + g*32 + c32)
__device__ __align__(16) __nv_bfloat16 g_Whi[512u*1728];
__device__ __align__(16) __nv_bfloat16 g_Wlo[512u*1728];
__device__ unsigned int g_xsplit[512u*64*540];   // packed hi | lo<<16
__device__ unsigned int g_hsplit[2u*HSZ];        // DOUBLE-BUFFERED packed h

__device__ __forceinline__ float sigmoidf_(float x) { return 1.f/(1.f+expf(-x)); }

__device__ __forceinline__ unsigned int pack_split(float f) {
    __nv_bfloat16 h = __float2bfloat16(f);
    float hf = __bfloat162float(h);
    __nv_bfloat16 l = __float2bfloat16(f - hf);
    unsigned short hu = *reinterpret_cast<unsigned short*>(&h);
    unsigned short lu = *reinterpret_cast<unsigned short*>(&l);
    return (unsigned int)hu | ((unsigned int)lu << 16);
}

// ----------------------------- mma helpers ---------------------------------
__device__ __forceinline__ uint32_t smem_u32(const void* p) {
    uint32_t a;
    asm("{ .reg .u64 t; cvta.to.shared.u64 t, %1; cvt.u32.u64 %0, t; }" : "=r"(a) : "l"(p));
    return a;
}
__device__ __forceinline__ void ldsm_x4(uint32_t* r, uint32_t addr) {
    asm volatile("ldmatrix.sync.aligned.m8n8.x4.shared.b16 {%0,%1,%2,%3}, [%4];"
        : "=r"(r[0]), "=r"(r[1]), "=r"(r[2]), "=r"(r[3]) : "r"(addr));
}
__device__ __forceinline__ void ldsm_x2(uint32_t* r, uint32_t addr) {
    asm volatile("ldmatrix.sync.aligned.m8n8.x2.shared.b16 {%0,%1}, [%2];"
        : "=r"(r[0]), "=r"(r[1]) : "r"(addr));
}
__device__ __forceinline__ void mma16816(float* d, const uint32_t* a, const uint32_t* b) {
    asm volatile(
        "mma.sync.aligned.m16n8k16.row.col.f32.bf16.bf16.f32 "
        "{%0,%1,%2,%3}, {%4,%5,%6,%7}, {%8,%9}, {%0,%1,%2,%3};"
        : "+f"(d[0]), "+f"(d[1]), "+f"(d[2]), "+f"(d[3])
        : "r"(a[0]), "r"(a[1]), "r"(a[2]), "r"(a[3]), "r"(b[0]), "r"(b[1]));
}

// ------------------------------ init -------------------------------------
__global__ void init_kernel(const float* __restrict__ core_h, const float* __restrict__ core_c,
                            const float* __restrict__ conv_h, const float* __restrict__ conv_c) {
    int i = blockIdx.x*blockDim.x + threadIdx.x;
    if (i < 540*64) {
        int p = i >> 6, k = i & 63;
        int y = p/20, x = p - y*20;
        int u = k >> 3, v = k & 7;
        double PI = 3.14159265358979323846;
        g_S[i] = (float)(cos((double)(y+1)*(u+1)*PI/27.0) * cos((double)(x+1)*(v+1)*PI/20.0));
    }
    if (i < 16*256) { g_ch[i] = core_h[i]; g_cc[i] = core_c[i]; }
    if (i < 16*128*540) {
        g_c[i] = conv_c[i];
        g_hsplit[i] = pack_split(conv_h[i]);      // buffer 0
    }
}

// Weight split with GATE-INTERLEAVED row permutation:
// orig row m = g*128 + rr -> perm row = (rr>>5)*128 + g*32 + (rr&31)
__global__ void split_w_kernel(const float* __restrict__ w) {
    int i = blockIdx.x*blockDim.x + threadIdx.x;
    if (i >= 512*1728) return;
    int row = i / 1728, k = i - row*1728;
    int g = row >> 7, rr = row & 127;
    int rp = (rr >> 5)*128 + g*32 + (rr & 31);
    float f = w[i];
    __nv_bfloat16 h = __float2bfloat16(f);
    __nv_bfloat16 l = __float2bfloat16(f - __bfloat162float(h));
    g_Whi[(size_t)rp*1728 + k] = h;
    g_Wlo[(size_t)rp*1728 + k] = l;
}

// -------------------- conv0: 8x8 s4, 3->32, tile 32x128 --------------------
__global__ void __launch_bounds__(256)
conv0_kernel(const float* __restrict__ W, const float* __restrict__ bias,
             const float* __restrict__ frame)
{
    __shared__ float As[16][32];
    __shared__ float Bs[16][128];

    int tid = threadIdx.x;
    int n0 = blockIdx.x * 128;
    int tx = tid & 31, ty = tid >> 5;          // ty 0..7 -> m, tx 0..31 -> n

    float acc[4][4];
    #pragma unroll
    for (int i=0;i<4;i++)
        #pragma unroll
        for (int j=0;j<4;j++) acc[i][j] = 0.f;

    int a_m = tid >> 3;            // 0..31
    int a_k = (tid & 7) * 2;       // 0,2,..,14

    int b_n = n0 + (tid & 127);
    int img = b_n / 2080;
    int pos = b_n - img * 2080;
    int oy  = pos / 40, ox = pos - oy*40;
    int iy0 = oy*4 - 1, ix0 = ox*4 - 2;
    int kh  = tid >> 7;            // 0/1
    const float* bbase = frame + (size_t)img * (3*210*160);

    for (int k0 = 0; k0 < 192; k0 += 16) {
        float2 av = *reinterpret_cast<const float2*>(W + a_m*192 + k0 + a_k);
        As[a_k  ][a_m] = av.x;
        As[a_k+1][a_m] = av.y;
        #pragma unroll
        for (int i=0;i<8;i++) {
            int kk = kh*8 + i;
            int k  = k0 + kk;
            int c  = k >> 6;
            int rs = k & 63;
            int r  = rs >> 3, s = rs & 7;
            int iy = iy0 + r, ix = ix0 + s;
            float v = 0.f;
            if ((unsigned)iy < 210u && (unsigned)ix < 160u)
                v = bbase[(c*210 + iy)*160 + ix];
            Bs[kk][tid & 127] = v;
        }
        __syncthreads();

        #pragma unroll
        for (int kk=0;kk<16;kk++) {
            float4 a4 = *reinterpret_cast<const float4*>(&As[kk][ty*4]);
            float4 b4 = *reinterpret_cast<const float4*>(&Bs[kk][tx*4]);
            float a[4] = {a4.x,a4.y,a4.z,a4.w};
            float b[4] = {b4.x,b4.y,b4.z,b4.w};
            #pragma unroll
            for (int i=0;i<4;i++)
                #pragma unroll
                for (int j=0;j<4;j++) acc[i][j] += a[i]*b[j];
        }
        __syncthreads();
    }

    #pragma unroll
    for (int i=0;i<4;i++) {
        int m = ty*4 + i;
        float bm = bias[m];
        #pragma unroll
        for (int j=0;j<4;j++) {
            int n  = n0 + tx*4 + j;
            int im = n / 2080;
            int pp = n - im*2080;
            g_conv1[(size_t)(im*32+m)*2080 + pp] = acc[i][j] + bm;
        }
    }
}

// ---------- conv1: 4x4 s2, 32->64, tile 64x128, micro 8(m)x4(n) ------------
__global__ void __launch_bounds__(256)
conv1_kernel(const float* __restrict__ W, const float* __restrict__ bias)
{
    constexpr int K=512, IH=52, IW=40;
    __shared__ float As[16][64];
    __shared__ float Bs[16][128];

    int tid = threadIdx.x;
    int n0 = blockIdx.x * 128;
    int tx = tid & 31;            // n sub-block of 4 -> 128 cols
    int ty = tid >> 5;            // m sub-block of 8 -> 64 rows

    float acc[8][4];
    #pragma unroll
    for (int i=0;i<8;i++)
        #pragma unroll
        for (int j=0;j<4;j++) acc[i][j] = 0.f;

    // A: 64 rows x 16 k = 1024 floats -> 4/thread (float4)
    int a_m = tid >> 2;
    int a_k = (tid & 3) * 4;

    // B: 128 cols x 16 k = 2048 -> 8/thread
    int b_n = n0 + (tid & 127);
    int img = b_n / 540;
    int pos = b_n - img * 540;
    int oy  = pos / 20;
    int ox  = pos - oy * 20;
    int iy0 = oy * 2 - 2;
    int ix0 = ox * 2 - 1;
    int kh  = tid >> 7;           // 0/1: k-halves 0-7 / 8-15

    const float* bbase = g_conv1 + (size_t)img * (32*52*40);

    for (int k0 = 0; k0 < K; k0 += 16) {
        float4 av4 = *reinterpret_cast<const float4*>(W + (size_t)a_m * K + k0 + a_k);
        As[a_k+0][a_m] = av4.x;
        As[a_k+1][a_m] = av4.y;
        As[a_k+2][a_m] = av4.z;
        As[a_k+3][a_m] = av4.w;

        #pragma unroll
        for (int i=0;i<8;i++) {
            int kk = kh*8 + i;
            int k  = k0 + kk;
            int c  = k >> 4;          // KH*KW = 16
            int rs = k & 15;
            int r  = rs >> 2, s = rs & 3;
            int iy = iy0 + r, ix = ix0 + s;
            float v = 0.f;
            if ((unsigned)iy < (unsigned)IH && (unsigned)ix < (unsigned)IW)
                v = bbase[((size_t)c*IH + iy)*IW + ix];
            Bs[kk][tid & 127] = v;
        }
        __syncthreads();

        #pragma unroll
        for (int kk=0;kk<16;kk++) {
            float4 a0 = *reinterpret_cast<const float4*>(&As[kk][ty*8]);     // broadcast/warp
            float4 a1v = *reinterpret_cast<const float4*>(&As[kk][ty*8+4]);  // broadcast/warp
            float4 b4 = *reinterpret_cast<const float4*>(&Bs[kk][tx*4]);     // conflict-free
            float a[8] = {a0.x,a0.y,a0.z,a0.w,a1v.x,a1v.y,a1v.z,a1v.w};
            float b[4] = {b4.x,b4.y,b4.z,b4.w};
            #pragma unroll
            for (int i=0;i<8;i++)
                #pragma unroll
                for (int j=0;j<4;j++) acc[i][j] += a[i]*b[j];
        }
        __syncthreads();
    }

    #pragma unroll
    for (int i=0;i<8;i++) {
        int m = ty*8 + i;
        float bm = bias[m];
        #pragma unroll
        for (int j=0;j<4;j++) {
            int n  = n0 + tx*4 + j;
            int im = n / 540;
            int pp = n - im*540;
            g_xsplit[(size_t)(im*64+m)*540 + pp] = pack_split(acc[i][j] + bm);
        }
    }
}

// ---------------- HMMA GEMM for the 3x3 convs (bf16 hi/lo split) -----------
static constexpr int OFF_AHI = 0;
static constexpr int OFF_ALO = 10240;
static constexpr int OFF_BHI = 20480;
static constexpr int OFF_BLO = 30720;
static constexpr int OFF_KTAB = 40960;            // 1152 x u32 (mainloop only)
static constexpr int SMEM_MMA = 128*132*4;        // 67584 (stage reuses tiles)

template<int MODE>
__global__ void __launch_bounds__(256, 2)
gemm_mma(const float* __restrict__ bias, int t, const unsigned char* __restrict__ done,
         int nbase)
{
    constexpr int KTOT  = (MODE==2) ? 576 : 1152;
    constexpr int WO    = (MODE==2) ? 0   : 576;
    constexpr int NTOT  = (MODE==2) ? 512*540 : 16*540;
    constexpr int NCH   = (MODE==2) ? 64  : 128;
    constexpr int NCHUNK= KTOT/32;

    extern __shared__ char smem[];
    uint32_t sb = smem_u32(smem);
    uint32_t* ktab = reinterpret_cast<uint32_t*>(smem + OFF_KTAB);
    int tid  = threadIdx.x;
    int wid  = tid >> 5;
    int lane = tid & 31;

    int n0 = (nbase + blockIdx.x) * 128;
    int m0 = blockIdx.y * 128;

    // double-buffer pointers (read old h, write new h elsewhere)
    const unsigned int* hread  = g_hsplit + (size_t)(t & 1) * HSZ;
    unsigned int*       hwrite = g_hsplit + (size_t)((t + 1) & 1) * HSZ;

    // ---- build k -> (delta, r, s) table ----
    for (int k = tid; k < KTOT; k += 256) {
        int c = k/9, rs = k - c*9, r = rs/3, s = rs - r*3;
        ktab[k] = (uint32_t)(c*540 + r*20 + s) | ((uint32_t)r << 20) | ((uint32_t)s << 24);
    }

    // ---- per-thread B-gather coords ----
    int nn    = tid & 127;
    int khalf = tid >> 7;
    int bn    = n0 + nn;
    bool nvalid = (bn < NTOT);
    int bnc = nvalid ? bn : 0;
    int img = bnc / 540;
    int pos = bnc - img * 540;
    int oy = pos / 20, ox = pos - oy * 20;
    int iy0 = oy - 1, ix0 = ox - 1;
    const unsigned int* bptr =
        (MODE==2 ? (const unsigned int*)g_xsplit : hread) + (size_t)img * NCH * 540 + (iy0*20 + ix0);
    if (MODE == 3 && nvalid && done[t*16 + img]) nvalid = false;

    // ---- per-thread A-load coords ----
    int a_r0 = (tid*2)   >> 2;  int a_k0 = ((tid*2)   & 3) * 8;
    int a_r1 = (tid*2+1) >> 2;  int a_k1 = ((tid*2+1) & 3) * 8;

    int wm = (wid >> 2) * 64;
    int wn = (wid & 3) * 32;

    float cfr[4][4][4];
    #pragma unroll
    for (int mi=0;mi<4;mi++)
        #pragma unroll
        for (int ni=0;ni<4;ni++)
            #pragma unroll
            for (int e=0;e<4;e++) cfr[mi][ni][e] = 0.f;

    __syncthreads();   // ktab ready

    for (int ch = 0; ch < NCHUNK; ch++) {
        int k0 = ch * 32;

        // ---- A tiles: direct gmem -> smem (latency hidden by co-resident CTA) ----
        *reinterpret_cast<uint4*>(smem + OFF_AHI + (a_r0*40 + a_k0)*2) =
            *reinterpret_cast<const uint4*>(g_Whi + (size_t)(m0+a_r0)*1728 + WO + k0 + a_k0);
        *reinterpret_cast<uint4*>(smem + OFF_AHI + (a_r1*40 + a_k1)*2) =
            *reinterpret_cast<const uint4*>(g_Whi + (size_t)(m0+a_r1)*1728 + WO + k0 + a_k1);
        *reinterpret_cast<uint4*>(smem + OFF_ALO + (a_r0*40 + a_k0)*2) =
            *reinterpret_cast<const uint4*>(g_Wlo + (size_t)(m0+a_r0)*1728 + WO + k0 + a_k0);
        *reinterpret_cast<uint4*>(smem + OFF_ALO + (a_r1*40 + a_k1)*2) =
            *reinterpret_cast<const uint4*>(g_Wlo + (size_t)(m0+a_r1)*1728 + WO + k0 + a_k1);

        // ---- B gather (im2col) direct to smem ----
        {
            int kb = khalf*16;
            #pragma unroll
            for (int i=0;i<16;i+=2) {
                uint32_t tv0 = ktab[k0 + kb + i];
                uint32_t tv1 = ktab[k0 + kb + i + 1];
                unsigned int v0 = 0, v1 = 0;
                int r0_=(tv0>>20)&15, s0_=(tv0>>24)&15;
                int r1_=(tv1>>20)&15, s1_=(tv1>>24)&15;
                if (nvalid && (unsigned)(iy0+r0_)<27u && (unsigned)(ix0+s0_)<20u)
                    v0 = bptr[tv0 & 0xFFFFF];
                if (nvalid && (unsigned)(iy0+r1_)<27u && (unsigned)(ix0+s1_)<20u)
                    v1 = bptr[tv1 & 0xFFFFF];
                uint32_t hi = (v0 & 0xFFFFu) | (v1 << 16);
                uint32_t lo = (v0 >> 16) | (v1 & 0xFFFF0000u);
                *reinterpret_cast<uint32_t*>(smem + OFF_BHI + (nn*40 + kb + i)*2) = hi;
                *reinterpret_cast<uint32_t*>(smem + OFF_BLO + (nn*40 + kb + i)*2) = lo;
            }
        }
        __syncthreads();

        #pragma unroll
        for (int kk = 0; kk < 32; kk += 16) {
            uint32_t af[4][4], bfh[4][2], bfl[4][2];
            {
                uint32_t row = wm + (lane & 15);
                uint32_t col = kk + (lane >> 4) * 8;
                #pragma unroll
                for (int mi=0;mi<4;mi++)
                    ldsm_x4(af[mi], sb + OFF_AHI + ((row + mi*16)*40 + col)*2);
            }
            {
                int l2 = lane & 15;
                uint32_t row = wn + (l2 & 7);
                uint32_t col = kk + (l2 >> 3) * 8;
                #pragma unroll
                for (int ni=0;ni<4;ni++) {
                    ldsm_x2(bfh[ni], sb + OFF_BHI + ((row + ni*8)*40 + col)*2);
                    ldsm_x2(bfl[ni], sb + OFF_BLO + ((row + ni*8)*40 + col)*2);
                }
            }
            #pragma unroll
            for (int mi=0;mi<4;mi++)
                #pragma unroll
                for (int ni=0;ni<4;ni++) {
                    mma16816(cfr[mi][ni], af[mi], bfh[ni]);
                    mma16816(cfr[mi][ni], af[mi], bfl[ni]);
                }
            {
                uint32_t row = wm + (lane & 15);
                uint32_t col = kk + (lane >> 4) * 8;
                #pragma unroll
                for (int mi=0;mi<4;mi++)
                    ldsm_x4(af[mi], sb + OFF_ALO + ((row + mi*16)*40 + col)*2);
            }
            #pragma unroll
            for (int mi=0;mi<4;mi++)
                #pragma unroll
                for (int ni=0;ni<4;ni++)
                    mma16816(cfr[mi][ni], af[mi], bfh[ni]);
        }
        __syncthreads();
    }

    // ---- frags -> smem stage ----
    float* stage = reinterpret_cast<float*>(smem);
    int gid = lane >> 2, tig = lane & 3;
    #pragma unroll
    for (int mi=0;mi<4;mi++)
        #pragma unroll
        for (int ni=0;ni<4;ni++) {
            int r0 = wm + mi*16 + gid;
            int c0 = wn + ni*8 + tig*2;
            stage[r0*132 + c0]       = cfr[mi][ni][0];
            stage[r0*132 + c0 + 1]   = cfr[mi][ni][1];
            stage[(r0+8)*132 + c0]   = cfr[mi][ni][2];
            stage[(r0+8)*132 + c0+1] = cfr[mi][ni][3];
        }
    __syncthreads();

    if constexpr (MODE == 2) {
        int my = blockIdx.y;
        for (int idx = tid; idx < 128*128; idx += 256) {
            int r = idx >> 7, c2 = idx & 127;
            int n = n0 + c2;
            int m  = m0 + r;
            int gg = r >> 5, c32 = r & 31;
            int morig = gg*128 + my*32 + c32;
            int im = n / 540;
            int pp = n - im*540;
            g_Gx[((size_t)im*512 + m)*540 + pp] = stage[r*132 + c2] + bias[morig];
        }
    } else {
        // fused ConvLSTM update: stage rows {c32, 32+c32, 64+c32, 96+c32} are
        // (ai, af, ao, ag) for channel my*32+c32.
        int my = blockIdx.y;
        int tb = t*16;
        for (int idx = tid; idx < 32*128; idx += 256) {
            int c32 = idx >> 7, col = idx & 127;
            int n = n0 + col;
            if (n >= 8640) continue;
            int im = n / 540, pp = n - im*540;
            int ch = my*32 + c32;
            size_t gxb = ((size_t)(tb + im)*512 + my*128 + c32)*540 + pp;
            float ai = stage[(     c32)*132 + col] + g_Gx[gxb];
            float af = stage[(32 + c32)*132 + col] + g_Gx[gxb + (size_t)32*540];
            float ao = stage[(64 + c32)*132 + col] + g_Gx[gxb + (size_t)64*540];
            float ag = stage[(96 + c32)*132 + col] + g_Gx[gxb + (size_t)96*540];
            float nd = (done[tb+im]==0) ? 1.f : 0.f;
            int hidx = (im*128 + ch)*540 + pp;
            float c = g_c[hidx] * nd;
            c = sigmoidf_(af)*c + sigmoidf_(ai)*tanhf(ag);
            float h = sigmoidf_(ao)*tanhf(c);
            g_c[hidx] = c;
            g_h[hidx] = h;
            hwrite[hidx] = pack_split(h);
            g_O[(size_t)(tb+im)*69120 + (size_t)ch*540 + pp] = h;
        }
    }
}

// --------------------------- fused core step (1024 threads) -----------------
__global__ void __launch_bounds__(1024)
core_step(int t, const unsigned char* __restrict__ done,
          const float* __restrict__ qw1, const float* __restrict__ qb1,
          const float* __restrict__ qw2, const float* __restrict__ qb2,
          const float* __restrict__ qw3, const float* __restrict__ qb3,
          const float* __restrict__ aw1, const float* __restrict__ ab1,
          const float* __restrict__ aw2, const float* __restrict__ ab2,
          const float* __restrict__ w_ih, const float* __restrict__ w_hh,
          const float* __restrict__ b_ih, const float* __restrict__ b_hh,
          const int* __restrict__ last_action, const float* __restrict__ reward)
{
    int b = blockIdx.x;
    int tid = threadIdx.x;
    int wid = tid >> 5, lane = tid & 31;

    __shared__ float sh[256];
    __shared__ float q1[128];
    __shared__ float q2[288];
    __shared__ float q3[288];
    __shared__ float sA[2160];
    __shared__ float red[1024];
    __shared__ float mx[4], sm[4];
    __shared__ float ans[736];
    __shared__ float a1p[2][512];
    __shared__ float a1[512];
    __shared__ float cip[2][256];
    __shared__ float ci[256];
    __shared__ float gsum[1024];

    if (tid < 256) sh[tid] = g_ch[b*256 + tid];
    __syncthreads();

    if (tid < 128) {
        float s = qb1[tid];
        for (int k=0;k<256;k++) s += sh[k]*qw1[k*128+tid];
        q1[tid] = fmaxf(s, 0.f);
    }
    __syncthreads();
    if (tid < 288) {
        float s = qb2[tid];
        for (int k=0;k<128;k++) s += q1[k]*qw2[k*288+tid];
        q2[tid] = fmaxf(s, 0.f);
    }
    __syncthreads();
    if (tid < 288) {
        float s = qb3[tid];
        for (int k=0;k<288;k++) s += q2[k]*qw3[k*288+tid];
        q3[tid] = s;
    }
    __syncthreads();

    const float* Ob = g_O + ((size_t)(t*16+b))*69120;
    for (int idx=tid; idx<2160; idx+=1024) {
        int p = idx >> 2, qi = idx & 3;
        const float* qv = q3 + qi*72;
        const float* op = Ob + (size_t)p*128;
        const float* sp = g_S + p*64;
        float s = 0.f;
        #pragma unroll
        for (int k=0;k<8;k++)  s += op[k]*qv[k];
        #pragma unroll 8
        for (int k=0;k<64;k++) s += sp[k]*qv[8+k];
        sA[idx] = s;
    }
    __syncthreads();

    {
        int qi = tid >> 8, l8 = tid & 255;
        float m = -1e30f;
        for (int p=l8;p<540;p+=256) m = fmaxf(m, sA[p*4+qi]);
        red[tid] = m;
        __syncthreads();
        if (tid < 4) { float mm=-1e30f; for (int i=0;i<256;i++) mm = fmaxf(mm, red[tid*256+i]); mx[tid]=mm; }
        __syncthreads();
        for (int idx=tid; idx<2160; idx+=1024) sA[idx] = expf(sA[idx]-mx[idx&3]);
        __syncthreads();
        float s = 0.f;
        for (int p=l8;p<540;p+=256) s += sA[p*4+qi];
        red[tid] = s;
        __syncthreads();
        if (tid < 4) { float ss=0.f; for (int i=0;i<256;i++) ss += red[tid*256+i]; sm[tid]=ss; }
        __syncthreads();
    }

    // ans: 1 output per thread (736 active)
    if (tid < 736) {
        int q0 = tid/184, v0 = tid-q0*184;
        const float* b0 = (v0<120) ? Ob+8+v0 : g_S+(v0-120);
        int s0 = (v0<120)?128:64;
        float a0=0.f;
        #pragma unroll 4
        for (int p=0;p<540;p++) a0 += sA[p*4+q0] * b0[(size_t)p*s0];
        ans[tid] = a0 / sm[q0];
    }
    __syncthreads();

    float rclip = fminf(fmaxf(reward[t*16+b], -1.f), 1.f);
    int act = last_action[t*16+b];
    float nd = (done[t*16+b]==0) ? 1.f : 0.f;

    // a1 split-k: kh=0 -> rows 0..511, kh=1 -> rows 512..1025 + bias/extras
    {
        int j = tid & 511, kh = tid >> 9;
        float s = 0.f;
        if (kh == 0) {
            for (int k=0;k<512;k++) s += ans[k]*aw1[(size_t)k*512+j];
        } else {
            for (int k=512;k<736;k++) s += ans[k]*aw1[(size_t)k*512+j];
            for (int k=0;k<288;k++)   s += q3[k]*aw1[(size_t)(736+k)*512+j];
            s += ab1[j] + rclip*aw1[(size_t)1024*512+j] + aw1[(size_t)(1025+act)*512+j];
        }
        a1p[kh][j] = s;
    }
    __syncthreads();
    if (tid < 512) a1[tid] = fmaxf(a1p[0][tid] + a1p[1][tid], 0.f);
    __syncthreads();

    // ci split-k: 2 halves of 256
    if (tid < 512) {
        int j = tid & 255, kh = tid >> 8;
        float s = (kh == 0) ? ab2[j] : 0.f;
        for (int k=kh*256;k<kh*256+256;k++) s += a1[k]*aw2[(size_t)k*256+j];
        cip[kh][j] = s;
    }
    __syncthreads();
    if (tid < 256) ci[tid] = cip[0][tid] + cip[1][tid];
    __syncthreads();

    // LSTM gates: 32 warps, warp-per-output, float4 reads + shuffle reduce
    for (int j = wid; j < 1024; j += 32) {
        const float4* wi4 = reinterpret_cast<const float4*>(w_ih + (size_t)j*256);
        const float4* wh4 = reinterpret_cast<const float4*>(w_hh + (size_t)j*256);
        float s1 = 0.f, s2 = 0.f;
        #pragma unroll
        for (int it = 0; it < 2; it++) {
            int k4 = lane + it*32;
            float4 a = wi4[k4];
            float4 bq = wh4[k4];
            int kb = k4*4;
            s1 += ci[kb]*a.x + ci[kb+1]*a.y + ci[kb+2]*a.z + ci[kb+3]*a.w;
            s2 += sh[kb]*bq.x + sh[kb+1]*bq.y + sh[kb+2]*bq.z + sh[kb+3]*bq.w;
        }
        #pragma unroll
        for (int off=16; off; off>>=1) {
            s1 += __shfl_down_sync(0xFFFFFFFFu, s1, off);
            s2 += __shfl_down_sync(0xFFFFFFFFu, s2, off);
        }
        if (lane == 0) gsum[j] = s1 + nd*s2 + b_ih[j] + b_hh[j];
    }
    __syncthreads();

    if (tid < 256) {
        float gi = gsum[tid], gf = gsum[256+tid], gG = gsum[512+tid], go = gsum[768+tid];
        float c = nd * g_cc[b*256+tid];
        c = sigmoidf_(gf)*c + sigmoidf_(gi)*tanhf(gG);
        float h = sigmoidf_(go)*tanhf(c);
        g_cc[b*256+tid] = c;
        g_ch[b*256+tid] = h;
        g_outs[((size_t)t*16+b)*256 + tid] = h;
    }
}

// ------------------------------- heads -------------------------------------
__global__ void head_kernel(const float* __restrict__ pw, const float* __restrict__ pb,
                            const float* __restrict__ vw, const float* __restrict__ vb,
                            float* __restrict__ out)
{
    int row = blockIdx.x;
    int tid = threadIdx.x;
    __shared__ float lg[18];
    const float* h = g_outs + (size_t)row*256;
    if (tid < 18) {
        float s = pb[tid];
        for (int k=0;k<256;k++) s += h[k]*pw[k*18+tid];
        lg[tid] = s;
        out[row*18 + tid] = s;
    }
    if (tid == 19) {
        float s = vb[0];
        for (int k=0;k<256;k++) s += h[k]*vw[k];
        out[9216 + row] = s;
    }
    __syncthreads();
    if (tid == 0) {
        int am = 0; float bv = lg[0];
        for (int j=1;j<18;j++) if (lg[j] > bv) { bv = lg[j]; am = j; }
        out[9728 + row] = (float)am;
    }
}

__global__ void write_states(float* __restrict__ out) {
    int i = blockIdx.x*blockDim.x + threadIdx.x;
    if (i < 4096) { out[10240 + i] = g_ch[i]; out[14336 + i] = g_cc[i]; }
    if (i < 1105920) { out[18432 + i] = g_h[i]; out[1124352 + i] = g_c[i]; }
}

// ------------------------------- launch ------------------------------------
extern "C" void kernel_launch(void* const* d_in, const int* in_sizes, int n_in,
                              void* d_out, int out_size) {
    const float*         frame      = (const float*)d_in[0];
    const unsigned char* done       = (const unsigned char*)d_in[1];
    const int*           last_action= (const int*)d_in[2];
    const float*         reward     = (const float*)d_in[3];
    const float*         core_h     = (const float*)d_in[4];
    const float*         core_c     = (const float*)d_in[5];
    const float*         conv_h     = (const float*)d_in[6];
    const float*         conv_c     = (const float*)d_in[7];
    const float*         cnn_w1     = (const float*)d_in[8];
    const float*         cnn_b1     = (const float*)d_in[9];
    const float*         cnn_w2     = (const float*)d_in[10];
    const float*         cnn_b2     = (const float*)d_in[11];
    const float*         lstm_w     = (const float*)d_in[12];
    const float*         lstm_b     = (const float*)d_in[13];
    const float*         qw1        = (const float*)d_in[14];
    const float*         qb1        = (const float*)d_in[15];
    const float*         qw2        = (const float*)d_in[16];
    const float*         qb2        = (const float*)d_in[17];
    const float*         qw3        = (const float*)d_in[18];
    const float*         qb3        = (const float*)d_in[19];
    const float*         aw1        = (const float*)d_in[20];
    const float*         ab1        = (const float*)d_in[21];
    const float*         aw2        = (const float*)d_in[22];
    const float*         ab2        = (const float*)d_in[23];
    const float*         w_ih       = (const float*)d_in[24];
    const float*         w_hh       = (const float*)d_in[25];
    const float*         b_ih       = (const float*)d_in[26];
    const float*         b_hh       = (const float*)d_in[27];
    const float*         pw         = (const float*)d_in[28];
    const float*         pb         = (const float*)d_in[29];
    const float*         vw         = (const float*)d_in[30];
    const float*         vb         = (const float*)d_in[31];
    float* out = (float*)d_out;

    // R13-proven topology: 2 streams only (passed the teardown memory check)
    static cudaStream_t sGx = nullptr, sCore = nullptr;
    static cudaEvent_t evFront, evGx[8], evM[NT], evCoreDone;
    if (!sGx) {
        cudaStreamCreateWithFlags(&sGx,   cudaStreamNonBlocking);
        cudaStreamCreateWithFlags(&sCore, cudaStreamNonBlocking);
        cudaEventCreateWithFlags(&evFront, cudaEventDisableTiming);
        for (int c = 0; c < 8; c++) cudaEventCreateWithFlags(&evGx[c], cudaEventDisableTiming);
        for (int t = 0; t < NT; t++) cudaEventCreateWithFlags(&evM[t], cudaEventDisableTiming);
        cudaEventCreateWithFlags(&evCoreDone, cudaEventDisableTiming);
        cudaFuncSetAttribute(gemm_mma<2>, cudaFuncAttributeMaxDynamicSharedMemorySize, SMEM_MMA);
        cudaFuncSetAttribute(gemm_mma<3>, cudaFuncAttributeMaxDynamicSharedMemorySize, SMEM_MMA);
    }

    // stream0: init (loop state), conv0, conv1; sGx: split_w (overlaps conv0)
    init_kernel<<<4320, 256>>>(core_h, core_c, conv_h, conv_c);
    split_w_kernel<<<3456, 256, 0, sGx>>>(lstm_w);

    conv0_kernel<<<8320, 256>>>(cnn_w1, cnn_b1, frame);
    conv1_kernel<<<2160, 256>>>(cnn_w2, cnn_b2);
    cudaEventRecord(evFront, 0);

    // Gx in 8 chunks of 4 timesteps each, on sGx (after split_w, after conv1)
    cudaStreamWaitEvent(sGx, evFront, 0);
    for (int c = 0; c < 8; c++) {
        gemm_mma<2><<<dim3(270,4), 256, SMEM_MMA, sGx>>>(lstm_b, 0, done, c*270);
        cudaEventRecord(evGx[c], sGx);
    }

    for (int t = 0; t < NT; t++) {
        if ((t & 3) == 0) cudaStreamWaitEvent(0, evGx[t >> 2], 0);
        // gates + fused ConvLSTM pointwise update (double-buffered h)
        gemm_mma<3><<<dim3(68,4), 256, SMEM_MMA>>>(lstm_b, t, done, 0);
        cudaEventRecord(evM[t], 0);
        // core_step(t) on its own stream: overlaps gemm_mma<3>(t+1)
        cudaStreamWaitEvent(sCore, evM[t], 0);
        core_step<<<16, 1024, 0, sCore>>>(t, done, qw1,qb1,qw2,qb2,qw3,qb3,
                                          aw1,ab1,aw2,ab2, w_ih,w_hh,b_ih,b_hh,
                                          last_action, reward);
    }
    cudaEventRecord(evCoreDone, sCore);
    cudaStreamWaitEvent(0, evCoreDone, 0);

    head_kernel<<<512, 32>>>(pw, pb, vw, vb, out);
    write_states<<<4320, 256>>>(out);
}